// round 9
// baseline (speedup 1.0000x reference)
#include <cuda_runtime.h>
#include <cuda_fp16.h>
#include <cstdint>

// ---------------- problem constants ----------------
constexpr int cN = 100000;   // nodes
constexpr int cE = 1600000;  // edges
constexpr int cD = 128;      // feature dim
constexpr int cK = 4;        // etypes
constexpr int cM = cK * cN;                  // 400000 keys (dst*4+etype)
constexpr int SCAN_NB = (cM + 1023) / 1024;  // 391

// ---------------- scratch ----------------
__device__ __align__(16) float g_h0[(size_t)cN * cD];
__device__ __align__(16) float g_h1[(size_t)cN * cD];
__device__ __align__(16) float g_a[(size_t)cN * cD];
__device__ __align__(16) float g_bsum[(size_t)cN * cD];

__device__ int g_deg[cM];
__device__ int g_rp[cM + 1];
__device__ int g_cur[cM];
__device__ int g_esrc[cE];
__device__ int g_part[512];

// fp16 weight copies (converted once per launch)
__device__ __align__(16) __half g_wet_h[cK * cD * cD];      // 65536
__device__ __align__(16) __half g_wih_h[3 * cD * cD];       // 49152
__device__ __align__(16) __half g_whh_h[3 * cD * cD];       // 49152
__device__ __align__(16) __half g_iw_h[cD * 2 * cD];        // 32768
__device__ __align__(16) __half g_jw_h[cD * cD];            // 16384

// ---------------- helpers ----------------
__device__ __forceinline__ float sigmf(float x) { return 1.0f / (1.0f + __expf(-x)); }

__device__ __forceinline__ uint32_t pk2(float x, float y) {
    __half2 h = __floats2half2_rn(x, y);
    return *reinterpret_cast<uint32_t*>(&h);
}

__device__ __forceinline__ void mma_f16(float c[4], const uint32_t a[4], const uint32_t b[2]) {
    asm volatile(
        "mma.sync.aligned.m16n8k16.row.col.f32.f16.f16.f32 "
        "{%0,%1,%2,%3}, {%4,%5,%6,%7}, {%8,%9}, {%0,%1,%2,%3};"
        : "+f"(c[0]), "+f"(c[1]), "+f"(c[2]), "+f"(c[3])
        : "r"(a[0]), "r"(a[1]), "r"(a[2]), "r"(a[3]), "r"(b[0]), "r"(b[1]));
}

// ---------------- CSR build ----------------
__global__ void k_fill_deg() {
    int i = blockIdx.x * blockDim.x + threadIdx.x;
    if (i < cM) g_deg[i] = 0;
}
__global__ void k_hist(const int* __restrict__ dst, const int* __restrict__ et) {
    int e = blockIdx.x * blockDim.x + threadIdx.x;
    if (e < cE) atomicAdd(&g_deg[dst[e] * 4 + et[e]], 1);
}
__global__ void k_scan1() {
    __shared__ int sm[1024];
    int i = blockIdx.x * 1024 + threadIdx.x;
    int v = (i < cM) ? g_deg[i] : 0;
    sm[threadIdx.x] = v;
    __syncthreads();
    for (int off = 1; off < 1024; off <<= 1) {
        int t = 0;
        if (threadIdx.x >= off) t = sm[threadIdx.x - off];
        __syncthreads();
        sm[threadIdx.x] += t;
        __syncthreads();
    }
    if (i < cM) g_rp[i] = sm[threadIdx.x] - v;
    if (threadIdx.x == 1023) g_part[blockIdx.x] = sm[1023];
}
__global__ void k_scan2() {
    __shared__ int sm[512];
    int t = threadIdx.x;
    int v = (t < SCAN_NB) ? g_part[t] : 0;
    sm[t] = v;
    __syncthreads();
    for (int off = 1; off < 512; off <<= 1) {
        int x = 0;
        if (t >= off) x = sm[t - off];
        __syncthreads();
        sm[t] += x;
        __syncthreads();
    }
    if (t < SCAN_NB) g_part[t] = sm[t] - v;
    if (t == 511) g_rp[cM] = sm[511];
}
__global__ void k_scan3() {  // also initializes g_cur
    int i = blockIdx.x * 1024 + threadIdx.x;
    if (i < cM) {
        int v = g_rp[i] + g_part[blockIdx.x];
        g_rp[i] = v;
        g_cur[i] = v;
    }
}
__global__ void k_scatter(const int* __restrict__ src, const int* __restrict__ dst,
                          const int* __restrict__ et) {
    int e = blockIdx.x * blockDim.x + threadIdx.x;
    if (e < cE) {
        int key = dst[e] * 4 + et[e];
        int pos = atomicAdd(&g_cur[key], 1);
        g_esrc[pos] = src[e];
    }
}
__global__ void k_bsum(const float* __restrict__ bet) {
    int idx = blockIdx.x * blockDim.x + threadIdx.x;
    if (idx >= cN * cD) return;
    int r = idx >> 7, col = idx & 127;
    int rp[5];
#pragma unroll
    for (int k = 0; k <= 4; k++) rp[k] = g_rp[4 * r + k];
    float v = 0.f;
#pragma unroll
    for (int k = 0; k < 4; k++) v += (float)(rp[k + 1] - rp[k]) * __ldg(&bet[k * cD + col]);
    g_bsum[idx] = v;
}

// ---------------- weight pre-conversion f32 -> f16 ----------------
__global__ void k_convw(const float* __restrict__ Wet, const float* __restrict__ Wih,
                        const float* __restrict__ Whh, const float* __restrict__ Iw,
                        const float* __restrict__ Jw) {
    int i = blockIdx.x * blockDim.x + threadIdx.x;
    if (i < cK * cD * cD) g_wet_h[i] = __float2half_rn(Wet[i]);
    if (i < 3 * cD * cD) {
        g_wih_h[i] = __float2half_rn(Wih[i]);
        g_whh_h[i] = __float2half_rn(Whh[i]);
    }
    if (i < cD * 2 * cD) g_iw_h[i] = __float2half_rn(Iw[i]);
    if (i < cD * cD) g_jw_h[i] = __float2half_rn(Jw[i]);
}

// ---------------- fp16 GEMM building blocks ----------------
constexpr int LD2 = 136;  // halves per smem row (272B stride, conflict-free)

__device__ __forceinline__ void load_tile_X16(const float* __restrict__ X, __half* Xs,
                                              int rowBase, int nrows, int tid) {
    for (int idx = tid; idx < 128 * 32; idx += 256) {
        int row = idx >> 5, c4 = (idx & 31) * 4;
        float4 v = make_float4(0.f, 0.f, 0.f, 0.f);
        int r = rowBase + row;
        if (r < nrows) v = *reinterpret_cast<const float4*>(X + (size_t)r * cD + c4);
        *reinterpret_cast<uint2*>(Xs + row * LD2 + c4) = make_uint2(pk2(v.x, v.y), pk2(v.z, v.w));
    }
}
// f16-source tile loaders (no conversion, half the bytes)
__device__ __forceinline__ void load_tile_W64_h(const __half* __restrict__ W, int ldw, __half* Ws,
                                                int colBase, int tid) {
    for (int idx = tid; idx < 64 * 32; idx += 256) {
        int o = idx >> 5, c4 = (idx & 31) * 4;
        uint2 v = *reinterpret_cast<const uint2*>(W + (size_t)(colBase + o) * ldw + c4);
        *reinterpret_cast<uint2*>(Ws + o * LD2 + c4) = v;
    }
}
__device__ __forceinline__ void load_tile_W128_h(const __half* __restrict__ W, int ldw, __half* Ws,
                                                 int tid) {
    for (int idx = tid; idx < 128 * 32; idx += 256) {
        int o = idx >> 5, c4 = (idx & 31) * 4;
        uint2 v = *reinterpret_cast<const uint2*>(W + (size_t)o * ldw + c4);
        *reinterpret_cast<uint2*>(Ws + o * LD2 + c4) = v;
    }
}
__device__ __forceinline__ uint32_t lds32(const __half* p) {
    return *reinterpret_cast<const uint32_t*>(p);
}

// warp-tile 32x32 mainloop, fp16 k16
__device__ __forceinline__ void mma_loop32(const __half* Xs, const __half* Ws,
                                           int wm, int wn, int gr, int gc, float c[2][4][4]) {
#pragma unroll
    for (int k0 = 0; k0 < cD; k0 += 16) {
        uint32_t a[2][4], b[4][2];
#pragma unroll
        for (int i = 0; i < 2; i++) {
            const __half* base = Xs + (wm + i * 16 + gr) * LD2 + k0 + 2 * gc;
            a[i][0] = lds32(base);
            a[i][1] = lds32(base + 8 * LD2);
            a[i][2] = lds32(base + 8);
            a[i][3] = lds32(base + 8 * LD2 + 8);
        }
#pragma unroll
        for (int j = 0; j < 4; j++) {
            const __half* base = Ws + (wn + j * 8 + gr) * LD2 + k0 + 2 * gc;
            b[j][0] = lds32(base);
            b[j][1] = lds32(base + 8);
        }
#pragma unroll
        for (int i = 0; i < 2; i++)
#pragma unroll
            for (int j = 0; j < 4; j++) mma_f16(c[i][j], a[i], b[j]);
    }
}
// warp-tile 32x64 mainloop, fp16 k16
__device__ __forceinline__ void mma_loop64(const __half* Xs, const __half* Ws,
                                           int wm, int wn, int gr, int gc, float c[2][8][4]) {
#pragma unroll
    for (int k0 = 0; k0 < cD; k0 += 16) {
        uint32_t a[2][4], b[8][2];
#pragma unroll
        for (int i = 0; i < 2; i++) {
            const __half* base = Xs + (wm + i * 16 + gr) * LD2 + k0 + 2 * gc;
            a[i][0] = lds32(base);
            a[i][1] = lds32(base + 8 * LD2);
            a[i][2] = lds32(base + 8);
            a[i][3] = lds32(base + 8 * LD2 + 8);
        }
#pragma unroll
        for (int j = 0; j < 8; j++) {
            const __half* base = Ws + (wn + j * 8 + gr) * LD2 + k0 + 2 * gc;
            b[j][0] = lds32(base);
            b[j][1] = lds32(base + 8);
        }
#pragma unroll
        for (int i = 0; i < 2; i++)
#pragma unroll
            for (int j = 0; j < 8; j++) mma_f16(c[i][j], a[i], b[j]);
    }
}

// ---------------- fused aggregation + etype GEMM (R6 structure: 64-row blocks) ----------------
constexpr int SM_AE = (64 + 128) * LD2 * 2;  // 52224 -> 3 CTAs/SM

__global__ __launch_bounds__(256, 3) void k_agg_etype(const float* __restrict__ h) {
    extern __shared__ __half smh[];
    __half* Xs = smh;             // 64 x LD2
    __half* Ws = smh + 64 * LD2;  // 128 x LD2
    int tid = threadIdx.x, lane = tid & 31, warp = tid >> 5;
    int rowBase = blockIdx.x * 64;
    int wm = (warp & 1) * 32, wn = (warp >> 1) * 32;
    int gr = lane >> 2, gc = lane & 3;
    const float4* hp = reinterpret_cast<const float4*>(h);

    float c[2][4][4];
#pragma unroll
    for (int i = 0; i < 2; i++)
#pragma unroll
        for (int j = 0; j < 4; j++)
#pragma unroll
            for (int q = 0; q < 4; q++) c[i][j][q] = 0.f;

    for (int ke = 0; ke < cK; ke++) {
        if (ke) __syncthreads();
#pragma unroll
        for (int i = 0; i < 8; i++) {
            int vl = warp * 8 + i;
            int v = rowBase + vl;
            float4 acc = make_float4(0.f, 0.f, 0.f, 0.f);
            if (v < cN) {
                int r0 = __ldg(&g_rp[4 * v + ke]), r1 = __ldg(&g_rp[4 * v + ke + 1]);
                int e = r0;
                for (; e + 4 <= r1; e += 4) {
                    int s0 = __ldg(&g_esrc[e]), s1 = __ldg(&g_esrc[e + 1]);
                    int s2 = __ldg(&g_esrc[e + 2]), s3 = __ldg(&g_esrc[e + 3]);
                    float4 x0 = hp[(size_t)s0 * 32 + lane];
                    float4 x1 = hp[(size_t)s1 * 32 + lane];
                    float4 x2 = hp[(size_t)s2 * 32 + lane];
                    float4 x3 = hp[(size_t)s3 * 32 + lane];
                    acc.x += (x0.x + x1.x) + (x2.x + x3.x);
                    acc.y += (x0.y + x1.y) + (x2.y + x3.y);
                    acc.z += (x0.z + x1.z) + (x2.z + x3.z);
                    acc.w += (x0.w + x1.w) + (x2.w + x3.w);
                }
                for (; e < r1; e++) {
                    int s = __ldg(&g_esrc[e]);
                    float4 x = hp[(size_t)s * 32 + lane];
                    acc.x += x.x; acc.y += x.y; acc.z += x.z; acc.w += x.w;
                }
            }
            *reinterpret_cast<uint2*>(Xs + vl * LD2 + lane * 4) =
                make_uint2(pk2(acc.x, acc.y), pk2(acc.z, acc.w));
        }
        load_tile_W128_h(g_wet_h + (size_t)ke * cD * cD, cD, Ws, tid);
        __syncthreads();
        mma_loop32(Xs, Ws, wm, wn, gr, gc, c);
    }

#pragma unroll
    for (int i = 0; i < 2; i++)
#pragma unroll
        for (int j = 0; j < 4; j++) {
            int col = wn + j * 8 + 2 * gc;
#pragma unroll
            for (int half = 0; half < 2; half++) {
                int r = rowBase + wm + i * 16 + gr + half * 8;
                if (r >= cN) continue;
                float2 bs = *reinterpret_cast<const float2*>(g_bsum + (size_t)r * cD + col);
                float2 o = make_float2(c[i][j][half * 2] + bs.x, c[i][j][half * 2 + 1] + bs.y);
                *reinterpret_cast<float2*>(g_a + (size_t)r * cD + col) = o;
            }
        }
}

// ---------------- fused GRU (R6 grid (782,2)) with W double-buffering ----------------
constexpr int SM_GRU = (2 * 128 + 2 * 64) * LD2 * 2;  // 104448 -> 2 CTAs/SM

__global__ __launch_bounds__(256, 2) void k_gru_fused(
    const float* __restrict__ A, const float* __restrict__ H,
    const float* __restrict__ b_ih, const float* __restrict__ b_hh,
    float* __restrict__ hout) {
    extern __shared__ __half smh[];
    __half* Xa = smh;
    __half* Xh = smh + 128 * LD2;
    __half* Wb0 = smh + 256 * LD2;
    __half* Wb1 = smh + 320 * LD2;
    int tid = threadIdx.x;
    int rowBase = blockIdx.x * 128, colBase = blockIdx.y * 64;
    int lane = tid & 31, warp = tid >> 5;
    int wm = (warp & 3) * 32, wn = (warp >> 2) * 32;
    int gr = lane >> 2, gc = lane & 3;

    load_tile_X16(A, Xa, rowBase, cN, tid);
    load_tile_X16(H, Xh, rowBase, cN, tid);

    // tile schedule: t = g*2 + part (g: gate r/z/n, part: ih/hh)
    auto loadW = [&](int t, __half* buf) {
        int g = t >> 1, part = t & 1;
        const __half* Wp = (part ? g_whh_h : g_wih_h) + (size_t)g * 128 * cD;
        load_tile_W64_h(Wp, cD, buf, colBase, tid);
    };
    loadW(0, Wb0);

    float rf[2][4][4], zf[2][4][4], ci[2][4][4], ch[2][4][4];

#pragma unroll 1
    for (int t = 0; t < 6; t++) {
        __syncthreads();  // tile t staged for all; mma(t-1) done -> other buffer reusable
        if (t + 1 < 6) loadW(t + 1, (t & 1) ? Wb0 : Wb1);  // overlaps mma below
        int g = t >> 1, part = t & 1;
        float (*acc)[4][4] = part ? ch : ci;
#pragma unroll
        for (int i = 0; i < 2; i++)
#pragma unroll
            for (int j = 0; j < 4; j++)
#pragma unroll
                for (int q = 0; q < 4; q++) acc[i][j][q] = 0.f;
        mma_loop32(part ? Xh : Xa, (t & 1) ? Wb1 : Wb0, wm, wn, gr, gc, acc);

        if (part == 1) {
#pragma unroll
            for (int i = 0; i < 2; i++)
#pragma unroll
                for (int j = 0; j < 4; j++) {
                    int col = colBase + wn + j * 8 + 2 * gc;
                    float bi0 = __ldg(&b_ih[g * 128 + col]), bi1 = __ldg(&b_ih[g * 128 + col + 1]);
                    float bh0 = __ldg(&b_hh[g * 128 + col]), bh1 = __ldg(&b_hh[g * 128 + col + 1]);
                    if (g == 0) {
#pragma unroll
                        for (int q = 0; q < 4; q++) {
                            float bi = (q & 1) ? bi1 : bi0, bh = (q & 1) ? bh1 : bh0;
                            rf[i][j][q] = sigmf(ci[i][j][q] + bi + ch[i][j][q] + bh);
                        }
                    } else if (g == 1) {
#pragma unroll
                        for (int q = 0; q < 4; q++) {
                            float bi = (q & 1) ? bi1 : bi0, bh = (q & 1) ? bh1 : bh0;
                            zf[i][j][q] = sigmf(ci[i][j][q] + bi + ch[i][j][q] + bh);
                        }
                    } else {
#pragma unroll
                        for (int half = 0; half < 2; half++) {
                            int r = rowBase + wm + i * 16 + gr + half * 8;
                            if (r >= cN) continue;
                            float2 hv = *reinterpret_cast<const float2*>(H + (size_t)r * cD + col);
                            int q0 = half * 2, q1 = half * 2 + 1;
                            float n0 = tanhf(ci[i][j][q0] + bi0 + rf[i][j][q0] * (ch[i][j][q0] + bh0));
                            float n1 = tanhf(ci[i][j][q1] + bi1 + rf[i][j][q1] * (ch[i][j][q1] + bh1));
                            float2 o;
                            o.x = (1.0f - zf[i][j][q0]) * n0 + zf[i][j][q0] * hv.x;
                            o.y = (1.0f - zf[i][j][q1]) * n1 + zf[i][j][q1] * hv.y;
                            *reinterpret_cast<float2*>(hout + (size_t)r * cD + col) = o;
                        }
                    }
                }
        }
    }
}

// ---------------- fused output head ----------------
constexpr int SM_HEAD = 3 * 128 * LD2 * 2;  // 104448 -> 2 CTAs/SM

__global__ __launch_bounds__(256, 2) void k_head(
    const float* __restrict__ H, const float* __restrict__ F,
    const float* __restrict__ i_b, const float* __restrict__ j_b,
    float* __restrict__ out) {
    extern __shared__ __half smh[];
    __half* Xh = smh;
    __half* Xf = smh + 128 * LD2;
    __half* Ws = smh + 256 * LD2;
    int tid = threadIdx.x;
    int rowBase = blockIdx.x * 128;
    int lane = tid & 31, warp = tid >> 5;
    int wm = (warp & 3) * 32, wn = (warp >> 2) * 64;
    int gr = lane >> 2, gc = lane & 3;

    load_tile_X16(H, Xh, rowBase, cN, tid);
    load_tile_X16(F, Xf, rowBase, cN, tid);

    float cg[2][8][4], cj[2][8][4];
#pragma unroll
    for (int i = 0; i < 2; i++)
#pragma unroll
        for (int j = 0; j < 8; j++)
#pragma unroll
            for (int q = 0; q < 4; q++) { cg[i][j][q] = 0.f; cj[i][j][q] = 0.f; }

    load_tile_W128_h(g_iw_h, 2 * cD, Ws, tid);
    __syncthreads();
    mma_loop64(Xh, Ws, wm, wn, gr, gc, cg);
    __syncthreads();
    load_tile_W128_h(g_iw_h + cD, 2 * cD, Ws, tid);
    __syncthreads();
    mma_loop64(Xf, Ws, wm, wn, gr, gc, cg);
    __syncthreads();
    load_tile_W128_h(g_jw_h, cD, Ws, tid);
    __syncthreads();
    mma_loop64(Xh, Ws, wm, wn, gr, gc, cj);

#pragma unroll
    for (int i = 0; i < 2; i++)
#pragma unroll
        for (int j = 0; j < 8; j++) {
            int col = wn + j * 8 + 2 * gc;
            float ib0 = __ldg(&i_b[col]), ib1 = __ldg(&i_b[col + 1]);
            float jb0 = __ldg(&j_b[col]), jb1 = __ldg(&j_b[col + 1]);
#pragma unroll
            for (int half = 0; half < 2; half++) {
                int r = rowBase + wm + i * 16 + gr + half * 8;
                if (r >= cN) continue;
                int q0 = half * 2, q1 = half * 2 + 1;
                float2 o;
                o.x = sigmf(cg[i][j][q0] + ib0) * (cj[i][j][q0] + jb0);
                o.y = sigmf(cg[i][j][q1] + ib1) * (cj[i][j][q1] + jb1);
                *reinterpret_cast<float2*>(out + (size_t)r * cD + col) = o;
            }
        }
}

// ---------------- host ----------------
extern "C" void kernel_launch(void* const* d_in, const int* in_sizes, int n_in,
                              void* d_out, int out_size) {
    (void)in_sizes; (void)n_in; (void)out_size;
    const float* features = (const float*)d_in[0];
    const int*   src      = (const int*)d_in[1];
    const int*   dst      = (const int*)d_in[2];
    const int*   etypes   = (const int*)d_in[3];
    const float* W_et     = (const float*)d_in[4];
    const float* b_et     = (const float*)d_in[5];
    const float* W_ih     = (const float*)d_in[6];
    const float* b_ih     = (const float*)d_in[7];
    const float* W_hh     = (const float*)d_in[8];
    const float* b_hh     = (const float*)d_in[9];
    const float* i_w      = (const float*)d_in[10];
    const float* i_b      = (const float*)d_in[11];
    const float* j_w      = (const float*)d_in[12];
    const float* j_b      = (const float*)d_in[13];
    float* out = (float*)d_out;

    float *h0, *h1, *abuf;
    cudaGetSymbolAddress((void**)&h0, g_h0);
    cudaGetSymbolAddress((void**)&h1, g_h1);
    cudaGetSymbolAddress((void**)&abuf, g_a);

    cudaFuncSetAttribute(k_agg_etype, cudaFuncAttributeMaxDynamicSharedMemorySize, SM_AE);
    cudaFuncSetAttribute(k_gru_fused, cudaFuncAttributeMaxDynamicSharedMemorySize, SM_GRU);
    cudaFuncSetAttribute(k_head, cudaFuncAttributeMaxDynamicSharedMemorySize, SM_HEAD);

    // ---- CSR build + weight conversion ----
    k_fill_deg<<<(cM + 255) / 256, 256>>>();
    k_hist<<<(cE + 255) / 256, 256>>>(dst, etypes);
    k_convw<<<(cK * cD * cD + 255) / 256, 256>>>(W_et, W_ih, W_hh, i_w, j_w);
    k_scan1<<<SCAN_NB, 1024>>>();
    k_scan2<<<1, 512>>>();
    k_scan3<<<SCAN_NB, 1024>>>();
    k_scatter<<<(cE + 255) / 256, 256>>>(src, dst, etypes);
    k_bsum<<<(cN * cD + 255) / 256, 256>>>(b_et);

    const int RB64 = (cN + 63) / 64;    // 1563
    const int RB128 = (cN + 127) / 128; // 782

    const float* hc = features;
    float* houts[3] = {h0, h1, h0};
    for (int s = 0; s < 3; s++) {
        k_agg_etype<<<RB64, 256, SM_AE>>>(hc);  // -> g_a
        k_gru_fused<<<dim3(RB128, 2), 256, SM_GRU>>>(abuf, hc, b_ih, b_hh, houts[s]);
        hc = houts[s];
    }
    k_head<<<RB128, 256, SM_HEAD>>>(hc, features, i_b, j_b, out);
}

// round 10
// speedup vs baseline: 1.5136x; 1.5136x over previous
#include <cuda_runtime.h>
#include <cuda_fp16.h>
#include <cstdint>

// ---------------- problem constants ----------------
constexpr int cN = 100000;   // nodes
constexpr int cE = 1600000;  // edges
constexpr int cD = 128;      // feature dim
constexpr int cK = 4;        // etypes
constexpr int cM = cK * cN;                  // 400000 keys (dst*4+etype)
constexpr int SCAN_NB = (cM + 1023) / 1024;  // 391

// ---------------- scratch ----------------
__device__ __align__(16) float g_h0[(size_t)cN * cD];
__device__ __align__(16) float g_h1[(size_t)cN * cD];
__device__ __align__(16) float g_a[(size_t)cN * cD];
__device__ __align__(16) float g_bsum[(size_t)cN * cD];

__device__ int g_deg[cM];
__device__ int g_rp[cM + 1];
__device__ int g_cur[cM];
__device__ int g_esrc[cE];
__device__ int g_part[512];

// fp16 weight copies (converted once per launch; cp.async needs pre-converted data)
__device__ __align__(16) __half g_wet_h[cK * cD * cD];
__device__ __align__(16) __half g_wih_h[3 * cD * cD];
__device__ __align__(16) __half g_whh_h[3 * cD * cD];

// ---------------- helpers ----------------
__device__ __forceinline__ float sigmf(float x) { return 1.0f / (1.0f + __expf(-x)); }

__device__ __forceinline__ uint32_t pk2(float x, float y) {
    __half2 h = __floats2half2_rn(x, y);
    return *reinterpret_cast<uint32_t*>(&h);
}

__device__ __forceinline__ void mma_f16(float c[4], const uint32_t a[4], const uint32_t b[2]) {
    asm volatile(
        "mma.sync.aligned.m16n8k16.row.col.f32.f16.f16.f32 "
        "{%0,%1,%2,%3}, {%4,%5,%6,%7}, {%8,%9}, {%0,%1,%2,%3};"
        : "+f"(c[0]), "+f"(c[1]), "+f"(c[2]), "+f"(c[3])
        : "r"(a[0]), "r"(a[1]), "r"(a[2]), "r"(a[3]), "r"(b[0]), "r"(b[1]));
}

// cp.async: register-free global->smem copy
__device__ __forceinline__ void cpa16(uint32_t dst, const void* src) {
    asm volatile("cp.async.ca.shared.global [%0], [%1], 16;" :: "r"(dst), "l"(src));
}
#define CP_COMMIT() asm volatile("cp.async.commit_group;" ::: "memory")
#define CP_WAIT0()  asm volatile("cp.async.wait_group 0;" ::: "memory")

// ---------------- CSR build ----------------
__global__ void k_fill_deg() {
    int i = blockIdx.x * blockDim.x + threadIdx.x;
    if (i < cM) g_deg[i] = 0;
}
__global__ void k_hist(const int* __restrict__ dst, const int* __restrict__ et) {
    int e = blockIdx.x * blockDim.x + threadIdx.x;
    if (e < cE) atomicAdd(&g_deg[dst[e] * 4 + et[e]], 1);
}
__global__ void k_scan1() {
    __shared__ int sm[1024];
    int i = blockIdx.x * 1024 + threadIdx.x;
    int v = (i < cM) ? g_deg[i] : 0;
    sm[threadIdx.x] = v;
    __syncthreads();
    for (int off = 1; off < 1024; off <<= 1) {
        int t = 0;
        if (threadIdx.x >= off) t = sm[threadIdx.x - off];
        __syncthreads();
        sm[threadIdx.x] += t;
        __syncthreads();
    }
    if (i < cM) g_rp[i] = sm[threadIdx.x] - v;
    if (threadIdx.x == 1023) g_part[blockIdx.x] = sm[1023];
}
__global__ void k_scan2() {
    __shared__ int sm[512];
    int t = threadIdx.x;
    int v = (t < SCAN_NB) ? g_part[t] : 0;
    sm[t] = v;
    __syncthreads();
    for (int off = 1; off < 512; off <<= 1) {
        int x = 0;
        if (t >= off) x = sm[t - off];
        __syncthreads();
        sm[t] += x;
        __syncthreads();
    }
    if (t < SCAN_NB) g_part[t] = sm[t] - v;
    if (t == 511) g_rp[cM] = sm[511];
}
__global__ void k_scan3() {  // also initializes g_cur
    int i = blockIdx.x * 1024 + threadIdx.x;
    if (i < cM) {
        int v = g_rp[i] + g_part[blockIdx.x];
        g_rp[i] = v;
        g_cur[i] = v;
    }
}
__global__ void k_scatter(const int* __restrict__ src, const int* __restrict__ dst,
                          const int* __restrict__ et) {
    int e = blockIdx.x * blockDim.x + threadIdx.x;
    if (e < cE) {
        int key = dst[e] * 4 + et[e];
        int pos = atomicAdd(&g_cur[key], 1);
        g_esrc[pos] = src[e];
    }
}
__global__ void k_bsum(const float* __restrict__ bet) {
    int idx = blockIdx.x * blockDim.x + threadIdx.x;
    if (idx >= cN * cD) return;
    int r = idx >> 7, col = idx & 127;
    int rp[5];
#pragma unroll
    for (int k = 0; k <= 4; k++) rp[k] = g_rp[4 * r + k];
    float v = 0.f;
#pragma unroll
    for (int k = 0; k < 4; k++) v += (float)(rp[k + 1] - rp[k]) * __ldg(&bet[k * cD + col]);
    g_bsum[idx] = v;
}
__global__ void k_convw(const float* __restrict__ Wet, const float* __restrict__ Wih,
                        const float* __restrict__ Whh) {
    int i = blockIdx.x * blockDim.x + threadIdx.x;
    if (i < cK * cD * cD) g_wet_h[i] = __float2half_rn(Wet[i]);
    if (i < 3 * cD * cD) {
        g_wih_h[i] = __float2half_rn(Wih[i]);
        g_whh_h[i] = __float2half_rn(Whh[i]);
    }
}

// ---------------- fp16 GEMM building blocks ----------------
constexpr int LD2 = 136;  // halves per smem row (272B stride, conflict-free)

__device__ __forceinline__ void load_tile_X16(const float* __restrict__ X, __half* Xs,
                                              int rowBase, int nrows, int tid) {
    for (int idx = tid; idx < 128 * 32; idx += 256) {
        int row = idx >> 5, c4 = (idx & 31) * 4;
        float4 v = make_float4(0.f, 0.f, 0.f, 0.f);
        int r = rowBase + row;
        if (r < nrows) v = *reinterpret_cast<const float4*>(X + (size_t)r * cD + c4);
        *reinterpret_cast<uint2*>(Xs + row * LD2 + c4) = make_uint2(pk2(v.x, v.y), pk2(v.z, v.w));
    }
}
__device__ __forceinline__ void load_tile_W128_16(const float* __restrict__ W, int ldw, __half* Ws,
                                                  int tid) {
    for (int idx = tid; idx < 128 * 32; idx += 256) {
        int o = idx >> 5, c4 = (idx & 31) * 4;
        float4 v = *reinterpret_cast<const float4*>(W + (size_t)o * ldw + c4);
        *reinterpret_cast<uint2*>(Ws + o * LD2 + c4) = make_uint2(pk2(v.x, v.y), pk2(v.z, v.w));
    }
}
__device__ __forceinline__ uint32_t lds32(const __half* p) {
    return *reinterpret_cast<const uint32_t*>(p);
}

// cp.async tile loaders (f16 source, no register staging). rows*16 16B-chunks.
__device__ __forceinline__ void cpa_tile(const __half* __restrict__ W, __half* Ws,
                                         int rows, int tid) {
    uint32_t base = (uint32_t)__cvta_generic_to_shared(Ws);
    for (int c = tid; c < rows * 16; c += 256) {
        int row = c >> 4, seg = c & 15;
        cpa16(base + (uint32_t)(row * LD2 + seg * 8) * 2, W + row * cD + seg * 8);
    }
    CP_COMMIT();
}

// warp-tile 32x32 mainloop, fp16 k16
__device__ __forceinline__ void mma_loop32(const __half* Xs, const __half* Ws,
                                           int wm, int wn, int gr, int gc, float c[2][4][4]) {
#pragma unroll
    for (int k0 = 0; k0 < cD; k0 += 16) {
        uint32_t a[2][4], b[4][2];
#pragma unroll
        for (int i = 0; i < 2; i++) {
            const __half* base = Xs + (wm + i * 16 + gr) * LD2 + k0 + 2 * gc;
            a[i][0] = lds32(base);
            a[i][1] = lds32(base + 8 * LD2);
            a[i][2] = lds32(base + 8);
            a[i][3] = lds32(base + 8 * LD2 + 8);
        }
#pragma unroll
        for (int j = 0; j < 4; j++) {
            const __half* base = Ws + (wn + j * 8 + gr) * LD2 + k0 + 2 * gc;
            b[j][0] = lds32(base);
            b[j][1] = lds32(base + 8);
        }
#pragma unroll
        for (int i = 0; i < 2; i++)
#pragma unroll
            for (int j = 0; j < 4; j++) mma_f16(c[i][j], a[i], b[j]);
    }
}
// warp-tile 32x64 mainloop, fp16 k16 (head only)
__device__ __forceinline__ void mma_loop64(const __half* Xs, const __half* Ws,
                                           int wm, int wn, int gr, int gc, float c[2][8][4]) {
#pragma unroll
    for (int k0 = 0; k0 < cD; k0 += 16) {
        uint32_t a[2][4], b[8][2];
#pragma unroll
        for (int i = 0; i < 2; i++) {
            const __half* base = Xs + (wm + i * 16 + gr) * LD2 + k0 + 2 * gc;
            a[i][0] = lds32(base);
            a[i][1] = lds32(base + 8 * LD2);
            a[i][2] = lds32(base + 8);
            a[i][3] = lds32(base + 8 * LD2 + 8);
        }
#pragma unroll
        for (int j = 0; j < 8; j++) {
            const __half* base = Ws + (wn + j * 8 + gr) * LD2 + k0 + 2 * gc;
            b[j][0] = lds32(base);
            b[j][1] = lds32(base + 8);
        }
#pragma unroll
        for (int i = 0; i < 2; i++)
#pragma unroll
            for (int j = 0; j < 8; j++) mma_f16(c[i][j], a[i], b[j]);
    }
}

// ---------------- fused aggregation + etype GEMM (64-row blocks; W prefetch under gather) ----------------
constexpr int SM_AE = (64 + 128) * LD2 * 2;  // 52224 -> 3 CTAs/SM

__global__ __launch_bounds__(256, 3) void k_agg_etype(const float* __restrict__ h,
                                                      const __half* __restrict__ wet) {
    extern __shared__ __half smh[];
    __half* Xs = smh;             // 64 x LD2
    __half* Ws = smh + 64 * LD2;  // 128 x LD2
    int tid = threadIdx.x, lane = tid & 31, warp = tid >> 5;
    int rowBase = blockIdx.x * 64;
    int wm = (warp & 1) * 32, wn = (warp >> 1) * 32;
    int gr = lane >> 2, gc = lane & 3;
    const float4* hp = reinterpret_cast<const float4*>(h);

    float c[2][4][4];
#pragma unroll
    for (int i = 0; i < 2; i++)
#pragma unroll
        for (int j = 0; j < 4; j++)
#pragma unroll
            for (int q = 0; q < 4; q++) c[i][j][q] = 0.f;

    for (int ke = 0; ke < cK; ke++) {
        if (ke) __syncthreads();  // mma(ke-1) done reading Xs/Ws
        cpa_tile(wet + (size_t)ke * cD * cD, Ws, 128, tid);  // W load hides under gather
#pragma unroll
        for (int i = 0; i < 8; i++) {
            int vl = warp * 8 + i;
            int v = rowBase + vl;
            float4 acc = make_float4(0.f, 0.f, 0.f, 0.f);
            if (v < cN) {
                int r0 = __ldg(&g_rp[4 * v + ke]), r1 = __ldg(&g_rp[4 * v + ke + 1]);
                int e = r0;
                for (; e + 4 <= r1; e += 4) {
                    int s0 = __ldg(&g_esrc[e]), s1 = __ldg(&g_esrc[e + 1]);
                    int s2 = __ldg(&g_esrc[e + 2]), s3 = __ldg(&g_esrc[e + 3]);
                    float4 x0 = hp[(size_t)s0 * 32 + lane];
                    float4 x1 = hp[(size_t)s1 * 32 + lane];
                    float4 x2 = hp[(size_t)s2 * 32 + lane];
                    float4 x3 = hp[(size_t)s3 * 32 + lane];
                    acc.x += (x0.x + x1.x) + (x2.x + x3.x);
                    acc.y += (x0.y + x1.y) + (x2.y + x3.y);
                    acc.z += (x0.z + x1.z) + (x2.z + x3.z);
                    acc.w += (x0.w + x1.w) + (x2.w + x3.w);
                }
                for (; e < r1; e++) {
                    int s = __ldg(&g_esrc[e]);
                    float4 x = hp[(size_t)s * 32 + lane];
                    acc.x += x.x; acc.y += x.y; acc.z += x.z; acc.w += x.w;
                }
            }
            *reinterpret_cast<uint2*>(Xs + vl * LD2 + lane * 4) =
                make_uint2(pk2(acc.x, acc.y), pk2(acc.z, acc.w));
        }
        CP_WAIT0();
        __syncthreads();
        mma_loop32(Xs, Ws, wm, wn, gr, gc, c);
    }

#pragma unroll
    for (int i = 0; i < 2; i++)
#pragma unroll
        for (int j = 0; j < 4; j++) {
            int col = wn + j * 8 + 2 * gc;
#pragma unroll
            for (int half = 0; half < 2; half++) {
                int r = rowBase + wm + i * 16 + gr + half * 8;
                if (r >= cN) continue;
                float2 bs = *reinterpret_cast<const float2*>(g_bsum + (size_t)r * cD + col);
                float2 o = make_float2(c[i][j][half * 2] + bs.x, c[i][j][half * 2 + 1] + bs.y);
                *reinterpret_cast<float2*>(g_a + (size_t)r * cD + col) = o;
            }
        }
}

// ---------------- fused GRU (grid (782,2)), cp.async double-buffered W ----------------
constexpr int SM_GRU = (2 * 128 + 2 * 64) * LD2 * 2;  // 104448 -> 2 CTAs/SM

__global__ __launch_bounds__(256, 2) void k_gru_fused(
    const float* __restrict__ A, const float* __restrict__ H,
    const __half* __restrict__ wih, const __half* __restrict__ whh,
    const float* __restrict__ b_ih, const float* __restrict__ b_hh,
    float* __restrict__ hout) {
    extern __shared__ __half smh[];
    __half* Xa = smh;
    __half* Xh = smh + 128 * LD2;
    __half* Wb0 = smh + 256 * LD2;
    __half* Wb1 = smh + 320 * LD2;
    int tid = threadIdx.x;
    int rowBase = blockIdx.x * 128, colBase = blockIdx.y * 64;
    int lane = tid & 31, warp = tid >> 5;
    int wm = (warp & 3) * 32, wn = (warp >> 2) * 32;
    int gr = lane >> 2, gc = lane & 3;

    load_tile_X16(A, Xa, rowBase, cN, tid);
    load_tile_X16(H, Xh, rowBase, cN, tid);

    // tile t = g*2 + part: 64-row W slice (output cols colBase..colBase+63)
    auto loadW = [&](int t, __half* buf) {
        int g = t >> 1, part = t & 1;
        const __half* Wp = (part ? whh : wih) + ((size_t)g * 128 + colBase) * cD;
        cpa_tile(Wp, buf, 64, tid);  // register-free
    };
    loadW(0, Wb0);

    float rf[2][4][4], zf[2][4][4], ci[2][4][4], ch[2][4][4];

#pragma unroll 1
    for (int t = 0; t < 6; t++) {
        CP_WAIT0();        // this thread's cp.async for tile t arrived
        __syncthreads();   // all arrived; all finished mma(t-1) -> old buffer free
        if (t + 1 < 6) loadW(t + 1, (t & 1) ? Wb0 : Wb1);
        int g = t >> 1, part = t & 1;
        float (*acc)[4][4] = part ? ch : ci;
#pragma unroll
        for (int i = 0; i < 2; i++)
#pragma unroll
            for (int j = 0; j < 4; j++)
#pragma unroll
                for (int q = 0; q < 4; q++) acc[i][j][q] = 0.f;
        mma_loop32(part ? Xh : Xa, (t & 1) ? Wb1 : Wb0, wm, wn, gr, gc, acc);

        if (part == 1) {
#pragma unroll
            for (int i = 0; i < 2; i++)
#pragma unroll
                for (int j = 0; j < 4; j++) {
                    int col = colBase + wn + j * 8 + 2 * gc;
                    float bi0 = __ldg(&b_ih[g * 128 + col]), bi1 = __ldg(&b_ih[g * 128 + col + 1]);
                    float bh0 = __ldg(&b_hh[g * 128 + col]), bh1 = __ldg(&b_hh[g * 128 + col + 1]);
                    if (g == 0) {
#pragma unroll
                        for (int q = 0; q < 4; q++) {
                            float bi = (q & 1) ? bi1 : bi0, bh = (q & 1) ? bh1 : bh0;
                            rf[i][j][q] = sigmf(ci[i][j][q] + bi + ch[i][j][q] + bh);
                        }
                    } else if (g == 1) {
#pragma unroll
                        for (int q = 0; q < 4; q++) {
                            float bi = (q & 1) ? bi1 : bi0, bh = (q & 1) ? bh1 : bh0;
                            zf[i][j][q] = sigmf(ci[i][j][q] + bi + ch[i][j][q] + bh);
                        }
                    } else {
#pragma unroll
                        for (int half = 0; half < 2; half++) {
                            int r = rowBase + wm + i * 16 + gr + half * 8;
                            if (r >= cN) continue;
                            float2 hv = *reinterpret_cast<const float2*>(H + (size_t)r * cD + col);
                            int q0 = half * 2, q1 = half * 2 + 1;
                            float n0 = tanhf(ci[i][j][q0] + bi0 + rf[i][j][q0] * (ch[i][j][q0] + bh0));
                            float n1 = tanhf(ci[i][j][q1] + bi1 + rf[i][j][q1] * (ch[i][j][q1] + bh1));
                            float2 o;
                            o.x = (1.0f - zf[i][j][q0]) * n0 + zf[i][j][q0] * hv.x;
                            o.y = (1.0f - zf[i][j][q1]) * n1 + zf[i][j][q1] * hv.y;
                            *reinterpret_cast<float2*>(hout + (size_t)r * cD + col) = o;
                        }
                    }
                }
        }
    }
}

// ---------------- fused output head (unchanged R6) ----------------
constexpr int SM_HEAD = 3 * 128 * LD2 * 2;  // 104448 -> 2 CTAs/SM

__global__ __launch_bounds__(256, 2) void k_head(
    const float* __restrict__ H, const float* __restrict__ F,
    const float* __restrict__ i_w, const float* __restrict__ i_b,
    const float* __restrict__ j_w, const float* __restrict__ j_b,
    float* __restrict__ out) {
    extern __shared__ __half smh[];
    __half* Xh = smh;
    __half* Xf = smh + 128 * LD2;
    __half* Ws = smh + 256 * LD2;
    int tid = threadIdx.x;
    int rowBase = blockIdx.x * 128;
    int lane = tid & 31, warp = tid >> 5;
    int wm = (warp & 3) * 32, wn = (warp >> 2) * 64;
    int gr = lane >> 2, gc = lane & 3;

    load_tile_X16(H, Xh, rowBase, cN, tid);
    load_tile_X16(F, Xf, rowBase, cN, tid);

    float cg[2][8][4], cj[2][8][4];
#pragma unroll
    for (int i = 0; i < 2; i++)
#pragma unroll
        for (int j = 0; j < 8; j++)
#pragma unroll
            for (int q = 0; q < 4; q++) { cg[i][j][q] = 0.f; cj[i][j][q] = 0.f; }

    load_tile_W128_16(i_w, 2 * cD, Ws, tid);
    __syncthreads();
    mma_loop64(Xh, Ws, wm, wn, gr, gc, cg);
    __syncthreads();
    load_tile_W128_16(i_w + cD, 2 * cD, Ws, tid);
    __syncthreads();
    mma_loop64(Xf, Ws, wm, wn, gr, gc, cg);
    __syncthreads();
    load_tile_W128_16(j_w, cD, Ws, tid);
    __syncthreads();
    mma_loop64(Xh, Ws, wm, wn, gr, gc, cj);

#pragma unroll
    for (int i = 0; i < 2; i++)
#pragma unroll
        for (int j = 0; j < 8; j++) {
            int col = wn + j * 8 + 2 * gc;
            float ib0 = __ldg(&i_b[col]), ib1 = __ldg(&i_b[col + 1]);
            float jb0 = __ldg(&j_b[col]), jb1 = __ldg(&j_b[col + 1]);
#pragma unroll
            for (int half = 0; half < 2; half++) {
                int r = rowBase + wm + i * 16 + gr + half * 8;
                if (r >= cN) continue;
                int q0 = half * 2, q1 = half * 2 + 1;
                float2 o;
                o.x = sigmf(cg[i][j][q0] + ib0) * (cj[i][j][q0] + jb0);
                o.y = sigmf(cg[i][j][q1] + ib1) * (cj[i][j][q1] + jb1);
                *reinterpret_cast<float2*>(out + (size_t)r * cD + col) = o;
            }
        }
}

// ---------------- host ----------------
extern "C" void kernel_launch(void* const* d_in, const int* in_sizes, int n_in,
                              void* d_out, int out_size) {
    (void)in_sizes; (void)n_in; (void)out_size;
    const float* features = (const float*)d_in[0];
    const int*   src      = (const int*)d_in[1];
    const int*   dst      = (const int*)d_in[2];
    const int*   etypes   = (const int*)d_in[3];
    const float* W_et     = (const float*)d_in[4];
    const float* b_et     = (const float*)d_in[5];
    const float* W_ih     = (const float*)d_in[6];
    const float* b_ih     = (const float*)d_in[7];
    const float* W_hh     = (const float*)d_in[8];
    const float* b_hh     = (const float*)d_in[9];
    const float* i_w      = (const float*)d_in[10];
    const float* i_b      = (const float*)d_in[11];
    const float* j_w      = (const float*)d_in[12];
    const float* j_b      = (const float*)d_in[13];
    float* out = (float*)d_out;

    float *h0, *h1, *abuf;
    __half *wet_h, *wih_h, *whh_h;
    cudaGetSymbolAddress((void**)&h0, g_h0);
    cudaGetSymbolAddress((void**)&h1, g_h1);
    cudaGetSymbolAddress((void**)&abuf, g_a);
    cudaGetSymbolAddress((void**)&wet_h, g_wet_h);
    cudaGetSymbolAddress((void**)&wih_h, g_wih_h);
    cudaGetSymbolAddress((void**)&whh_h, g_whh_h);

    cudaFuncSetAttribute(k_agg_etype, cudaFuncAttributeMaxDynamicSharedMemorySize, SM_AE);
    cudaFuncSetAttribute(k_gru_fused, cudaFuncAttributeMaxDynamicSharedMemorySize, SM_GRU);
    cudaFuncSetAttribute(k_head, cudaFuncAttributeMaxDynamicSharedMemorySize, SM_HEAD);

    // ---- CSR build + weight conversion ----
    k_fill_deg<<<(cM + 255) / 256, 256>>>();
    k_hist<<<(cE + 255) / 256, 256>>>(dst, etypes);
    k_convw<<<(cK * cD * cD + 255) / 256, 256>>>(W_et, W_ih, W_hh);
    k_scan1<<<SCAN_NB, 1024>>>();
    k_scan2<<<1, 512>>>();
    k_scan3<<<SCAN_NB, 1024>>>();
    k_scatter<<<(cE + 255) / 256, 256>>>(src, dst, etypes);
    k_bsum<<<(cN * cD + 255) / 256, 256>>>(b_et);

    const int RB64 = (cN + 63) / 64;    // 1563
    const int RB128 = (cN + 127) / 128; // 782

    const float* hc = features;
    float* houts[3] = {h0, h1, h0};
    for (int s = 0; s < 3; s++) {
        k_agg_etype<<<RB64, 256, SM_AE>>>(hc, wet_h);  // -> g_a
        k_gru_fused<<<dim3(RB128, 2), 256, SM_GRU>>>(abuf, hc, wih_h, whh_h, b_ih, b_hh, houts[s]);
        hc = houts[s];
    }
    k_head<<<RB128, 256, SM_HEAD>>>(hc, features, i_w, i_b, j_w, j_b, out);
}

// round 11
// speedup vs baseline: 1.5984x; 1.0561x over previous
#include <cuda_runtime.h>
#include <cuda_fp16.h>
#include <cstdint>

// ---------------- problem constants ----------------
constexpr int cN = 100000;   // nodes
constexpr int cE = 1600000;  // edges
constexpr int cD = 128;      // feature dim
constexpr int cK = 4;        // etypes
constexpr int cM = cK * cN;                 // 400000 keys (dst*4+etype)
constexpr int NTILE = (cM + 1023) / 1024;   // 391 scan tiles

// ---------------- scratch ----------------
__device__ __align__(16) float g_h0[(size_t)cN * cD];
__device__ __align__(16) float g_h1[(size_t)cN * cD];
__device__ __align__(16) float g_a[(size_t)cN * cD];
__device__ __align__(16) float g_bsum[(size_t)cN * cD];

__device__ int g_deg[cM];          // zero-initialized; re-zeroed by k_scanlb each launch
__device__ int g_rp[cM + 1];
__device__ int g_cur[cM];
__device__ int g_esrc[cE];
__device__ unsigned long long g_lbstate[NTILE + 1];
__device__ int g_ticket;

// ---------------- helpers ----------------
__device__ __forceinline__ float sigmf(float x) { return 1.0f / (1.0f + __expf(-x)); }

__device__ __forceinline__ uint32_t pk2(float x, float y) {
    __half2 h = __floats2half2_rn(x, y);
    return *reinterpret_cast<uint32_t*>(&h);
}

__device__ __forceinline__ void mma_f16(float c[4], const uint32_t a[4], const uint32_t b[2]) {
    asm volatile(
        "mma.sync.aligned.m16n8k16.row.col.f32.f16.f16.f32 "
        "{%0,%1,%2,%3}, {%4,%5,%6,%7}, {%8,%9}, {%0,%1,%2,%3};"
        : "+f"(c[0]), "+f"(c[1]), "+f"(c[2]), "+f"(c[3])
        : "r"(a[0]), "r"(a[1]), "r"(a[2]), "r"(a[3]), "r"(b[0]), "r"(b[1]));
}

// ---------------- CSR build: 3 kernels ----------------
// (0) histogram; also resets scan bookkeeping for this launch
__global__ void k_hist(const int* __restrict__ dst, const int* __restrict__ et) {
    int e = blockIdx.x * blockDim.x + threadIdx.x;
    if (e < cE) atomicAdd(&g_deg[dst[e] * 4 + et[e]], 1);
    if (blockIdx.x == 0) {
        if (threadIdx.x == 0) g_ticket = 0;
        for (int i = threadIdx.x; i <= NTILE; i += blockDim.x) g_lbstate[i] = 0ull;
    }
}

// (1) single-pass exclusive scan with decoupled lookback.
// Writes g_rp (exclusive) + g_cur, sets g_rp[cM], and re-zeros g_deg for the next replay.
__global__ void k_scanlb() {
    __shared__ int sm[1024];
    __shared__ int bid_s, exc_s;
    if (threadIdx.x == 0) bid_s = atomicAdd(&g_ticket, 1);
    __syncthreads();
    int bid = bid_s;
    int i = bid * 1024 + threadIdx.x;
    int v = 0;
    if (i < cM) {
        v = g_deg[i];
        g_deg[i] = 0;  // reset for next launch (value already consumed)
    }
    sm[threadIdx.x] = v;
    __syncthreads();
    for (int off = 1; off < 1024; off <<= 1) {
        int t = 0;
        if (threadIdx.x >= off) t = sm[threadIdx.x - off];
        __syncthreads();
        sm[threadIdx.x] += t;
        __syncthreads();
    }
    int total = sm[1023];
    if (threadIdx.x == 0) {
        if (bid == 0) {
            atomicExch(&g_lbstate[0], (2ull << 32) | (unsigned)total);
            exc_s = 0;
        } else {
            atomicExch(&g_lbstate[bid], (1ull << 32) | (unsigned)total);
            int exc = 0;
            for (int j = bid - 1;; j--) {
                unsigned long long s;
                do { s = atomicAdd(&g_lbstate[j], 0ull); } while ((s >> 32) == 0ull);
                exc += (int)(unsigned)(s & 0xffffffffull);
                if ((s >> 32) == 2ull) break;
            }
            atomicExch(&g_lbstate[bid], (2ull << 32) | (unsigned)(exc + total));
            exc_s = exc;
        }
    }
    __syncthreads();
    int exc = exc_s;
    if (i < cM) {
        int rp = exc + sm[threadIdx.x] - v;  // exclusive
        g_rp[i] = rp;
        g_cur[i] = rp;
    }
    if (bid == NTILE - 1 && threadIdx.x == 1023) g_rp[cM] = exc + total;
}

// (2) scatter edges into CSR order + per-node etype-bias sums (independent work, one launch)
__global__ void k_scatter_bsum(const int* __restrict__ src, const int* __restrict__ dst,
                               const int* __restrict__ et, const float* __restrict__ bet) {
    int idx = blockIdx.x * blockDim.x + threadIdx.x;
    if (idx < cE) {
        int key = dst[idx] * 4 + et[idx];
        int pos = atomicAdd(&g_cur[key], 1);
        g_esrc[pos] = src[idx];
    }
    if (idx < cN * cD) {
        int r = idx >> 7, col = idx & 127;
        int rp[5];
#pragma unroll
        for (int k = 0; k <= 4; k++) rp[k] = g_rp[4 * r + k];
        float v = 0.f;
#pragma unroll
        for (int k = 0; k < 4; k++) v += (float)(rp[k + 1] - rp[k]) * __ldg(&bet[k * cD + col]);
        g_bsum[idx] = v;
    }
}

// ---------------- fp16 GEMM building blocks (R6 verbatim) ----------------
constexpr int LD2 = 136;  // halves per smem row (272B stride, conflict-free)

__device__ __forceinline__ void load_tile_X16(const float* __restrict__ X, __half* Xs,
                                              int rowBase, int nrows, int tid) {
    for (int idx = tid; idx < 128 * 32; idx += 256) {
        int row = idx >> 5, c4 = (idx & 31) * 4;
        float4 v = make_float4(0.f, 0.f, 0.f, 0.f);
        int r = rowBase + row;
        if (r < nrows) v = *reinterpret_cast<const float4*>(X + (size_t)r * cD + c4);
        *reinterpret_cast<uint2*>(Xs + row * LD2 + c4) = make_uint2(pk2(v.x, v.y), pk2(v.z, v.w));
    }
}
__device__ __forceinline__ void load_tile_W64_16(const float* __restrict__ W, int ldw, __half* Ws,
                                                 int colBase, int tid) {
    for (int idx = tid; idx < 64 * 32; idx += 256) {
        int o = idx >> 5, c4 = (idx & 31) * 4;
        float4 v = *reinterpret_cast<const float4*>(W + (size_t)(colBase + o) * ldw + c4);
        *reinterpret_cast<uint2*>(Ws + o * LD2 + c4) = make_uint2(pk2(v.x, v.y), pk2(v.z, v.w));
    }
}
__device__ __forceinline__ void load_tile_W128_16(const float* __restrict__ W, int ldw, __half* Ws,
                                                  int tid) {
    for (int idx = tid; idx < 128 * 32; idx += 256) {
        int o = idx >> 5, c4 = (idx & 31) * 4;
        float4 v = *reinterpret_cast<const float4*>(W + (size_t)o * ldw + c4);
        *reinterpret_cast<uint2*>(Ws + o * LD2 + c4) = make_uint2(pk2(v.x, v.y), pk2(v.z, v.w));
    }
}
__device__ __forceinline__ uint32_t lds32(const __half* p) {
    return *reinterpret_cast<const uint32_t*>(p);
}

__device__ __forceinline__ void mma_loop32(const __half* Xs, const __half* Ws,
                                           int wm, int wn, int gr, int gc, float c[2][4][4]) {
#pragma unroll
    for (int k0 = 0; k0 < cD; k0 += 16) {
        uint32_t a[2][4], b[4][2];
#pragma unroll
        for (int i = 0; i < 2; i++) {
            const __half* base = Xs + (wm + i * 16 + gr) * LD2 + k0 + 2 * gc;
            a[i][0] = lds32(base);
            a[i][1] = lds32(base + 8 * LD2);
            a[i][2] = lds32(base + 8);
            a[i][3] = lds32(base + 8 * LD2 + 8);
        }
#pragma unroll
        for (int j = 0; j < 4; j++) {
            const __half* base = Ws + (wn + j * 8 + gr) * LD2 + k0 + 2 * gc;
            b[j][0] = lds32(base);
            b[j][1] = lds32(base + 8);
        }
#pragma unroll
        for (int i = 0; i < 2; i++)
#pragma unroll
            for (int j = 0; j < 4; j++) mma_f16(c[i][j], a[i], b[j]);
    }
}
__device__ __forceinline__ void mma_loop64(const __half* Xs, const __half* Ws,
                                           int wm, int wn, int gr, int gc, float c[2][8][4]) {
#pragma unroll
    for (int k0 = 0; k0 < cD; k0 += 16) {
        uint32_t a[2][4], b[8][2];
#pragma unroll
        for (int i = 0; i < 2; i++) {
            const __half* base = Xs + (wm + i * 16 + gr) * LD2 + k0 + 2 * gc;
            a[i][0] = lds32(base);
            a[i][1] = lds32(base + 8 * LD2);
            a[i][2] = lds32(base + 8);
            a[i][3] = lds32(base + 8 * LD2 + 8);
        }
#pragma unroll
        for (int j = 0; j < 8; j++) {
            const __half* base = Ws + (wn + j * 8 + gr) * LD2 + k0 + 2 * gc;
            b[j][0] = lds32(base);
            b[j][1] = lds32(base + 8);
        }
#pragma unroll
        for (int i = 0; i < 2; i++)
#pragma unroll
            for (int j = 0; j < 8; j++) mma_f16(c[i][j], a[i], b[j]);
    }
}

// ---------------- fused aggregation + etype GEMM (R6 verbatim) ----------------
constexpr int SM_AE = (64 + 128) * LD2 * 2;  // 52224 -> 3 CTAs/SM

__global__ __launch_bounds__(256, 3) void k_agg_etype(const float* __restrict__ h,
                                                      const float* __restrict__ Wet) {
    extern __shared__ __half smh[];
    __half* Xs = smh;             // 64 x LD2
    __half* Ws = smh + 64 * LD2;  // 128 x LD2
    int tid = threadIdx.x, lane = tid & 31, warp = tid >> 5;
    int rowBase = blockIdx.x * 64;
    int wm = (warp & 1) * 32, wn = (warp >> 1) * 32;
    int gr = lane >> 2, gc = lane & 3;
    const float4* hp = reinterpret_cast<const float4*>(h);

    float c[2][4][4];
#pragma unroll
    for (int i = 0; i < 2; i++)
#pragma unroll
        for (int j = 0; j < 4; j++)
#pragma unroll
            for (int q = 0; q < 4; q++) c[i][j][q] = 0.f;

    for (int ke = 0; ke < cK; ke++) {
        if (ke) __syncthreads();
#pragma unroll
        for (int i = 0; i < 8; i++) {
            int vl = warp * 8 + i;
            int v = rowBase + vl;
            float4 acc = make_float4(0.f, 0.f, 0.f, 0.f);
            if (v < cN) {
                int r0 = __ldg(&g_rp[4 * v + ke]), r1 = __ldg(&g_rp[4 * v + ke + 1]);
                int e = r0;
                for (; e + 4 <= r1; e += 4) {
                    int s0 = __ldg(&g_esrc[e]), s1 = __ldg(&g_esrc[e + 1]);
                    int s2 = __ldg(&g_esrc[e + 2]), s3 = __ldg(&g_esrc[e + 3]);
                    float4 x0 = hp[(size_t)s0 * 32 + lane];
                    float4 x1 = hp[(size_t)s1 * 32 + lane];
                    float4 x2 = hp[(size_t)s2 * 32 + lane];
                    float4 x3 = hp[(size_t)s3 * 32 + lane];
                    acc.x += (x0.x + x1.x) + (x2.x + x3.x);
                    acc.y += (x0.y + x1.y) + (x2.y + x3.y);
                    acc.z += (x0.z + x1.z) + (x2.z + x3.z);
                    acc.w += (x0.w + x1.w) + (x2.w + x3.w);
                }
                for (; e < r1; e++) {
                    int s = __ldg(&g_esrc[e]);
                    float4 x = hp[(size_t)s * 32 + lane];
                    acc.x += x.x; acc.y += x.y; acc.z += x.z; acc.w += x.w;
                }
            }
            *reinterpret_cast<uint2*>(Xs + vl * LD2 + lane * 4) =
                make_uint2(pk2(acc.x, acc.y), pk2(acc.z, acc.w));
        }
        load_tile_W128_16(Wet + (size_t)ke * cD * cD, cD, Ws, tid);
        __syncthreads();
        mma_loop32(Xs, Ws, wm, wn, gr, gc, c);
    }

#pragma unroll
    for (int i = 0; i < 2; i++)
#pragma unroll
        for (int j = 0; j < 4; j++) {
            int col = wn + j * 8 + 2 * gc;
#pragma unroll
            for (int half = 0; half < 2; half++) {
                int r = rowBase + wm + i * 16 + gr + half * 8;
                if (r >= cN) continue;
                float2 bs = *reinterpret_cast<const float2*>(g_bsum + (size_t)r * cD + col);
                float2 o = make_float2(c[i][j][half * 2] + bs.x, c[i][j][half * 2 + 1] + bs.y);
                *reinterpret_cast<float2*>(g_a + (size_t)r * cD + col) = o;
            }
        }
}

// ---------------- fused GRU (R6 verbatim) ----------------
constexpr int SM_GRU = (2 * 128 + 64) * LD2 * 2;  // 87040 -> 2 CTAs/SM

__global__ __launch_bounds__(256, 2) void k_gru_fused(
    const float* __restrict__ A, const float* __restrict__ H,
    const float* __restrict__ W_ih, const float* __restrict__ b_ih,
    const float* __restrict__ W_hh, const float* __restrict__ b_hh,
    float* __restrict__ hout) {
    extern __shared__ __half smh[];
    __half* Xa = smh;
    __half* Xh = smh + 128 * LD2;
    __half* Ws = smh + 256 * LD2;
    int tid = threadIdx.x;
    int rowBase = blockIdx.x * 128, colBase = blockIdx.y * 64;
    int lane = tid & 31, warp = tid >> 5;
    int wm = (warp & 3) * 32, wn = (warp >> 2) * 32;
    int gr = lane >> 2, gc = lane & 3;

    load_tile_X16(A, Xa, rowBase, cN, tid);
    load_tile_X16(H, Xh, rowBase, cN, tid);

    float rf[2][4][4], zf[2][4][4], ci[2][4][4], ch[2][4][4];

#pragma unroll
    for (int g = 0; g < 3; g++) {
#pragma unroll
        for (int i = 0; i < 2; i++)
#pragma unroll
            for (int j = 0; j < 4; j++)
#pragma unroll
                for (int q = 0; q < 4; q++) { ci[i][j][q] = 0.f; ch[i][j][q] = 0.f; }

        load_tile_W64_16(W_ih + (size_t)g * 128 * cD, cD, Ws, colBase, tid);
        __syncthreads();
        mma_loop32(Xa, Ws, wm, wn, gr, gc, ci);
        __syncthreads();
        load_tile_W64_16(W_hh + (size_t)g * 128 * cD, cD, Ws, colBase, tid);
        __syncthreads();
        mma_loop32(Xh, Ws, wm, wn, gr, gc, ch);
        __syncthreads();

#pragma unroll
        for (int i = 0; i < 2; i++)
#pragma unroll
            for (int j = 0; j < 4; j++) {
                int col = colBase + wn + j * 8 + 2 * gc;
                float bi0 = __ldg(&b_ih[g * 128 + col]), bi1 = __ldg(&b_ih[g * 128 + col + 1]);
                float bh0 = __ldg(&b_hh[g * 128 + col]), bh1 = __ldg(&b_hh[g * 128 + col + 1]);
                if (g == 0) {
#pragma unroll
                    for (int q = 0; q < 4; q++) {
                        float bi = (q & 1) ? bi1 : bi0, bh = (q & 1) ? bh1 : bh0;
                        rf[i][j][q] = sigmf(ci[i][j][q] + bi + ch[i][j][q] + bh);
                    }
                } else if (g == 1) {
#pragma unroll
                    for (int q = 0; q < 4; q++) {
                        float bi = (q & 1) ? bi1 : bi0, bh = (q & 1) ? bh1 : bh0;
                        zf[i][j][q] = sigmf(ci[i][j][q] + bi + ch[i][j][q] + bh);
                    }
                } else {
#pragma unroll
                    for (int half = 0; half < 2; half++) {
                        int r = rowBase + wm + i * 16 + gr + half * 8;
                        if (r >= cN) continue;
                        float2 hv = *reinterpret_cast<const float2*>(H + (size_t)r * cD + col);
                        int q0 = half * 2, q1 = half * 2 + 1;
                        float n0 = tanhf(ci[i][j][q0] + bi0 + rf[i][j][q0] * (ch[i][j][q0] + bh0));
                        float n1 = tanhf(ci[i][j][q1] + bi1 + rf[i][j][q1] * (ch[i][j][q1] + bh1));
                        float2 o;
                        o.x = (1.0f - zf[i][j][q0]) * n0 + zf[i][j][q0] * hv.x;
                        o.y = (1.0f - zf[i][j][q1]) * n1 + zf[i][j][q1] * hv.y;
                        *reinterpret_cast<float2*>(hout + (size_t)r * cD + col) = o;
                    }
                }
            }
    }
}

// ---------------- fused output head (R6 verbatim) ----------------
constexpr int SM_HEAD = 3 * 128 * LD2 * 2;  // 104448 -> 2 CTAs/SM

__global__ __launch_bounds__(256, 2) void k_head(
    const float* __restrict__ H, const float* __restrict__ F,
    const float* __restrict__ i_w, const float* __restrict__ i_b,
    const float* __restrict__ j_w, const float* __restrict__ j_b,
    float* __restrict__ out) {
    extern __shared__ __half smh[];
    __half* Xh = smh;
    __half* Xf = smh + 128 * LD2;
    __half* Ws = smh + 256 * LD2;
    int tid = threadIdx.x;
    int rowBase = blockIdx.x * 128;
    int lane = tid & 31, warp = tid >> 5;
    int wm = (warp & 3) * 32, wn = (warp >> 2) * 64;
    int gr = lane >> 2, gc = lane & 3;

    load_tile_X16(H, Xh, rowBase, cN, tid);
    load_tile_X16(F, Xf, rowBase, cN, tid);

    float cg[2][8][4], cj[2][8][4];
#pragma unroll
    for (int i = 0; i < 2; i++)
#pragma unroll
        for (int j = 0; j < 8; j++)
#pragma unroll
            for (int q = 0; q < 4; q++) { cg[i][j][q] = 0.f; cj[i][j][q] = 0.f; }

    load_tile_W128_16(i_w, 2 * cD, Ws, tid);
    __syncthreads();
    mma_loop64(Xh, Ws, wm, wn, gr, gc, cg);
    __syncthreads();
    load_tile_W128_16(i_w + cD, 2 * cD, Ws, tid);
    __syncthreads();
    mma_loop64(Xf, Ws, wm, wn, gr, gc, cg);
    __syncthreads();
    load_tile_W128_16(j_w, cD, Ws, tid);
    __syncthreads();
    mma_loop64(Xh, Ws, wm, wn, gr, gc, cj);

#pragma unroll
    for (int i = 0; i < 2; i++)
#pragma unroll
        for (int j = 0; j < 8; j++) {
            int col = wn + j * 8 + 2 * gc;
            float ib0 = __ldg(&i_b[col]), ib1 = __ldg(&i_b[col + 1]);
            float jb0 = __ldg(&j_b[col]), jb1 = __ldg(&j_b[col + 1]);
#pragma unroll
            for (int half = 0; half < 2; half++) {
                int r = rowBase + wm + i * 16 + gr + half * 8;
                if (r >= cN) continue;
                int q0 = half * 2, q1 = half * 2 + 1;
                float2 o;
                o.x = sigmf(cg[i][j][q0] + ib0) * (cj[i][j][q0] + jb0);
                o.y = sigmf(cg[i][j][q1] + ib1) * (cj[i][j][q1] + jb1);
                *reinterpret_cast<float2*>(out + (size_t)r * cD + col) = o;
            }
        }
}

// ---------------- host ----------------
extern "C" void kernel_launch(void* const* d_in, const int* in_sizes, int n_in,
                              void* d_out, int out_size) {
    (void)in_sizes; (void)n_in; (void)out_size;
    const float* features = (const float*)d_in[0];
    const int*   src      = (const int*)d_in[1];
    const int*   dst      = (const int*)d_in[2];
    const int*   etypes   = (const int*)d_in[3];
    const float* W_et     = (const float*)d_in[4];
    const float* b_et     = (const float*)d_in[5];
    const float* W_ih     = (const float*)d_in[6];
    const float* b_ih     = (const float*)d_in[7];
    const float* W_hh     = (const float*)d_in[8];
    const float* b_hh     = (const float*)d_in[9];
    const float* i_w      = (const float*)d_in[10];
    const float* i_b      = (const float*)d_in[11];
    const float* j_w      = (const float*)d_in[12];
    const float* j_b      = (const float*)d_in[13];
    float* out = (float*)d_out;

    float *h0, *h1, *abuf;
    cudaGetSymbolAddress((void**)&h0, g_h0);
    cudaGetSymbolAddress((void**)&h1, g_h1);
    cudaGetSymbolAddress((void**)&abuf, g_a);

    cudaFuncSetAttribute(k_agg_etype, cudaFuncAttributeMaxDynamicSharedMemorySize, SM_AE);
    cudaFuncSetAttribute(k_gru_fused, cudaFuncAttributeMaxDynamicSharedMemorySize, SM_GRU);
    cudaFuncSetAttribute(k_head, cudaFuncAttributeMaxDynamicSharedMemorySize, SM_HEAD);

    // ---- CSR build: 3 launches, then agg is launch index 3 (ncu window) ----
    k_hist<<<(cE + 255) / 256, 256>>>(dst, etypes);
    k_scanlb<<<NTILE, 1024>>>();
    {
        int tot = cN * cD > cE ? cN * cD : cE;
        k_scatter_bsum<<<(tot + 255) / 256, 256>>>(src, dst, etypes, b_et);
    }

    const int RB64 = (cN + 63) / 64;    // 1563
    const int RB128 = (cN + 127) / 128; // 782

    const float* hc = features;
    float* houts[3] = {h0, h1, h0};
    for (int s = 0; s < 3; s++) {
        k_agg_etype<<<RB64, 256, SM_AE>>>(hc, W_et);  // -> g_a
        k_gru_fused<<<dim3(RB128, 2), 256, SM_GRU>>>(abuf, hc, W_ih, b_ih, W_hh, b_hh, houts[s]);
        hc = houts[s];
    }
    k_head<<<RB128, 256, SM_HEAD>>>(hc, features, i_w, i_b, j_w, j_b, out);
}

// round 12
// speedup vs baseline: 1.7147x; 1.0727x over previous
#include <cuda_runtime.h>
#include <cuda_fp16.h>
#include <cstdint>

// ---------------- problem constants ----------------
constexpr int cN = 100000;   // nodes
constexpr int cE = 1600000;  // edges
constexpr int cD = 128;      // feature dim
constexpr int cK = 4;        // etypes
constexpr int cM = cK * cN;                 // 400000 keys (dst*4+etype)
constexpr int NTILE = (cM + 1023) / 1024;   // 391 scan tiles

// ---------------- scratch ----------------
__device__ __align__(16) float g_h0[(size_t)cN * cD];
__device__ __align__(16) float g_h1[(size_t)cN * cD];
__device__ __align__(16) float g_a[(size_t)cN * cD];
__device__ __align__(16) float g_bsum[(size_t)cN * cD];

__device__ int g_deg[cM];          // zero-initialized; re-zeroed by k_scanlb each launch
__device__ int g_rp[cM + 1];
__device__ int g_cur[cM];
__device__ int g_esrc[cE];
__device__ unsigned long long g_lbstate[NTILE + 1];
__device__ int g_ticket;

// ---------------- helpers ----------------
__device__ __forceinline__ float sigmf(float x) { return 1.0f / (1.0f + __expf(-x)); }

__device__ __forceinline__ uint32_t pk2(float x, float y) {
    __half2 h = __floats2half2_rn(x, y);
    return *reinterpret_cast<uint32_t*>(&h);
}

__device__ __forceinline__ void mma_f16(float c[4], const uint32_t a[4], const uint32_t b[2]) {
    asm volatile(
        "mma.sync.aligned.m16n8k16.row.col.f32.f16.f16.f32 "
        "{%0,%1,%2,%3}, {%4,%5,%6,%7}, {%8,%9}, {%0,%1,%2,%3};"
        : "+f"(c[0]), "+f"(c[1]), "+f"(c[2]), "+f"(c[3])
        : "r"(a[0]), "r"(a[1]), "r"(a[2]), "r"(a[3]), "r"(b[0]), "r"(b[1]));
}

// ---------------- CSR build: 3 kernels ----------------
__global__ void k_hist(const int* __restrict__ dst, const int* __restrict__ et) {
    int e = blockIdx.x * blockDim.x + threadIdx.x;
    if (e < cE) atomicAdd(&g_deg[dst[e] * 4 + et[e]], 1);
    if (blockIdx.x == 0) {
        if (threadIdx.x == 0) g_ticket = 0;
        for (int i = threadIdx.x; i <= NTILE; i += blockDim.x) g_lbstate[i] = 0ull;
    }
}

__global__ void k_scanlb() {
    __shared__ int sm[1024];
    __shared__ int bid_s, exc_s;
    if (threadIdx.x == 0) bid_s = atomicAdd(&g_ticket, 1);
    __syncthreads();
    int bid = bid_s;
    int i = bid * 1024 + threadIdx.x;
    int v = 0;
    if (i < cM) {
        v = g_deg[i];
        g_deg[i] = 0;  // reset for next launch
    }
    sm[threadIdx.x] = v;
    __syncthreads();
    for (int off = 1; off < 1024; off <<= 1) {
        int t = 0;
        if (threadIdx.x >= off) t = sm[threadIdx.x - off];
        __syncthreads();
        sm[threadIdx.x] += t;
        __syncthreads();
    }
    int total = sm[1023];
    if (threadIdx.x == 0) {
        if (bid == 0) {
            atomicExch(&g_lbstate[0], (2ull << 32) | (unsigned)total);
            exc_s = 0;
        } else {
            atomicExch(&g_lbstate[bid], (1ull << 32) | (unsigned)total);
            int exc = 0;
            for (int j = bid - 1;; j--) {
                unsigned long long s;
                do { s = atomicAdd(&g_lbstate[j], 0ull); } while ((s >> 32) == 0ull);
                exc += (int)(unsigned)(s & 0xffffffffull);
                if ((s >> 32) == 2ull) break;
            }
            atomicExch(&g_lbstate[bid], (2ull << 32) | (unsigned)(exc + total));
            exc_s = exc;
        }
    }
    __syncthreads();
    int exc = exc_s;
    if (i < cM) {
        int rp = exc + sm[threadIdx.x] - v;  // exclusive
        g_rp[i] = rp;
        g_cur[i] = rp;
    }
    if (bid == NTILE - 1 && threadIdx.x == 1023) g_rp[cM] = exc + total;
}

__global__ void k_scatter_bsum(const int* __restrict__ src, const int* __restrict__ dst,
                               const int* __restrict__ et, const float* __restrict__ bet) {
    int idx = blockIdx.x * blockDim.x + threadIdx.x;
    if (idx < cE) {
        int key = dst[idx] * 4 + et[idx];
        int pos = atomicAdd(&g_cur[key], 1);
        g_esrc[pos] = src[idx];
    }
    if (idx < cN * cD) {
        int r = idx >> 7, col = idx & 127;
        int rp[5];
#pragma unroll
        for (int k = 0; k <= 4; k++) rp[k] = g_rp[4 * r + k];
        float v = 0.f;
#pragma unroll
        for (int k = 0; k < 4; k++) v += (float)(rp[k + 1] - rp[k]) * __ldg(&bet[k * cD + col]);
        g_bsum[idx] = v;
    }
}

// ---------------- fp16 GEMM building blocks ----------------
constexpr int LD2 = 136;  // halves per smem row (272B stride, conflict-free)

__device__ __forceinline__ void load_tile_X16(const float* __restrict__ X, __half* Xs,
                                              int rowBase, int nrows, int tid) {
    for (int idx = tid; idx < 128 * 32; idx += 256) {
        int row = idx >> 5, c4 = (idx & 31) * 4;
        float4 v = make_float4(0.f, 0.f, 0.f, 0.f);
        int r = rowBase + row;
        if (r < nrows) v = *reinterpret_cast<const float4*>(X + (size_t)r * cD + c4);
        *reinterpret_cast<uint2*>(Xs + row * LD2 + c4) = make_uint2(pk2(v.x, v.y), pk2(v.z, v.w));
    }
}
__device__ __forceinline__ void load_tile_W64_16(const float* __restrict__ W, int ldw, __half* Ws,
                                                 int colBase, int tid) {
    for (int idx = tid; idx < 64 * 32; idx += 256) {
        int o = idx >> 5, c4 = (idx & 31) * 4;
        float4 v = *reinterpret_cast<const float4*>(W + (size_t)(colBase + o) * ldw + c4);
        *reinterpret_cast<uint2*>(Ws + o * LD2 + c4) = make_uint2(pk2(v.x, v.y), pk2(v.z, v.w));
    }
}
__device__ __forceinline__ void load_tile_W128_16(const float* __restrict__ W, int ldw, __half* Ws,
                                                  int tid) {
    for (int idx = tid; idx < 128 * 32; idx += 256) {
        int o = idx >> 5, c4 = (idx & 31) * 4;
        float4 v = *reinterpret_cast<const float4*>(W + (size_t)o * ldw + c4);
        *reinterpret_cast<uint2*>(Ws + o * LD2 + c4) = make_uint2(pk2(v.x, v.y), pk2(v.z, v.w));
    }
}
__device__ __forceinline__ uint32_t lds32(const __half* p) {
    return *reinterpret_cast<const uint32_t*>(p);
}

__device__ __forceinline__ void mma_loop32(const __half* Xs, const __half* Ws,
                                           int wm, int wn, int gr, int gc, float c[2][4][4]) {
#pragma unroll
    for (int k0 = 0; k0 < cD; k0 += 16) {
        uint32_t a[2][4], b[4][2];
#pragma unroll
        for (int i = 0; i < 2; i++) {
            const __half* base = Xs + (wm + i * 16 + gr) * LD2 + k0 + 2 * gc;
            a[i][0] = lds32(base);
            a[i][1] = lds32(base + 8 * LD2);
            a[i][2] = lds32(base + 8);
            a[i][3] = lds32(base + 8 * LD2 + 8);
        }
#pragma unroll
        for (int j = 0; j < 4; j++) {
            const __half* base = Ws + (wn + j * 8 + gr) * LD2 + k0 + 2 * gc;
            b[j][0] = lds32(base);
            b[j][1] = lds32(base + 8);
        }
#pragma unroll
        for (int i = 0; i < 2; i++)
#pragma unroll
            for (int j = 0; j < 4; j++) mma_f16(c[i][j], a[i], b[j]);
    }
}
__device__ __forceinline__ void mma_loop64(const __half* Xs, const __half* Ws,
                                           int wm, int wn, int gr, int gc, float c[2][8][4]) {
#pragma unroll
    for (int k0 = 0; k0 < cD; k0 += 16) {
        uint32_t a[2][4], b[8][2];
#pragma unroll
        for (int i = 0; i < 2; i++) {
            const __half* base = Xs + (wm + i * 16 + gr) * LD2 + k0 + 2 * gc;
            a[i][0] = lds32(base);
            a[i][1] = lds32(base + 8 * LD2);
            a[i][2] = lds32(base + 8);
            a[i][3] = lds32(base + 8 * LD2 + 8);
        }
#pragma unroll
        for (int j = 0; j < 8; j++) {
            const __half* base = Ws + (wn + j * 8 + gr) * LD2 + k0 + 2 * gc;
            b[j][0] = lds32(base);
            b[j][1] = lds32(base + 8);
        }
#pragma unroll
        for (int i = 0; i < 2; i++)
#pragma unroll
            for (int j = 0; j < 8; j++) mma_f16(c[i][j], a[i], b[j]);
    }
}

// ---------------- fused aggregation + etype GEMM ----------------
// smem: X tile (64 x LD2 f16) + W tile (128 x LD2 f16) + rp cache (260 ints)
constexpr int SM_AE = (64 + 128) * LD2 * 2 + 260 * 4;  // 53264 -> 3 CTAs/SM (regs bind)

__global__ __launch_bounds__(256, 3) void k_agg_etype(const float* __restrict__ h,
                                                      const float* __restrict__ Wet) {
    extern __shared__ __half smh[];
    __half* Xs = smh;             // 64 x LD2
    __half* Ws = smh + 64 * LD2;  // 128 x LD2
    int* rps = reinterpret_cast<int*>(smh + 192 * LD2);  // 257 used
    int tid = threadIdx.x, lane = tid & 31, warp = tid >> 5;
    int rowBase = blockIdx.x * 64;
    int wm = (warp & 1) * 32, wn = (warp >> 1) * 32;
    int gr = lane >> 2, gc = lane & 3;
    const float4* hp = reinterpret_cast<const float4*>(h);

    // stage this block's row-pointer window once (kills per-segment rp latency)
    {
        int base = 4 * rowBase;
        for (int i = tid; i < 257; i += 256) {
            int g = base + i;
            rps[i] = g_rp[g <= cM ? g : cM];
        }
    }
    __syncthreads();

    float c[2][4][4];
#pragma unroll
    for (int i = 0; i < 2; i++)
#pragma unroll
        for (int j = 0; j < 4; j++)
#pragma unroll
            for (int q = 0; q < 4; q++) c[i][j][q] = 0.f;

    for (int ke = 0; ke < cK; ke++) {
        if (ke) __syncthreads();  // mma(ke-1) done reading Xs/Ws
#pragma unroll
        for (int i = 0; i < 8; i++) {
            int vl = warp * 8 + i;
            float4 acc = make_float4(0.f, 0.f, 0.f, 0.f);
            {
                int r0 = rps[4 * vl + ke], r1 = rps[4 * vl + ke + 1];
                int e = r0;
                for (; e + 4 <= r1; e += 4) {  // MLP-4 main loop
                    int s0 = __ldg(&g_esrc[e]), s1 = __ldg(&g_esrc[e + 1]);
                    int s2 = __ldg(&g_esrc[e + 2]), s3 = __ldg(&g_esrc[e + 3]);
                    float4 x0 = hp[(size_t)s0 * 32 + lane];
                    float4 x1 = hp[(size_t)s1 * 32 + lane];
                    float4 x2 = hp[(size_t)s2 * 32 + lane];
                    float4 x3 = hp[(size_t)s3 * 32 + lane];
                    acc.x += (x0.x + x1.x) + (x2.x + x3.x);
                    acc.y += (x0.y + x1.y) + (x2.y + x3.y);
                    acc.z += (x0.z + x1.z) + (x2.z + x3.z);
                    acc.w += (x0.w + x1.w) + (x2.w + x3.w);
                }
                int rem = r1 - e;  // 0..3: parallel predicated tail, adds in order
                if (rem > 0) {
                    int s0 = __ldg(&g_esrc[e]);
                    int s1 = (rem > 1) ? __ldg(&g_esrc[e + 1]) : s0;
                    int s2 = (rem > 2) ? __ldg(&g_esrc[e + 2]) : s0;
                    float4 x0 = hp[(size_t)s0 * 32 + lane];
                    float4 x1 = hp[(size_t)s1 * 32 + lane];
                    float4 x2 = hp[(size_t)s2 * 32 + lane];
                    acc.x += x0.x; acc.y += x0.y; acc.z += x0.z; acc.w += x0.w;
                    if (rem > 1) { acc.x += x1.x; acc.y += x1.y; acc.z += x1.z; acc.w += x1.w; }
                    if (rem > 2) { acc.x += x2.x; acc.y += x2.y; acc.z += x2.z; acc.w += x2.w; }
                }
            }
            *reinterpret_cast<uint2*>(Xs + vl * LD2 + lane * 4) =
                make_uint2(pk2(acc.x, acc.y), pk2(acc.z, acc.w));
        }
        load_tile_W128_16(Wet + (size_t)ke * cD * cD, cD, Ws, tid);
        __syncthreads();
        mma_loop32(Xs, Ws, wm, wn, gr, gc, c);
    }

#pragma unroll
    for (int i = 0; i < 2; i++)
#pragma unroll
        for (int j = 0; j < 4; j++) {
            int col = wn + j * 8 + 2 * gc;
#pragma unroll
            for (int half = 0; half < 2; half++) {
                int r = rowBase + wm + i * 16 + gr + half * 8;
                if (r >= cN) continue;
                float2 bs = *reinterpret_cast<const float2*>(g_bsum + (size_t)r * cD + col);
                float2 o = make_float2(c[i][j][half * 2] + bs.x, c[i][j][half * 2 + 1] + bs.y);
                *reinterpret_cast<float2*>(g_a + (size_t)r * cD + col) = o;
            }
        }
}

// ---------------- fused GRU (R6 verbatim) ----------------
constexpr int SM_GRU = (2 * 128 + 64) * LD2 * 2;  // 87040 -> 2 CTAs/SM

__global__ __launch_bounds__(256, 2) void k_gru_fused(
    const float* __restrict__ A, const float* __restrict__ H,
    const float* __restrict__ W_ih, const float* __restrict__ b_ih,
    const float* __restrict__ W_hh, const float* __restrict__ b_hh,
    float* __restrict__ hout) {
    extern __shared__ __half smh[];
    __half* Xa = smh;
    __half* Xh = smh + 128 * LD2;
    __half* Ws = smh + 256 * LD2;
    int tid = threadIdx.x;
    int rowBase = blockIdx.x * 128, colBase = blockIdx.y * 64;
    int lane = tid & 31, warp = tid >> 5;
    int wm = (warp & 3) * 32, wn = (warp >> 2) * 32;
    int gr = lane >> 2, gc = lane & 3;

    load_tile_X16(A, Xa, rowBase, cN, tid);
    load_tile_X16(H, Xh, rowBase, cN, tid);

    float rf[2][4][4], zf[2][4][4], ci[2][4][4], ch[2][4][4];

#pragma unroll
    for (int g = 0; g < 3; g++) {
#pragma unroll
        for (int i = 0; i < 2; i++)
#pragma unroll
            for (int j = 0; j < 4; j++)
#pragma unroll
                for (int q = 0; q < 4; q++) { ci[i][j][q] = 0.f; ch[i][j][q] = 0.f; }

        load_tile_W64_16(W_ih + (size_t)g * 128 * cD, cD, Ws, colBase, tid);
        __syncthreads();
        mma_loop32(Xa, Ws, wm, wn, gr, gc, ci);
        __syncthreads();
        load_tile_W64_16(W_hh + (size_t)g * 128 * cD, cD, Ws, colBase, tid);
        __syncthreads();
        mma_loop32(Xh, Ws, wm, wn, gr, gc, ch);
        __syncthreads();

#pragma unroll
        for (int i = 0; i < 2; i++)
#pragma unroll
            for (int j = 0; j < 4; j++) {
                int col = colBase + wn + j * 8 + 2 * gc;
                float bi0 = __ldg(&b_ih[g * 128 + col]), bi1 = __ldg(&b_ih[g * 128 + col + 1]);
                float bh0 = __ldg(&b_hh[g * 128 + col]), bh1 = __ldg(&b_hh[g * 128 + col + 1]);
                if (g == 0) {
#pragma unroll
                    for (int q = 0; q < 4; q++) {
                        float bi = (q & 1) ? bi1 : bi0, bh = (q & 1) ? bh1 : bh0;
                        rf[i][j][q] = sigmf(ci[i][j][q] + bi + ch[i][j][q] + bh);
                    }
                } else if (g == 1) {
#pragma unroll
                    for (int q = 0; q < 4; q++) {
                        float bi = (q & 1) ? bi1 : bi0, bh = (q & 1) ? bh1 : bh0;
                        zf[i][j][q] = sigmf(ci[i][j][q] + bi + ch[i][j][q] + bh);
                    }
                } else {
#pragma unroll
                    for (int half = 0; half < 2; half++) {
                        int r = rowBase + wm + i * 16 + gr + half * 8;
                        if (r >= cN) continue;
                        float2 hv = *reinterpret_cast<const float2*>(H + (size_t)r * cD + col);
                        int q0 = half * 2, q1 = half * 2 + 1;
                        float n0 = tanhf(ci[i][j][q0] + bi0 + rf[i][j][q0] * (ch[i][j][q0] + bh0));
                        float n1 = tanhf(ci[i][j][q1] + bi1 + rf[i][j][q1] * (ch[i][j][q1] + bh1));
                        float2 o;
                        o.x = (1.0f - zf[i][j][q0]) * n0 + zf[i][j][q0] * hv.x;
                        o.y = (1.0f - zf[i][j][q1]) * n1 + zf[i][j][q1] * hv.y;
                        *reinterpret_cast<float2*>(hout + (size_t)r * cD + col) = o;
                    }
                }
            }
    }
}

// ---------------- fused output head (R6 verbatim) ----------------
constexpr int SM_HEAD = 3 * 128 * LD2 * 2;  // 104448 -> 2 CTAs/SM

__global__ __launch_bounds__(256, 2) void k_head(
    const float* __restrict__ H, const float* __restrict__ F,
    const float* __restrict__ i_w, const float* __restrict__ i_b,
    const float* __restrict__ j_w, const float* __restrict__ j_b,
    float* __restrict__ out) {
    extern __shared__ __half smh[];
    __half* Xh = smh;
    __half* Xf = smh + 128 * LD2;
    __half* Ws = smh + 256 * LD2;
    int tid = threadIdx.x;
    int rowBase = blockIdx.x * 128;
    int lane = tid & 31, warp = tid >> 5;
    int wm = (warp & 3) * 32, wn = (warp >> 2) * 64;
    int gr = lane >> 2, gc = lane & 3;

    load_tile_X16(H, Xh, rowBase, cN, tid);
    load_tile_X16(F, Xf, rowBase, cN, tid);

    float cg[2][8][4], cj[2][8][4];
#pragma unroll
    for (int i = 0; i < 2; i++)
#pragma unroll
        for (int j = 0; j < 8; j++)
#pragma unroll
            for (int q = 0; q < 4; q++) { cg[i][j][q] = 0.f; cj[i][j][q] = 0.f; }

    load_tile_W128_16(i_w, 2 * cD, Ws, tid);
    __syncthreads();
    mma_loop64(Xh, Ws, wm, wn, gr, gc, cg);
    __syncthreads();
    load_tile_W128_16(i_w + cD, 2 * cD, Ws, tid);
    __syncthreads();
    mma_loop64(Xf, Ws, wm, wn, gr, gc, cg);
    __syncthreads();
    load_tile_W128_16(j_w, cD, Ws, tid);
    __syncthreads();
    mma_loop64(Xh, Ws, wm, wn, gr, gc, cj);

#pragma unroll
    for (int i = 0; i < 2; i++)
#pragma unroll
        for (int j = 0; j < 8; j++) {
            int col = wn + j * 8 + 2 * gc;
            float ib0 = __ldg(&i_b[col]), ib1 = __ldg(&i_b[col + 1]);
            float jb0 = __ldg(&j_b[col]), jb1 = __ldg(&j_b[col + 1]);
#pragma unroll
            for (int half = 0; half < 2; half++) {
                int r = rowBase + wm + i * 16 + gr + half * 8;
                if (r >= cN) continue;
                int q0 = half * 2, q1 = half * 2 + 1;
                float2 o;
                o.x = sigmf(cg[i][j][q0] + ib0) * (cj[i][j][q0] + jb0);
                o.y = sigmf(cg[i][j][q1] + ib1) * (cj[i][j][q1] + jb1);
                *reinterpret_cast<float2*>(out + (size_t)r * cD + col) = o;
            }
        }
}

// ---------------- host ----------------
extern "C" void kernel_launch(void* const* d_in, const int* in_sizes, int n_in,
                              void* d_out, int out_size) {
    (void)in_sizes; (void)n_in; (void)out_size;
    const float* features = (const float*)d_in[0];
    const int*   src      = (const int*)d_in[1];
    const int*   dst      = (const int*)d_in[2];
    const int*   etypes   = (const int*)d_in[3];
    const float* W_et     = (const float*)d_in[4];
    const float* b_et     = (const float*)d_in[5];
    const float* W_ih     = (const float*)d_in[6];
    const float* b_ih     = (const float*)d_in[7];
    const float* W_hh     = (const float*)d_in[8];
    const float* b_hh     = (const float*)d_in[9];
    const float* i_w      = (const float*)d_in[10];
    const float* i_b      = (const float*)d_in[11];
    const float* j_w      = (const float*)d_in[12];
    const float* j_b      = (const float*)d_in[13];
    float* out = (float*)d_out;

    float *h0, *h1, *abuf;
    cudaGetSymbolAddress((void**)&h0, g_h0);
    cudaGetSymbolAddress((void**)&h1, g_h1);
    cudaGetSymbolAddress((void**)&abuf, g_a);

    cudaFuncSetAttribute(k_agg_etype, cudaFuncAttributeMaxDynamicSharedMemorySize, SM_AE);
    cudaFuncSetAttribute(k_gru_fused, cudaFuncAttributeMaxDynamicSharedMemorySize, SM_GRU);
    cudaFuncSetAttribute(k_head, cudaFuncAttributeMaxDynamicSharedMemorySize, SM_HEAD);

    // ---- CSR build: 3 launches, then agg is launch index 3 (ncu window) ----
    k_hist<<<(cE + 255) / 256, 256>>>(dst, etypes);
    k_scanlb<<<NTILE, 1024>>>();
    {
        int tot = cN * cD > cE ? cN * cD : cE;
        k_scatter_bsum<<<(tot + 255) / 256, 256>>>(src, dst, etypes, b_et);
    }

    const int RB64 = (cN + 63) / 64;    // 1563
    const int RB128 = (cN + 127) / 128; // 782

    const float* hc = features;
    float* houts[3] = {h0, h1, h0};
    for (int s = 0; s < 3; s++) {
        k_agg_etype<<<RB64, 256, SM_AE>>>(hc, W_et);  // -> g_a
        k_gru_fused<<<dim3(RB128, 2), 256, SM_GRU>>>(abuf, hc, W_ih, b_ih, W_hh, b_hh, houts[s]);
        hc = houts[s];
    }
    k_head<<<RB128, 256, SM_HEAD>>>(hc, features, i_w, i_b, j_w, j_b, out);
}

// round 13
// speedup vs baseline: 1.7536x; 1.0227x over previous
#include <cuda_runtime.h>
#include <cuda_fp16.h>
#include <cstdint>

// ---------------- problem constants ----------------
constexpr int cN = 100000;   // nodes
constexpr int cE = 1600000;  // edges
constexpr int cD = 128;      // feature dim
constexpr int cK = 4;        // etypes
constexpr int cM = cK * cN;                 // 400000 keys (dst*4+etype)
constexpr int NTILE = (cM + 1023) / 1024;   // 391 scan tiles

// ---------------- scratch ----------------
__device__ __align__(16) float g_h0[(size_t)cN * cD];
__device__ __align__(16) float g_h1[(size_t)cN * cD];
__device__ __align__(16) float g_a[(size_t)cN * cD];
__device__ __align__(16) float g_bsum[(size_t)cN * cD];

__device__ int g_deg[cM];          // zero-initialized; re-zeroed by k_scanlb each launch
__device__ int g_rp[cM + 1];
__device__ int g_cur[cM];
__device__ int g_esrc[cE];
__device__ unsigned long long g_lbstate[NTILE + 1];
__device__ int g_ticket;

// ---------------- helpers ----------------
__device__ __forceinline__ float sigmf(float x) { return 1.0f / (1.0f + __expf(-x)); }

__device__ __forceinline__ uint32_t pk2(float x, float y) {
    __half2 h = __floats2half2_rn(x, y);
    return *reinterpret_cast<uint32_t*>(&h);
}

__device__ __forceinline__ void mma_f16(float c[4], const uint32_t a[4], const uint32_t b[2]) {
    asm volatile(
        "mma.sync.aligned.m16n8k16.row.col.f32.f16.f16.f32 "
        "{%0,%1,%2,%3}, {%4,%5,%6,%7}, {%8,%9}, {%0,%1,%2,%3};"
        : "+f"(c[0]), "+f"(c[1]), "+f"(c[2]), "+f"(c[3])
        : "r"(a[0]), "r"(a[1]), "r"(a[2]), "r"(a[3]), "r"(b[0]), "r"(b[1]));
}

// ---------------- CSR build: 3 kernels ----------------
__global__ void k_hist(const int* __restrict__ dst, const int* __restrict__ et) {
    int e = blockIdx.x * blockDim.x + threadIdx.x;
    if (e < cE) atomicAdd(&g_deg[dst[e] * 4 + et[e]], 1);
    if (blockIdx.x == 0) {
        if (threadIdx.x == 0) g_ticket = 0;
        for (int i = threadIdx.x; i <= NTILE; i += blockDim.x) g_lbstate[i] = 0ull;
    }
}

__global__ void k_scanlb() {
    __shared__ int sm[1024];
    __shared__ int bid_s, exc_s;
    if (threadIdx.x == 0) bid_s = atomicAdd(&g_ticket, 1);
    __syncthreads();
    int bid = bid_s;
    int i = bid * 1024 + threadIdx.x;
    int v = 0;
    if (i < cM) {
        v = g_deg[i];
        g_deg[i] = 0;  // reset for next launch
    }
    sm[threadIdx.x] = v;
    __syncthreads();
    for (int off = 1; off < 1024; off <<= 1) {
        int t = 0;
        if (threadIdx.x >= off) t = sm[threadIdx.x - off];
        __syncthreads();
        sm[threadIdx.x] += t;
        __syncthreads();
    }
    int total = sm[1023];
    if (threadIdx.x == 0) {
        if (bid == 0) {
            atomicExch(&g_lbstate[0], (2ull << 32) | (unsigned)total);
            exc_s = 0;
        } else {
            atomicExch(&g_lbstate[bid], (1ull << 32) | (unsigned)total);
            int exc = 0;
            for (int j = bid - 1;; j--) {
                unsigned long long s;
                do { s = atomicAdd(&g_lbstate[j], 0ull); } while ((s >> 32) == 0ull);
                exc += (int)(unsigned)(s & 0xffffffffull);
                if ((s >> 32) == 2ull) break;
            }
            atomicExch(&g_lbstate[bid], (2ull << 32) | (unsigned)(exc + total));
            exc_s = exc;
        }
    }
    __syncthreads();
    int exc = exc_s;
    if (i < cM) {
        int rp = exc + sm[threadIdx.x] - v;  // exclusive
        g_rp[i] = rp;
        g_cur[i] = rp;
    }
    if (bid == NTILE - 1 && threadIdx.x == 1023) g_rp[cM] = exc + total;
}

__global__ void k_scatter_bsum(const int* __restrict__ src, const int* __restrict__ dst,
                               const int* __restrict__ et, const float* __restrict__ bet) {
    int idx = blockIdx.x * blockDim.x + threadIdx.x;
    if (idx < cE) {
        int key = dst[idx] * 4 + et[idx];
        int pos = atomicAdd(&g_cur[key], 1);
        g_esrc[pos] = src[idx];
    }
    if (idx < cN * cD) {
        int r = idx >> 7, col = idx & 127;
        int rp[5];
#pragma unroll
        for (int k = 0; k <= 4; k++) rp[k] = g_rp[4 * r + k];
        float v = 0.f;
#pragma unroll
        for (int k = 0; k < 4; k++) v += (float)(rp[k + 1] - rp[k]) * __ldg(&bet[k * cD + col]);
        g_bsum[idx] = v;
    }
}

// ---------------- fp16 GEMM building blocks ----------------
constexpr int LD2 = 136;  // halves per smem row (272B stride, conflict-free)

__device__ __forceinline__ void load_tile_X16(const float* __restrict__ X, __half* Xs,
                                              int rowBase, int nrows, int tid) {
    for (int idx = tid; idx < 128 * 32; idx += 256) {
        int row = idx >> 5, c4 = (idx & 31) * 4;
        float4 v = make_float4(0.f, 0.f, 0.f, 0.f);
        int r = rowBase + row;
        if (r < nrows) v = *reinterpret_cast<const float4*>(X + (size_t)r * cD + c4);
        *reinterpret_cast<uint2*>(Xs + row * LD2 + c4) = make_uint2(pk2(v.x, v.y), pk2(v.z, v.w));
    }
}
__device__ __forceinline__ void load_tile_W64_16(const float* __restrict__ W, int ldw, __half* Ws,
                                                 int colBase, int tid) {
    for (int idx = tid; idx < 64 * 32; idx += 256) {
        int o = idx >> 5, c4 = (idx & 31) * 4;
        float4 v = *reinterpret_cast<const float4*>(W + (size_t)(colBase + o) * ldw + c4);
        *reinterpret_cast<uint2*>(Ws + o * LD2 + c4) = make_uint2(pk2(v.x, v.y), pk2(v.z, v.w));
    }
}
__device__ __forceinline__ void load_tile_W128_16(const float* __restrict__ W, int ldw, __half* Ws,
                                                  int tid) {
    for (int idx = tid; idx < 128 * 32; idx += 256) {
        int o = idx >> 5, c4 = (idx & 31) * 4;
        float4 v = *reinterpret_cast<const float4*>(W + (size_t)o * ldw + c4);
        *reinterpret_cast<uint2*>(Ws + o * LD2 + c4) = make_uint2(pk2(v.x, v.y), pk2(v.z, v.w));
    }
}
__device__ __forceinline__ uint32_t lds32(const __half* p) {
    return *reinterpret_cast<const uint32_t*>(p);
}

__device__ __forceinline__ void mma_loop32(const __half* Xs, const __half* Ws,
                                           int wm, int wn, int gr, int gc, float c[2][4][4]) {
#pragma unroll
    for (int k0 = 0; k0 < cD; k0 += 16) {
        uint32_t a[2][4], b[4][2];
#pragma unroll
        for (int i = 0; i < 2; i++) {
            const __half* base = Xs + (wm + i * 16 + gr) * LD2 + k0 + 2 * gc;
            a[i][0] = lds32(base);
            a[i][1] = lds32(base + 8 * LD2);
            a[i][2] = lds32(base + 8);
            a[i][3] = lds32(base + 8 * LD2 + 8);
        }
#pragma unroll
        for (int j = 0; j < 4; j++) {
            const __half* base = Ws + (wn + j * 8 + gr) * LD2 + k0 + 2 * gc;
            b[j][0] = lds32(base);
            b[j][1] = lds32(base + 8);
        }
#pragma unroll
        for (int i = 0; i < 2; i++)
#pragma unroll
            for (int j = 0; j < 4; j++) mma_f16(c[i][j], a[i], b[j]);
    }
}
__device__ __forceinline__ void mma_loop64(const __half* Xs, const __half* Ws,
                                           int wm, int wn, int gr, int gc, float c[2][8][4]) {
#pragma unroll
    for (int k0 = 0; k0 < cD; k0 += 16) {
        uint32_t a[2][4], b[8][2];
#pragma unroll
        for (int i = 0; i < 2; i++) {
            const __half* base = Xs + (wm + i * 16 + gr) * LD2 + k0 + 2 * gc;
            a[i][0] = lds32(base);
            a[i][1] = lds32(base + 8 * LD2);
            a[i][2] = lds32(base + 8);
            a[i][3] = lds32(base + 8 * LD2 + 8);
        }
#pragma unroll
        for (int j = 0; j < 8; j++) {
            const __half* base = Ws + (wn + j * 8 + gr) * LD2 + k0 + 2 * gc;
            b[j][0] = lds32(base);
            b[j][1] = lds32(base + 8);
        }
#pragma unroll
        for (int i = 0; i < 2; i++)
#pragma unroll
            for (int j = 0; j < 8; j++) mma_f16(c[i][j], a[i], b[j]);
    }
}

// ---------------- fused aggregation + etype GEMM ----------------
// smem: X tile + W tile + rp cache (260) + edge-index slice (1536)
constexpr int ESMEM = 1536;
constexpr int SM_AE = (64 + 128) * LD2 * 2 + 260 * 4 + ESMEM * 4;  // 59408 -> 3 CTAs/SM

// segment gather: SMI=true reads indices from smem slice, else from global
template <bool SMI>
__device__ __forceinline__ void seg_sum(const float4* __restrict__ hp,
                                        const int* __restrict__ eix, int estart,
                                        int r0, int r1, int lane, float4& acc) {
    int e = r0;
    for (; e + 4 <= r1; e += 4) {  // MLP-4 main loop
        int s0 = SMI ? eix[e - estart] : __ldg(&g_esrc[e]);
        int s1 = SMI ? eix[e + 1 - estart] : __ldg(&g_esrc[e + 1]);
        int s2 = SMI ? eix[e + 2 - estart] : __ldg(&g_esrc[e + 2]);
        int s3 = SMI ? eix[e + 3 - estart] : __ldg(&g_esrc[e + 3]);
        float4 x0 = hp[(size_t)s0 * 32 + lane];
        float4 x1 = hp[(size_t)s1 * 32 + lane];
        float4 x2 = hp[(size_t)s2 * 32 + lane];
        float4 x3 = hp[(size_t)s3 * 32 + lane];
        acc.x += (x0.x + x1.x) + (x2.x + x3.x);
        acc.y += (x0.y + x1.y) + (x2.y + x3.y);
        acc.z += (x0.z + x1.z) + (x2.z + x3.z);
        acc.w += (x0.w + x1.w) + (x2.w + x3.w);
    }
    int rem = r1 - e;  // 0..3: parallel tail, adds applied in order
    if (rem > 0) {
        int s0 = SMI ? eix[e - estart] : __ldg(&g_esrc[e]);
        int s1 = (rem > 1) ? (SMI ? eix[e + 1 - estart] : __ldg(&g_esrc[e + 1])) : s0;
        int s2 = (rem > 2) ? (SMI ? eix[e + 2 - estart] : __ldg(&g_esrc[e + 2])) : s0;
        float4 x0 = hp[(size_t)s0 * 32 + lane];
        float4 x1 = hp[(size_t)s1 * 32 + lane];
        float4 x2 = hp[(size_t)s2 * 32 + lane];
        acc.x += x0.x; acc.y += x0.y; acc.z += x0.z; acc.w += x0.w;
        if (rem > 1) { acc.x += x1.x; acc.y += x1.y; acc.z += x1.z; acc.w += x1.w; }
        if (rem > 2) { acc.x += x2.x; acc.y += x2.y; acc.z += x2.z; acc.w += x2.w; }
    }
}

__global__ __launch_bounds__(256, 3) void k_agg_etype(const float* __restrict__ h,
                                                      const float* __restrict__ Wet) {
    extern __shared__ __half smh[];
    __half* Xs = smh;             // 64 x LD2
    __half* Ws = smh + 64 * LD2;  // 128 x LD2
    int* rps = reinterpret_cast<int*>(smh + 192 * LD2);  // 257 used
    int* eix = rps + 260;                                 // ESMEM entries
    int tid = threadIdx.x, lane = tid & 31, warp = tid >> 5;
    int rowBase = blockIdx.x * 64;
    int wm = (warp & 1) * 32, wn = (warp >> 1) * 32;
    int gr = lane >> 2, gc = lane & 3;
    const float4* hp = reinterpret_cast<const float4*>(h);

    // stage this block's row-pointer window once
    {
        int base = 4 * rowBase;
        for (int i = tid; i < 257; i += 256) {
            int g = base + i;
            rps[i] = g_rp[g <= cM ? g : cM];
        }
    }
    __syncthreads();
    // stage the block's contiguous edge-index slice (coalesced)
    int estart = rps[0];
    int ecnt = rps[256] - estart;
    bool insm = (ecnt <= ESMEM);
    if (insm) {
        for (int i = tid; i < ecnt; i += 256) eix[i] = g_esrc[estart + i];
    }
    __syncthreads();

    float c[2][4][4];
#pragma unroll
    for (int i = 0; i < 2; i++)
#pragma unroll
        for (int j = 0; j < 4; j++)
#pragma unroll
            for (int q = 0; q < 4; q++) c[i][j][q] = 0.f;

    for (int ke = 0; ke < cK; ke++) {
        if (ke) __syncthreads();  // mma(ke-1) done reading Xs/Ws
#pragma unroll
        for (int i = 0; i < 8; i++) {
            int vl = warp * 8 + i;
            float4 acc = make_float4(0.f, 0.f, 0.f, 0.f);
            int r0 = rps[4 * vl + ke], r1 = rps[4 * vl + ke + 1];
            if (insm) seg_sum<true>(hp, eix, estart, r0, r1, lane, acc);
            else      seg_sum<false>(hp, eix, estart, r0, r1, lane, acc);
            *reinterpret_cast<uint2*>(Xs + vl * LD2 + lane * 4) =
                make_uint2(pk2(acc.x, acc.y), pk2(acc.z, acc.w));
        }
        load_tile_W128_16(Wet + (size_t)ke * cD * cD, cD, Ws, tid);
        __syncthreads();
        mma_loop32(Xs, Ws, wm, wn, gr, gc, c);
    }

#pragma unroll
    for (int i = 0; i < 2; i++)
#pragma unroll
        for (int j = 0; j < 4; j++) {
            int col = wn + j * 8 + 2 * gc;
#pragma unroll
            for (int half = 0; half < 2; half++) {
                int r = rowBase + wm + i * 16 + gr + half * 8;
                if (r >= cN) continue;
                float2 bs = *reinterpret_cast<const float2*>(g_bsum + (size_t)r * cD + col);
                float2 o = make_float2(c[i][j][half * 2] + bs.x, c[i][j][half * 2 + 1] + bs.y);
                *reinterpret_cast<float2*>(g_a + (size_t)r * cD + col) = o;
            }
        }
}

// ---------------- fused GRU (R6 verbatim) ----------------
constexpr int SM_GRU = (2 * 128 + 64) * LD2 * 2;  // 87040 -> 2 CTAs/SM

__global__ __launch_bounds__(256, 2) void k_gru_fused(
    const float* __restrict__ A, const float* __restrict__ H,
    const float* __restrict__ W_ih, const float* __restrict__ b_ih,
    const float* __restrict__ W_hh, const float* __restrict__ b_hh,
    float* __restrict__ hout) {
    extern __shared__ __half smh[];
    __half* Xa = smh;
    __half* Xh = smh + 128 * LD2;
    __half* Ws = smh + 256 * LD2;
    int tid = threadIdx.x;
    int rowBase = blockIdx.x * 128, colBase = blockIdx.y * 64;
    int lane = tid & 31, warp = tid >> 5;
    int wm = (warp & 3) * 32, wn = (warp >> 2) * 32;
    int gr = lane >> 2, gc = lane & 3;

    load_tile_X16(A, Xa, rowBase, cN, tid);
    load_tile_X16(H, Xh, rowBase, cN, tid);

    float rf[2][4][4], zf[2][4][4], ci[2][4][4], ch[2][4][4];

#pragma unroll
    for (int g = 0; g < 3; g++) {
#pragma unroll
        for (int i = 0; i < 2; i++)
#pragma unroll
            for (int j = 0; j < 4; j++)
#pragma unroll
                for (int q = 0; q < 4; q++) { ci[i][j][q] = 0.f; ch[i][j][q] = 0.f; }

        load_tile_W64_16(W_ih + (size_t)g * 128 * cD, cD, Ws, colBase, tid);
        __syncthreads();
        mma_loop32(Xa, Ws, wm, wn, gr, gc, ci);
        __syncthreads();
        load_tile_W64_16(W_hh + (size_t)g * 128 * cD, cD, Ws, colBase, tid);
        __syncthreads();
        mma_loop32(Xh, Ws, wm, wn, gr, gc, ch);
        __syncthreads();

#pragma unroll
        for (int i = 0; i < 2; i++)
#pragma unroll
            for (int j = 0; j < 4; j++) {
                int col = colBase + wn + j * 8 + 2 * gc;
                float bi0 = __ldg(&b_ih[g * 128 + col]), bi1 = __ldg(&b_ih[g * 128 + col + 1]);
                float bh0 = __ldg(&b_hh[g * 128 + col]), bh1 = __ldg(&b_hh[g * 128 + col + 1]);
                if (g == 0) {
#pragma unroll
                    for (int q = 0; q < 4; q++) {
                        float bi = (q & 1) ? bi1 : bi0, bh = (q & 1) ? bh1 : bh0;
                        rf[i][j][q] = sigmf(ci[i][j][q] + bi + ch[i][j][q] + bh);
                    }
                } else if (g == 1) {
#pragma unroll
                    for (int q = 0; q < 4; q++) {
                        float bi = (q & 1) ? bi1 : bi0, bh = (q & 1) ? bh1 : bh0;
                        zf[i][j][q] = sigmf(ci[i][j][q] + bi + ch[i][j][q] + bh);
                    }
                } else {
#pragma unroll
                    for (int half = 0; half < 2; half++) {
                        int r = rowBase + wm + i * 16 + gr + half * 8;
                        if (r >= cN) continue;
                        float2 hv = *reinterpret_cast<const float2*>(H + (size_t)r * cD + col);
                        int q0 = half * 2, q1 = half * 2 + 1;
                        float n0 = tanhf(ci[i][j][q0] + bi0 + rf[i][j][q0] * (ch[i][j][q0] + bh0));
                        float n1 = tanhf(ci[i][j][q1] + bi1 + rf[i][j][q1] * (ch[i][j][q1] + bh1));
                        float2 o;
                        o.x = (1.0f - zf[i][j][q0]) * n0 + zf[i][j][q0] * hv.x;
                        o.y = (1.0f - zf[i][j][q1]) * n1 + zf[i][j][q1] * hv.y;
                        *reinterpret_cast<float2*>(hout + (size_t)r * cD + col) = o;
                    }
                }
            }
    }
}

// ---------------- fused output head (R6 verbatim) ----------------
constexpr int SM_HEAD = 3 * 128 * LD2 * 2;  // 104448 -> 2 CTAs/SM

__global__ __launch_bounds__(256, 2) void k_head(
    const float* __restrict__ H, const float* __restrict__ F,
    const float* __restrict__ i_w, const float* __restrict__ i_b,
    const float* __restrict__ j_w, const float* __restrict__ j_b,
    float* __restrict__ out) {
    extern __shared__ __half smh[];
    __half* Xh = smh;
    __half* Xf = smh + 128 * LD2;
    __half* Ws = smh + 256 * LD2;
    int tid = threadIdx.x;
    int rowBase = blockIdx.x * 128;
    int lane = tid & 31, warp = tid >> 5;
    int wm = (warp & 3) * 32, wn = (warp >> 2) * 64;
    int gr = lane >> 2, gc = lane & 3;

    load_tile_X16(H, Xh, rowBase, cN, tid);
    load_tile_X16(F, Xf, rowBase, cN, tid);

    float cg[2][8][4], cj[2][8][4];
#pragma unroll
    for (int i = 0; i < 2; i++)
#pragma unroll
        for (int j = 0; j < 8; j++)
#pragma unroll
            for (int q = 0; q < 4; q++) { cg[i][j][q] = 0.f; cj[i][j][q] = 0.f; }

    load_tile_W128_16(i_w, 2 * cD, Ws, tid);
    __syncthreads();
    mma_loop64(Xh, Ws, wm, wn, gr, gc, cg);
    __syncthreads();
    load_tile_W128_16(i_w + cD, 2 * cD, Ws, tid);
    __syncthreads();
    mma_loop64(Xf, Ws, wm, wn, gr, gc, cg);
    __syncthreads();
    load_tile_W128_16(j_w, cD, Ws, tid);
    __syncthreads();
    mma_loop64(Xh, Ws, wm, wn, gr, gc, cj);

#pragma unroll
    for (int i = 0; i < 2; i++)
#pragma unroll
        for (int j = 0; j < 8; j++) {
            int col = wn + j * 8 + 2 * gc;
            float ib0 = __ldg(&i_b[col]), ib1 = __ldg(&i_b[col + 1]);
            float jb0 = __ldg(&j_b[col]), jb1 = __ldg(&j_b[col + 1]);
#pragma unroll
            for (int half = 0; half < 2; half++) {
                int r = rowBase + wm + i * 16 + gr + half * 8;
                if (r >= cN) continue;
                int q0 = half * 2, q1 = half * 2 + 1;
                float2 o;
                o.x = sigmf(cg[i][j][q0] + ib0) * (cj[i][j][q0] + jb0);
                o.y = sigmf(cg[i][j][q1] + ib1) * (cj[i][j][q1] + jb1);
                *reinterpret_cast<float2*>(out + (size_t)r * cD + col) = o;
            }
        }
}

// ---------------- host ----------------
extern "C" void kernel_launch(void* const* d_in, const int* in_sizes, int n_in,
                              void* d_out, int out_size) {
    (void)in_sizes; (void)n_in; (void)out_size;
    const float* features = (const float*)d_in[0];
    const int*   src      = (const int*)d_in[1];
    const int*   dst      = (const int*)d_in[2];
    const int*   etypes   = (const int*)d_in[3];
    const float* W_et     = (const float*)d_in[4];
    const float* b_et     = (const float*)d_in[5];
    const float* W_ih     = (const float*)d_in[6];
    const float* b_ih     = (const float*)d_in[7];
    const float* W_hh     = (const float*)d_in[8];
    const float* b_hh     = (const float*)d_in[9];
    const float* i_w      = (const float*)d_in[10];
    const float* i_b      = (const float*)d_in[11];
    const float* j_w      = (const float*)d_in[12];
    const float* j_b      = (const float*)d_in[13];
    float* out = (float*)d_out;

    float *h0, *h1, *abuf;
    cudaGetSymbolAddress((void**)&h0, g_h0);
    cudaGetSymbolAddress((void**)&h1, g_h1);
    cudaGetSymbolAddress((void**)&abuf, g_a);

    cudaFuncSetAttribute(k_agg_etype, cudaFuncAttributeMaxDynamicSharedMemorySize, SM_AE);
    cudaFuncSetAttribute(k_gru_fused, cudaFuncAttributeMaxDynamicSharedMemorySize, SM_GRU);
    cudaFuncSetAttribute(k_head, cudaFuncAttributeMaxDynamicSharedMemorySize, SM_HEAD);

    // ---- CSR build: 3 launches, then agg is launch index 3 (ncu window) ----
    k_hist<<<(cE + 255) / 256, 256>>>(dst, etypes);
    k_scanlb<<<NTILE, 1024>>>();
    {
        int tot = cN * cD > cE ? cN * cD : cE;
        k_scatter_bsum<<<(tot + 255) / 256, 256>>>(src, dst, etypes, b_et);
    }

    const int RB64 = (cN + 63) / 64;    // 1563
    const int RB128 = (cN + 127) / 128; // 782

    const float* hc = features;
    float* houts[3] = {h0, h1, h0};
    for (int s = 0; s < 3; s++) {
        k_agg_etype<<<RB64, 256, SM_AE>>>(hc, W_et);  // -> g_a
        k_gru_fused<<<dim3(RB128, 2), 256, SM_GRU>>>(abuf, hc, W_ih, b_ih, W_hh, b_hh, houts[s]);
        hc = houts[s];
    }
    k_head<<<RB128, 256, SM_HEAD>>>(hc, features, i_w, i_b, j_w, j_b, out);
}

// round 14
// speedup vs baseline: 1.8283x; 1.0426x over previous
#include <cuda_runtime.h>
#include <cuda_fp16.h>
#include <cstdint>

// ---------------- problem constants ----------------
constexpr int cN = 100000;   // nodes
constexpr int cE = 1600000;  // edges
constexpr int cD = 128;      // feature dim
constexpr int cK = 4;        // etypes
constexpr int cM = cK * cN;                 // 400000 keys (dst*4+etype)
constexpr int NTILE = (cM + 1023) / 1024;   // 391 scan tiles

// ---------------- scratch ----------------
__device__ __align__(16) float g_h0[(size_t)cN * cD];
__device__ __align__(16) float g_h1[(size_t)cN * cD];
__device__ __align__(16) __half g_a_h[(size_t)cN * cD];   // message result (fp16)
__device__ __align__(16) float g_bsum[(size_t)cN * cD];

__device__ int g_deg[cM];          // zero-initialized; re-zeroed by k_scanlb each launch
__device__ int g_rp[cM + 1];
__device__ int g_cur[cM];
__device__ int g_esrc[cE];
__device__ unsigned long long g_lbstate[NTILE + 1];
__device__ int g_ticket;

// ---------------- helpers ----------------
__device__ __forceinline__ float sigmf(float x) { return 1.0f / (1.0f + __expf(-x)); }

__device__ __forceinline__ uint32_t pk2(float x, float y) {
    __half2 h = __floats2half2_rn(x, y);
    return *reinterpret_cast<uint32_t*>(&h);
}

__device__ __forceinline__ void mma_f16(float c[4], const uint32_t a[4], const uint32_t b[2]) {
    asm volatile(
        "mma.sync.aligned.m16n8k16.row.col.f32.f16.f16.f32 "
        "{%0,%1,%2,%3}, {%4,%5,%6,%7}, {%8,%9}, {%0,%1,%2,%3};"
        : "+f"(c[0]), "+f"(c[1]), "+f"(c[2]), "+f"(c[3])
        : "r"(a[0]), "r"(a[1]), "r"(a[2]), "r"(a[3]), "r"(b[0]), "r"(b[1]));
}

// ---------------- CSR build: 3 kernels ----------------
__global__ void k_hist(const int* __restrict__ dst, const int* __restrict__ et) {
    int e = blockIdx.x * blockDim.x + threadIdx.x;
    if (e < cE) atomicAdd(&g_deg[dst[e] * 4 + et[e]], 1);
    if (blockIdx.x == 0) {
        if (threadIdx.x == 0) g_ticket = 0;
        for (int i = threadIdx.x; i <= NTILE; i += blockDim.x) g_lbstate[i] = 0ull;
    }
}

__global__ void k_scanlb() {
    __shared__ int sm[1024];
    __shared__ int bid_s, exc_s;
    if (threadIdx.x == 0) bid_s = atomicAdd(&g_ticket, 1);
    __syncthreads();
    int bid = bid_s;
    int i = bid * 1024 + threadIdx.x;
    int v = 0;
    if (i < cM) {
        v = g_deg[i];
        g_deg[i] = 0;  // reset for next launch
    }
    sm[threadIdx.x] = v;
    __syncthreads();
    for (int off = 1; off < 1024; off <<= 1) {
        int t = 0;
        if (threadIdx.x >= off) t = sm[threadIdx.x - off];
        __syncthreads();
        sm[threadIdx.x] += t;
        __syncthreads();
    }
    int total = sm[1023];
    if (threadIdx.x == 0) {
        if (bid == 0) {
            atomicExch(&g_lbstate[0], (2ull << 32) | (unsigned)total);
            exc_s = 0;
        } else {
            atomicExch(&g_lbstate[bid], (1ull << 32) | (unsigned)total);
            int exc = 0;
            for (int j = bid - 1;; j--) {
                unsigned long long s;
                do { s = atomicAdd(&g_lbstate[j], 0ull); } while ((s >> 32) == 0ull);
                exc += (int)(unsigned)(s & 0xffffffffull);
                if ((s >> 32) == 2ull) break;
            }
            atomicExch(&g_lbstate[bid], (2ull << 32) | (unsigned)(exc + total));
            exc_s = exc;
        }
    }
    __syncthreads();
    int exc = exc_s;
    if (i < cM) {
        int rp = exc + sm[threadIdx.x] - v;  // exclusive
        g_rp[i] = rp;
        g_cur[i] = rp;
    }
    if (bid == NTILE - 1 && threadIdx.x == 1023) g_rp[cM] = exc + total;
}

__global__ void k_scatter_bsum(const int* __restrict__ src, const int* __restrict__ dst,
                               const int* __restrict__ et, const float* __restrict__ bet) {
    int idx = blockIdx.x * blockDim.x + threadIdx.x;
    if (idx < cE) {
        int key = dst[idx] * 4 + et[idx];
        int pos = atomicAdd(&g_cur[key], 1);
        g_esrc[pos] = src[idx];
    }
    if (idx < cN * cD) {
        int r = idx >> 7, col = idx & 127;
        int rp[5];
#pragma unroll
        for (int k = 0; k <= 4; k++) rp[k] = g_rp[4 * r + k];
        float v = 0.f;
#pragma unroll
        for (int k = 0; k < 4; k++) v += (float)(rp[k + 1] - rp[k]) * __ldg(&bet[k * cD + col]);
        g_bsum[idx] = v;
    }
}

// ---------------- fp16 GEMM building blocks ----------------
constexpr int LD2 = 136;  // halves per smem row (272B stride, conflict-free)

__device__ __forceinline__ void load_tile_X16(const float* __restrict__ X, __half* Xs,
                                              int rowBase, int nrows, int tid) {
    for (int idx = tid; idx < 128 * 32; idx += 256) {
        int row = idx >> 5, c4 = (idx & 31) * 4;
        float4 v = make_float4(0.f, 0.f, 0.f, 0.f);
        int r = rowBase + row;
        if (r < nrows) v = *reinterpret_cast<const float4*>(X + (size_t)r * cD + c4);
        *reinterpret_cast<uint2*>(Xs + row * LD2 + c4) = make_uint2(pk2(v.x, v.y), pk2(v.z, v.w));
    }
}
// fp16-source X tile (no conversion, half the bytes)
__device__ __forceinline__ void load_tile_A16(const __half* __restrict__ X, __half* Xs,
                                              int rowBase, int nrows, int tid) {
    for (int idx = tid; idx < 128 * 32; idx += 256) {
        int row = idx >> 5, c4 = (idx & 31) * 4;
        uint2 v = make_uint2(0u, 0u);
        int r = rowBase + row;
        if (r < nrows) v = *reinterpret_cast<const uint2*>(X + (size_t)r * cD + c4);
        *reinterpret_cast<uint2*>(Xs + row * LD2 + c4) = v;
    }
}
__device__ __forceinline__ void load_tile_W64_16(const float* __restrict__ W, int ldw, __half* Ws,
                                                 int colBase, int tid) {
    for (int idx = tid; idx < 64 * 32; idx += 256) {
        int o = idx >> 5, c4 = (idx & 31) * 4;
        float4 v = *reinterpret_cast<const float4*>(W + (size_t)(colBase + o) * ldw + c4);
        *reinterpret_cast<uint2*>(Ws + o * LD2 + c4) = make_uint2(pk2(v.x, v.y), pk2(v.z, v.w));
    }
}
__device__ __forceinline__ void load_tile_W128_16(const float* __restrict__ W, int ldw, __half* Ws,
                                                  int tid) {
    for (int idx = tid; idx < 128 * 32; idx += 256) {
        int o = idx >> 5, c4 = (idx & 31) * 4;
        float4 v = *reinterpret_cast<const float4*>(W + (size_t)o * ldw + c4);
        *reinterpret_cast<uint2*>(Ws + o * LD2 + c4) = make_uint2(pk2(v.x, v.y), pk2(v.z, v.w));
    }
}
__device__ __forceinline__ uint32_t lds32(const __half* p) {
    return *reinterpret_cast<const uint32_t*>(p);
}

__device__ __forceinline__ void mma_loop32(const __half* Xs, const __half* Ws,
                                           int wm, int wn, int gr, int gc, float c[2][4][4]) {
#pragma unroll
    for (int k0 = 0; k0 < cD; k0 += 16) {
        uint32_t a[2][4], b[4][2];
#pragma unroll
        for (int i = 0; i < 2; i++) {
            const __half* base = Xs + (wm + i * 16 + gr) * LD2 + k0 + 2 * gc;
            a[i][0] = lds32(base);
            a[i][1] = lds32(base + 8 * LD2);
            a[i][2] = lds32(base + 8);
            a[i][3] = lds32(base + 8 * LD2 + 8);
        }
#pragma unroll
        for (int j = 0; j < 4; j++) {
            const __half* base = Ws + (wn + j * 8 + gr) * LD2 + k0 + 2 * gc;
            b[j][0] = lds32(base);
            b[j][1] = lds32(base + 8);
        }
#pragma unroll
        for (int i = 0; i < 2; i++)
#pragma unroll
            for (int j = 0; j < 4; j++) mma_f16(c[i][j], a[i], b[j]);
    }
}
__device__ __forceinline__ void mma_loop64(const __half* Xs, const __half* Ws,
                                           int wm, int wn, int gr, int gc, float c[2][8][4]) {
#pragma unroll
    for (int k0 = 0; k0 < cD; k0 += 16) {
        uint32_t a[2][4], b[8][2];
#pragma unroll
        for (int i = 0; i < 2; i++) {
            const __half* base = Xs + (wm + i * 16 + gr) * LD2 + k0 + 2 * gc;
            a[i][0] = lds32(base);
            a[i][1] = lds32(base + 8 * LD2);
            a[i][2] = lds32(base + 8);
            a[i][3] = lds32(base + 8 * LD2 + 8);
        }
#pragma unroll
        for (int j = 0; j < 8; j++) {
            const __half* base = Ws + (wn + j * 8 + gr) * LD2 + k0 + 2 * gc;
            b[j][0] = lds32(base);
            b[j][1] = lds32(base + 8);
        }
#pragma unroll
        for (int i = 0; i < 2; i++)
#pragma unroll
            for (int j = 0; j < 8; j++) mma_f16(c[i][j], a[i], b[j]);
    }
}

// ---------------- fused aggregation + etype GEMM ----------------
// smem: X tile + W tile + rp cache (260) + edge-index slice (1536)
constexpr int ESMEM = 1536;
constexpr int SM_AE = (64 + 128) * LD2 * 2 + 260 * 4 + ESMEM * 4;  // 59408 -> 3 CTAs/SM

template <bool SMI>
__device__ __forceinline__ void seg_sum(const float4* __restrict__ hp,
                                        const int* __restrict__ eix, int estart,
                                        int r0, int r1, int lane, float4& acc) {
    int e = r0;
    for (; e + 4 <= r1; e += 4) {  // MLP-4 main loop
        int s0 = SMI ? eix[e - estart] : __ldg(&g_esrc[e]);
        int s1 = SMI ? eix[e + 1 - estart] : __ldg(&g_esrc[e + 1]);
        int s2 = SMI ? eix[e + 2 - estart] : __ldg(&g_esrc[e + 2]);
        int s3 = SMI ? eix[e + 3 - estart] : __ldg(&g_esrc[e + 3]);
        float4 x0 = hp[(size_t)s0 * 32 + lane];
        float4 x1 = hp[(size_t)s1 * 32 + lane];
        float4 x2 = hp[(size_t)s2 * 32 + lane];
        float4 x3 = hp[(size_t)s3 * 32 + lane];
        acc.x += (x0.x + x1.x) + (x2.x + x3.x);
        acc.y += (x0.y + x1.y) + (x2.y + x3.y);
        acc.z += (x0.z + x1.z) + (x2.z + x3.z);
        acc.w += (x0.w + x1.w) + (x2.w + x3.w);
    }
    int rem = r1 - e;  // 0..3: parallel tail, adds applied in order
    if (rem > 0) {
        int s0 = SMI ? eix[e - estart] : __ldg(&g_esrc[e]);
        int s1 = (rem > 1) ? (SMI ? eix[e + 1 - estart] : __ldg(&g_esrc[e + 1])) : s0;
        int s2 = (rem > 2) ? (SMI ? eix[e + 2 - estart] : __ldg(&g_esrc[e + 2])) : s0;
        float4 x0 = hp[(size_t)s0 * 32 + lane];
        float4 x1 = hp[(size_t)s1 * 32 + lane];
        float4 x2 = hp[(size_t)s2 * 32 + lane];
        acc.x += x0.x; acc.y += x0.y; acc.z += x0.z; acc.w += x0.w;
        if (rem > 1) { acc.x += x1.x; acc.y += x1.y; acc.z += x1.z; acc.w += x1.w; }
        if (rem > 2) { acc.x += x2.x; acc.y += x2.y; acc.z += x2.z; acc.w += x2.w; }
    }
}

__global__ __launch_bounds__(256, 3) void k_agg_etype(const float* __restrict__ h,
                                                      const float* __restrict__ Wet) {
    extern __shared__ __half smh[];
    __half* Xs = smh;             // 64 x LD2
    __half* Ws = smh + 64 * LD2;  // 128 x LD2
    int* rps = reinterpret_cast<int*>(smh + 192 * LD2);  // 257 used
    int* eix = rps + 260;                                 // ESMEM entries
    int tid = threadIdx.x, lane = tid & 31, warp = tid >> 5;
    int rowBase = blockIdx.x * 64;
    int wm = (warp & 1) * 32, wn = (warp >> 1) * 32;
    int gr = lane >> 2, gc = lane & 3;
    const float4* hp = reinterpret_cast<const float4*>(h);

    {
        int base = 4 * rowBase;
        for (int i = tid; i < 257; i += 256) {
            int g = base + i;
            rps[i] = g_rp[g <= cM ? g : cM];
        }
    }
    __syncthreads();
    int estart = rps[0];
    int ecnt = rps[256] - estart;
    bool insm = (ecnt <= ESMEM);
    if (insm) {
        for (int i = tid; i < ecnt; i += 256) eix[i] = g_esrc[estart + i];
    }
    __syncthreads();

    float c[2][4][4];
#pragma unroll
    for (int i = 0; i < 2; i++)
#pragma unroll
        for (int j = 0; j < 4; j++)
#pragma unroll
            for (int q = 0; q < 4; q++) c[i][j][q] = 0.f;

    for (int ke = 0; ke < cK; ke++) {
        if (ke) __syncthreads();
#pragma unroll
        for (int i = 0; i < 8; i++) {
            int vl = warp * 8 + i;
            float4 acc = make_float4(0.f, 0.f, 0.f, 0.f);
            int r0 = rps[4 * vl + ke], r1 = rps[4 * vl + ke + 1];
            if (insm) seg_sum<true>(hp, eix, estart, r0, r1, lane, acc);
            else      seg_sum<false>(hp, eix, estart, r0, r1, lane, acc);
            *reinterpret_cast<uint2*>(Xs + vl * LD2 + lane * 4) =
                make_uint2(pk2(acc.x, acc.y), pk2(acc.z, acc.w));
        }
        load_tile_W128_16(Wet + (size_t)ke * cD * cD, cD, Ws, tid);
        __syncthreads();
        mma_loop32(Xs, Ws, wm, wn, gr, gc, c);
    }

    // epilogue -> fp16 a (rounded at the same dataflow point the GRU would round)
#pragma unroll
    for (int i = 0; i < 2; i++)
#pragma unroll
        for (int j = 0; j < 4; j++) {
            int col = wn + j * 8 + 2 * gc;
#pragma unroll
            for (int half = 0; half < 2; half++) {
                int r = rowBase + wm + i * 16 + gr + half * 8;
                if (r >= cN) continue;
                float2 bs = *reinterpret_cast<const float2*>(g_bsum + (size_t)r * cD + col);
                uint32_t o = pk2(c[i][j][half * 2] + bs.x, c[i][j][half * 2 + 1] + bs.y);
                *reinterpret_cast<uint32_t*>(g_a_h + (size_t)r * cD + col) = o;
            }
        }
}

// ---------------- fused GRU (fp16 A input; otherwise R6 verbatim) ----------------
constexpr int SM_GRU = (2 * 128 + 64) * LD2 * 2;  // 87040 -> 2 CTAs/SM

__global__ __launch_bounds__(256, 2) void k_gru_fused(
    const __half* __restrict__ A, const float* __restrict__ H,
    const float* __restrict__ W_ih, const float* __restrict__ b_ih,
    const float* __restrict__ W_hh, const float* __restrict__ b_hh,
    float* __restrict__ hout) {
    extern __shared__ __half smh[];
    __half* Xa = smh;
    __half* Xh = smh + 128 * LD2;
    __half* Ws = smh + 256 * LD2;
    int tid = threadIdx.x;
    int rowBase = blockIdx.x * 128, colBase = blockIdx.y * 64;
    int lane = tid & 31, warp = tid >> 5;
    int wm = (warp & 3) * 32, wn = (warp >> 2) * 32;
    int gr = lane >> 2, gc = lane & 3;

    load_tile_A16(A, Xa, rowBase, cN, tid);
    load_tile_X16(H, Xh, rowBase, cN, tid);

    float rf[2][4][4], zf[2][4][4], ci[2][4][4], ch[2][4][4];

#pragma unroll
    for (int g = 0; g < 3; g++) {
#pragma unroll
        for (int i = 0; i < 2; i++)
#pragma unroll
            for (int j = 0; j < 4; j++)
#pragma unroll
                for (int q = 0; q < 4; q++) { ci[i][j][q] = 0.f; ch[i][j][q] = 0.f; }

        load_tile_W64_16(W_ih + (size_t)g * 128 * cD, cD, Ws, colBase, tid);
        __syncthreads();
        mma_loop32(Xa, Ws, wm, wn, gr, gc, ci);
        __syncthreads();
        load_tile_W64_16(W_hh + (size_t)g * 128 * cD, cD, Ws, colBase, tid);
        __syncthreads();
        mma_loop32(Xh, Ws, wm, wn, gr, gc, ch);
        __syncthreads();

#pragma unroll
        for (int i = 0; i < 2; i++)
#pragma unroll
            for (int j = 0; j < 4; j++) {
                int col = colBase + wn + j * 8 + 2 * gc;
                float bi0 = __ldg(&b_ih[g * 128 + col]), bi1 = __ldg(&b_ih[g * 128 + col + 1]);
                float bh0 = __ldg(&b_hh[g * 128 + col]), bh1 = __ldg(&b_hh[g * 128 + col + 1]);
                if (g == 0) {
#pragma unroll
                    for (int q = 0; q < 4; q++) {
                        float bi = (q & 1) ? bi1 : bi0, bh = (q & 1) ? bh1 : bh0;
                        rf[i][j][q] = sigmf(ci[i][j][q] + bi + ch[i][j][q] + bh);
                    }
                } else if (g == 1) {
#pragma unroll
                    for (int q = 0; q < 4; q++) {
                        float bi = (q & 1) ? bi1 : bi0, bh = (q & 1) ? bh1 : bh0;
                        zf[i][j][q] = sigmf(ci[i][j][q] + bi + ch[i][j][q] + bh);
                    }
                } else {
#pragma unroll
                    for (int half = 0; half < 2; half++) {
                        int r = rowBase + wm + i * 16 + gr + half * 8;
                        if (r >= cN) continue;
                        float2 hv = *reinterpret_cast<const float2*>(H + (size_t)r * cD + col);
                        int q0 = half * 2, q1 = half * 2 + 1;
                        float n0 = tanhf(ci[i][j][q0] + bi0 + rf[i][j][q0] * (ch[i][j][q0] + bh0));
                        float n1 = tanhf(ci[i][j][q1] + bi1 + rf[i][j][q1] * (ch[i][j][q1] + bh1));
                        float2 o;
                        o.x = (1.0f - zf[i][j][q0]) * n0 + zf[i][j][q0] * hv.x;
                        o.y = (1.0f - zf[i][j][q1]) * n1 + zf[i][j][q1] * hv.y;
                        *reinterpret_cast<float2*>(hout + (size_t)r * cD + col) = o;
                    }
                }
            }
    }
}

// ---------------- fused output head (R6 verbatim) ----------------
constexpr int SM_HEAD = 3 * 128 * LD2 * 2;  // 104448 -> 2 CTAs/SM

__global__ __launch_bounds__(256, 2) void k_head(
    const float* __restrict__ H, const float* __restrict__ F,
    const float* __restrict__ i_w, const float* __restrict__ i_b,
    const float* __restrict__ j_w, const float* __restrict__ j_b,
    float* __restrict__ out) {
    extern __shared__ __half smh[];
    __half* Xh = smh;
    __half* Xf = smh + 128 * LD2;
    __half* Ws = smh + 256 * LD2;
    int tid = threadIdx.x;
    int rowBase = blockIdx.x * 128;
    int lane = tid & 31, warp = tid >> 5;
    int wm = (warp & 3) * 32, wn = (warp >> 2) * 64;
    int gr = lane >> 2, gc = lane & 3;

    load_tile_X16(H, Xh, rowBase, cN, tid);
    load_tile_X16(F, Xf, rowBase, cN, tid);

    float cg[2][8][4], cj[2][8][4];
#pragma unroll
    for (int i = 0; i < 2; i++)
#pragma unroll
        for (int j = 0; j < 8; j++)
#pragma unroll
            for (int q = 0; q < 4; q++) { cg[i][j][q] = 0.f; cj[i][j][q] = 0.f; }

    load_tile_W128_16(i_w, 2 * cD, Ws, tid);
    __syncthreads();
    mma_loop64(Xh, Ws, wm, wn, gr, gc, cg);
    __syncthreads();
    load_tile_W128_16(i_w + cD, 2 * cD, Ws, tid);
    __syncthreads();
    mma_loop64(Xf, Ws, wm, wn, gr, gc, cg);
    __syncthreads();
    load_tile_W128_16(j_w, cD, Ws, tid);
    __syncthreads();
    mma_loop64(Xh, Ws, wm, wn, gr, gc, cj);

#pragma unroll
    for (int i = 0; i < 2; i++)
#pragma unroll
        for (int j = 0; j < 8; j++) {
            int col = wn + j * 8 + 2 * gc;
            float ib0 = __ldg(&i_b[col]), ib1 = __ldg(&i_b[col + 1]);
            float jb0 = __ldg(&j_b[col]), jb1 = __ldg(&j_b[col + 1]);
#pragma unroll
            for (int half = 0; half < 2; half++) {
                int r = rowBase + wm + i * 16 + gr + half * 8;
                if (r >= cN) continue;
                int q0 = half * 2, q1 = half * 2 + 1;
                float2 o;
                o.x = sigmf(cg[i][j][q0] + ib0) * (cj[i][j][q0] + jb0);
                o.y = sigmf(cg[i][j][q1] + ib1) * (cj[i][j][q1] + jb1);
                *reinterpret_cast<float2*>(out + (size_t)r * cD + col) = o;
            }
        }
}

// ---------------- host ----------------
extern "C" void kernel_launch(void* const* d_in, const int* in_sizes, int n_in,
                              void* d_out, int out_size) {
    (void)in_sizes; (void)n_in; (void)out_size;
    const float* features = (const float*)d_in[0];
    const int*   src      = (const int*)d_in[1];
    const int*   dst      = (const int*)d_in[2];
    const int*   etypes   = (const int*)d_in[3];
    const float* W_et     = (const float*)d_in[4];
    const float* b_et     = (const float*)d_in[5];
    const float* W_ih     = (const float*)d_in[6];
    const float* b_ih     = (const float*)d_in[7];
    const float* W_hh     = (const float*)d_in[8];
    const float* b_hh     = (const float*)d_in[9];
    const float* i_w      = (const float*)d_in[10];
    const float* i_b      = (const float*)d_in[11];
    const float* j_w      = (const float*)d_in[12];
    const float* j_b      = (const float*)d_in[13];
    float* out = (float*)d_out;

    float *h0, *h1;
    __half *abuf;
    cudaGetSymbolAddress((void**)&h0, g_h0);
    cudaGetSymbolAddress((void**)&h1, g_h1);
    cudaGetSymbolAddress((void**)&abuf, g_a_h);

    cudaFuncSetAttribute(k_agg_etype, cudaFuncAttributeMaxDynamicSharedMemorySize, SM_AE);
    cudaFuncSetAttribute(k_gru_fused, cudaFuncAttributeMaxDynamicSharedMemorySize, SM_GRU);
    cudaFuncSetAttribute(k_head, cudaFuncAttributeMaxDynamicSharedMemorySize, SM_HEAD);

    // ---- CSR build: 3 launches, then agg is launch index 3 (ncu window) ----
    k_hist<<<(cE + 255) / 256, 256>>>(dst, etypes);
    k_scanlb<<<NTILE, 1024>>>();
    {
        int tot = cN * cD > cE ? cN * cD : cE;
        k_scatter_bsum<<<(tot + 255) / 256, 256>>>(src, dst, etypes, b_et);
    }

    const int RB64 = (cN + 63) / 64;    // 1563
    const int RB128 = (cN + 127) / 128; // 782

    const float* hc = features;
    float* houts[3] = {h0, h1, h0};
    for (int s = 0; s < 3; s++) {
        k_agg_etype<<<RB64, 256, SM_AE>>>(hc, W_et);  // -> g_a_h (fp16)
        k_gru_fused<<<dim3(RB128, 2), 256, SM_GRU>>>(abuf, hc, W_ih, b_ih, W_hh, b_hh, houts[s]);
        hc = houts[s];
    }
    k_head<<<RB128, 256, SM_HEAD>>>(hc, features, i_w, i_b, j_w, j_b, out);
}

// round 15
// speedup vs baseline: 1.8771x; 1.0267x over previous
#include <cuda_runtime.h>
#include <cuda_fp16.h>
#include <cstdint>

// ---------------- problem constants ----------------
constexpr int cN = 100000;   // nodes
constexpr int cE = 1600000;  // edges
constexpr int cD = 128;      // feature dim
constexpr int cK = 4;        // etypes
constexpr int cM = cK * cN;                 // 400000 keys (dst*4+etype)
constexpr int NTILE = (cM + 1023) / 1024;   // 391 scan tiles

// ---------------- scratch ----------------
__device__ __align__(16) float g_h0[(size_t)cN * cD];
__device__ __align__(16) float g_h1[(size_t)cN * cD];
__device__ __align__(16) __half g_h0h[(size_t)cN * cD];   // fp16 image of g_h0
__device__ __align__(16) __half g_h1h[(size_t)cN * cD];   // fp16 image of g_h1
__device__ __align__(16) __half g_feath[(size_t)cN * cD]; // fp16 image of features
__device__ __align__(16) __half g_a_h[(size_t)cN * cD];   // message result (fp16)
__device__ __align__(16) float g_bsum[(size_t)cN * cD];

__device__ int g_deg[cM];          // zero-initialized; re-zeroed by k_scanlb each launch
__device__ int g_rp[cM + 1];
__device__ int g_cur[cM];
__device__ int g_esrc[cE];
__device__ unsigned long long g_lbstate[NTILE + 1];
__device__ int g_ticket;

// ---------------- helpers ----------------
__device__ __forceinline__ float sigmf(float x) { return 1.0f / (1.0f + __expf(-x)); }

__device__ __forceinline__ uint32_t pk2(float x, float y) {
    __half2 h = __floats2half2_rn(x, y);
    return *reinterpret_cast<uint32_t*>(&h);
}
__device__ __forceinline__ float4 up4(uint2 v) {
    float2 fa = __half22float2(*reinterpret_cast<const __half2*>(&v.x));
    float2 fb = __half22float2(*reinterpret_cast<const __half2*>(&v.y));
    return make_float4(fa.x, fa.y, fb.x, fb.y);
}

__device__ __forceinline__ void mma_f16(float c[4], const uint32_t a[4], const uint32_t b[2]) {
    asm volatile(
        "mma.sync.aligned.m16n8k16.row.col.f32.f16.f16.f32 "
        "{%0,%1,%2,%3}, {%4,%5,%6,%7}, {%8,%9}, {%0,%1,%2,%3};"
        : "+f"(c[0]), "+f"(c[1]), "+f"(c[2]), "+f"(c[3])
        : "r"(a[0]), "r"(a[1]), "r"(a[2]), "r"(a[3]), "r"(b[0]), "r"(b[1]));
}

// ---------------- CSR build: 3 kernels ----------------
__global__ void k_hist(const int* __restrict__ dst, const int* __restrict__ et) {
    int e = blockIdx.x * blockDim.x + threadIdx.x;
    if (e < cE) atomicAdd(&g_deg[dst[e] * 4 + et[e]], 1);
    if (blockIdx.x == 0) {
        if (threadIdx.x == 0) g_ticket = 0;
        for (int i = threadIdx.x; i <= NTILE; i += blockDim.x) g_lbstate[i] = 0ull;
    }
}

__global__ void k_scanlb() {
    __shared__ int sm[1024];
    __shared__ int bid_s, exc_s;
    if (threadIdx.x == 0) bid_s = atomicAdd(&g_ticket, 1);
    __syncthreads();
    int bid = bid_s;
    int i = bid * 1024 + threadIdx.x;
    int v = 0;
    if (i < cM) {
        v = g_deg[i];
        g_deg[i] = 0;  // reset for next launch
    }
    sm[threadIdx.x] = v;
    __syncthreads();
    for (int off = 1; off < 1024; off <<= 1) {
        int t = 0;
        if (threadIdx.x >= off) t = sm[threadIdx.x - off];
        __syncthreads();
        sm[threadIdx.x] += t;
        __syncthreads();
    }
    int total = sm[1023];
    if (threadIdx.x == 0) {
        if (bid == 0) {
            atomicExch(&g_lbstate[0], (2ull << 32) | (unsigned)total);
            exc_s = 0;
        } else {
            atomicExch(&g_lbstate[bid], (1ull << 32) | (unsigned)total);
            int exc = 0;
            for (int j = bid - 1;; j--) {
                unsigned long long s;
                do { s = atomicAdd(&g_lbstate[j], 0ull); } while ((s >> 32) == 0ull);
                exc += (int)(unsigned)(s & 0xffffffffull);
                if ((s >> 32) == 2ull) break;
            }
            atomicExch(&g_lbstate[bid], (2ull << 32) | (unsigned)(exc + total));
            exc_s = exc;
        }
    }
    __syncthreads();
    int exc = exc_s;
    if (i < cM) {
        int rp = exc + sm[threadIdx.x] - v;  // exclusive
        g_rp[i] = rp;
        g_cur[i] = rp;
    }
    if (bid == NTILE - 1 && threadIdx.x == 1023) g_rp[cM] = exc + total;
}

__global__ void k_scatter_bsum(const int* __restrict__ src, const int* __restrict__ dst,
                               const int* __restrict__ et, const float* __restrict__ bet,
                               const float* __restrict__ feat) {
    int idx = blockIdx.x * blockDim.x + threadIdx.x;
    if (idx < cE) {
        int key = dst[idx] * 4 + et[idx];
        int pos = atomicAdd(&g_cur[key], 1);
        g_esrc[pos] = src[idx];
    }
    if (idx < cN * cD) {
        int r = idx >> 7, col = idx & 127;
        int rp[5];
#pragma unroll
        for (int k = 0; k <= 4; k++) rp[k] = g_rp[4 * r + k];
        float v = 0.f;
#pragma unroll
        for (int k = 0; k < 4; k++) v += (float)(rp[k + 1] - rp[k]) * __ldg(&bet[k * cD + col]);
        g_bsum[idx] = v;
        g_feath[idx] = __float2half_rn(feat[idx]);  // fp16 image of features
    }
}

// ---------------- fp16 GEMM building blocks ----------------
constexpr int LD2 = 136;  // halves per smem row (272B stride, conflict-free)

__device__ __forceinline__ void load_tile_X16(const float* __restrict__ X, __half* Xs,
                                              int rowBase, int nrows, int tid) {
    for (int idx = tid; idx < 128 * 32; idx += 256) {
        int row = idx >> 5, c4 = (idx & 31) * 4;
        float4 v = make_float4(0.f, 0.f, 0.f, 0.f);
        int r = rowBase + row;
        if (r < nrows) v = *reinterpret_cast<const float4*>(X + (size_t)r * cD + c4);
        *reinterpret_cast<uint2*>(Xs + row * LD2 + c4) = make_uint2(pk2(v.x, v.y), pk2(v.z, v.w));
    }
}
// fp16-source X tile (no conversion, half the bytes)
__device__ __forceinline__ void load_tile_A16(const __half* __restrict__ X, __half* Xs,
                                              int rowBase, int nrows, int tid) {
    for (int idx = tid; idx < 128 * 32; idx += 256) {
        int row = idx >> 5, c4 = (idx & 31) * 4;
        uint2 v = make_uint2(0u, 0u);
        int r = rowBase + row;
        if (r < nrows) v = *reinterpret_cast<const uint2*>(X + (size_t)r * cD + c4);
        *reinterpret_cast<uint2*>(Xs + row * LD2 + c4) = v;
    }
}
__device__ __forceinline__ void load_tile_W64_16(const float* __restrict__ W, int ldw, __half* Ws,
                                                 int colBase, int tid) {
    for (int idx = tid; idx < 64 * 32; idx += 256) {
        int o = idx >> 5, c4 = (idx & 31) * 4;
        float4 v = *reinterpret_cast<const float4*>(W + (size_t)(colBase + o) * ldw + c4);
        *reinterpret_cast<uint2*>(Ws + o * LD2 + c4) = make_uint2(pk2(v.x, v.y), pk2(v.z, v.w));
    }
}
__device__ __forceinline__ void load_tile_W128_16(const float* __restrict__ W, int ldw, __half* Ws,
                                                  int tid) {
    for (int idx = tid; idx < 128 * 32; idx += 256) {
        int o = idx >> 5, c4 = (idx & 31) * 4;
        float4 v = *reinterpret_cast<const float4*>(W + (size_t)o * ldw + c4);
        *reinterpret_cast<uint2*>(Ws + o * LD2 + c4) = make_uint2(pk2(v.x, v.y), pk2(v.z, v.w));
    }
}
__device__ __forceinline__ uint32_t lds32(const __half* p) {
    return *reinterpret_cast<const uint32_t*>(p);
}

__device__ __forceinline__ void mma_loop32(const __half* Xs, const __half* Ws,
                                           int wm, int wn, int gr, int gc, float c[2][4][4]) {
#pragma unroll
    for (int k0 = 0; k0 < cD; k0 += 16) {
        uint32_t a[2][4], b[4][2];
#pragma unroll
        for (int i = 0; i < 2; i++) {
            const __half* base = Xs + (wm + i * 16 + gr) * LD2 + k0 + 2 * gc;
            a[i][0] = lds32(base);
            a[i][1] = lds32(base + 8 * LD2);
            a[i][2] = lds32(base + 8);
            a[i][3] = lds32(base + 8 * LD2 + 8);
        }
#pragma unroll
        for (int j = 0; j < 4; j++) {
            const __half* base = Ws + (wn + j * 8 + gr) * LD2 + k0 + 2 * gc;
            b[j][0] = lds32(base);
            b[j][1] = lds32(base + 8);
        }
#pragma unroll
        for (int i = 0; i < 2; i++)
#pragma unroll
            for (int j = 0; j < 4; j++) mma_f16(c[i][j], a[i], b[j]);
    }
}
__device__ __forceinline__ void mma_loop64(const __half* Xs, const __half* Ws,
                                           int wm, int wn, int gr, int gc, float c[2][8][4]) {
#pragma unroll
    for (int k0 = 0; k0 < cD; k0 += 16) {
        uint32_t a[2][4], b[8][2];
#pragma unroll
        for (int i = 0; i < 2; i++) {
            const __half* base = Xs + (wm + i * 16 + gr) * LD2 + k0 + 2 * gc;
            a[i][0] = lds32(base);
            a[i][1] = lds32(base + 8 * LD2);
            a[i][2] = lds32(base + 8);
            a[i][3] = lds32(base + 8 * LD2 + 8);
        }
#pragma unroll
        for (int j = 0; j < 8; j++) {
            const __half* base = Ws + (wn + j * 8 + gr) * LD2 + k0 + 2 * gc;
            b[j][0] = lds32(base);
            b[j][1] = lds32(base + 8);
        }
#pragma unroll
        for (int i = 0; i < 2; i++)
#pragma unroll
            for (int j = 0; j < 8; j++) mma_f16(c[i][j], a[i], b[j]);
    }
}

// ---------------- fused aggregation + etype GEMM (fp16 h gather) ----------------
constexpr int ESMEM = 1536;
constexpr int SM_AE = (64 + 128) * LD2 * 2 + 260 * 4 + ESMEM * 4;  // 59408 -> 3 CTAs/SM

template <bool SMI>
__device__ __forceinline__ void seg_sum(const uint2* __restrict__ hp,
                                        const int* __restrict__ eix, int estart,
                                        int r0, int r1, int lane, float4& acc) {
    int e = r0;
    for (; e + 4 <= r1; e += 4) {  // MLP-4 main loop
        int s0 = SMI ? eix[e - estart] : __ldg(&g_esrc[e]);
        int s1 = SMI ? eix[e + 1 - estart] : __ldg(&g_esrc[e + 1]);
        int s2 = SMI ? eix[e + 2 - estart] : __ldg(&g_esrc[e + 2]);
        int s3 = SMI ? eix[e + 3 - estart] : __ldg(&g_esrc[e + 3]);
        float4 x0 = up4(hp[(size_t)s0 * 32 + lane]);
        float4 x1 = up4(hp[(size_t)s1 * 32 + lane]);
        float4 x2 = up4(hp[(size_t)s2 * 32 + lane]);
        float4 x3 = up4(hp[(size_t)s3 * 32 + lane]);
        acc.x += (x0.x + x1.x) + (x2.x + x3.x);
        acc.y += (x0.y + x1.y) + (x2.y + x3.y);
        acc.z += (x0.z + x1.z) + (x2.z + x3.z);
        acc.w += (x0.w + x1.w) + (x2.w + x3.w);
    }
    int rem = r1 - e;  // 0..3: parallel tail, adds applied in order
    if (rem > 0) {
        int s0 = SMI ? eix[e - estart] : __ldg(&g_esrc[e]);
        int s1 = (rem > 1) ? (SMI ? eix[e + 1 - estart] : __ldg(&g_esrc[e + 1])) : s0;
        int s2 = (rem > 2) ? (SMI ? eix[e + 2 - estart] : __ldg(&g_esrc[e + 2])) : s0;
        float4 x0 = up4(hp[(size_t)s0 * 32 + lane]);
        float4 x1 = up4(hp[(size_t)s1 * 32 + lane]);
        float4 x2 = up4(hp[(size_t)s2 * 32 + lane]);
        acc.x += x0.x; acc.y += x0.y; acc.z += x0.z; acc.w += x0.w;
        if (rem > 1) { acc.x += x1.x; acc.y += x1.y; acc.z += x1.z; acc.w += x1.w; }
        if (rem > 2) { acc.x += x2.x; acc.y += x2.y; acc.z += x2.z; acc.w += x2.w; }
    }
}

__global__ __launch_bounds__(256, 3) void k_agg_etype(const __half* __restrict__ h,
                                                      const float* __restrict__ Wet) {
    extern __shared__ __half smh[];
    __half* Xs = smh;             // 64 x LD2
    __half* Ws = smh + 64 * LD2;  // 128 x LD2
    int* rps = reinterpret_cast<int*>(smh + 192 * LD2);  // 257 used
    int* eix = rps + 260;                                 // ESMEM entries
    int tid = threadIdx.x, lane = tid & 31, warp = tid >> 5;
    int rowBase = blockIdx.x * 64;
    int wm = (warp & 1) * 32, wn = (warp >> 1) * 32;
    int gr = lane >> 2, gc = lane & 3;
    const uint2* hp = reinterpret_cast<const uint2*>(h);

    {
        int base = 4 * rowBase;
        for (int i = tid; i < 257; i += 256) {
            int g = base + i;
            rps[i] = g_rp[g <= cM ? g : cM];
        }
    }
    __syncthreads();
    int estart = rps[0];
    int ecnt = rps[256] - estart;
    bool insm = (ecnt <= ESMEM);
    if (insm) {
        for (int i = tid; i < ecnt; i += 256) eix[i] = g_esrc[estart + i];
    }
    __syncthreads();

    float c[2][4][4];
#pragma unroll
    for (int i = 0; i < 2; i++)
#pragma unroll
        for (int j = 0; j < 4; j++)
#pragma unroll
            for (int q = 0; q < 4; q++) c[i][j][q] = 0.f;

    for (int ke = 0; ke < cK; ke++) {
        if (ke) __syncthreads();
#pragma unroll
        for (int i = 0; i < 8; i++) {
            int vl = warp * 8 + i;
            float4 acc = make_float4(0.f, 0.f, 0.f, 0.f);
            int r0 = rps[4 * vl + ke], r1 = rps[4 * vl + ke + 1];
            if (insm) seg_sum<true>(hp, eix, estart, r0, r1, lane, acc);
            else      seg_sum<false>(hp, eix, estart, r0, r1, lane, acc);
            *reinterpret_cast<uint2*>(Xs + vl * LD2 + lane * 4) =
                make_uint2(pk2(acc.x, acc.y), pk2(acc.z, acc.w));
        }
        load_tile_W128_16(Wet + (size_t)ke * cD * cD, cD, Ws, tid);
        __syncthreads();
        mma_loop32(Xs, Ws, wm, wn, gr, gc, c);
    }

    // epilogue -> fp16 a
#pragma unroll
    for (int i = 0; i < 2; i++)
#pragma unroll
        for (int j = 0; j < 4; j++) {
            int col = wn + j * 8 + 2 * gc;
#pragma unroll
            for (int half = 0; half < 2; half++) {
                int r = rowBase + wm + i * 16 + gr + half * 8;
                if (r >= cN) continue;
                float2 bs = *reinterpret_cast<const float2*>(g_bsum + (size_t)r * cD + col);
                uint32_t o = pk2(c[i][j][half * 2] + bs.x, c[i][j][half * 2 + 1] + bs.y);
                *reinterpret_cast<uint32_t*>(g_a_h + (size_t)r * cD + col) = o;
            }
        }
}

// ---------------- fused GRU (fp16 A + fp16 Xh tile; f32 blend; dual h output) ----------------
constexpr int SM_GRU = (2 * 128 + 64) * LD2 * 2;  // 87040 -> 2 CTAs/SM

__global__ __launch_bounds__(256, 2) void k_gru_fused(
    const __half* __restrict__ A, const float* __restrict__ H,
    const __half* __restrict__ Hh,
    const float* __restrict__ W_ih, const float* __restrict__ b_ih,
    const float* __restrict__ W_hh, const float* __restrict__ b_hh,
    float* __restrict__ hout, __half* __restrict__ houth) {
    extern __shared__ __half smh[];
    __half* Xa = smh;
    __half* Xh = smh + 128 * LD2;
    __half* Ws = smh + 256 * LD2;
    int tid = threadIdx.x;
    int rowBase = blockIdx.x * 128, colBase = blockIdx.y * 64;
    int lane = tid & 31, warp = tid >> 5;
    int wm = (warp & 3) * 32, wn = (warp >> 2) * 32;
    int gr = lane >> 2, gc = lane & 3;

    load_tile_A16(A, Xa, rowBase, cN, tid);
    load_tile_A16(Hh, Xh, rowBase, cN, tid);   // fp16 image == what X16 would produce

    float rf[2][4][4], zf[2][4][4], ci[2][4][4], ch[2][4][4];

#pragma unroll
    for (int g = 0; g < 3; g++) {
#pragma unroll
        for (int i = 0; i < 2; i++)
#pragma unroll
            for (int j = 0; j < 4; j++)
#pragma unroll
                for (int q = 0; q < 4; q++) { ci[i][j][q] = 0.f; ch[i][j][q] = 0.f; }

        load_tile_W64_16(W_ih + (size_t)g * 128 * cD, cD, Ws, colBase, tid);
        __syncthreads();
        mma_loop32(Xa, Ws, wm, wn, gr, gc, ci);
        __syncthreads();
        load_tile_W64_16(W_hh + (size_t)g * 128 * cD, cD, Ws, colBase, tid);
        __syncthreads();
        mma_loop32(Xh, Ws, wm, wn, gr, gc, ch);
        __syncthreads();

#pragma unroll
        for (int i = 0; i < 2; i++)
#pragma unroll
            for (int j = 0; j < 4; j++) {
                int col = colBase + wn + j * 8 + 2 * gc;
                float bi0 = __ldg(&b_ih[g * 128 + col]), bi1 = __ldg(&b_ih[g * 128 + col + 1]);
                float bh0 = __ldg(&b_hh[g * 128 + col]), bh1 = __ldg(&b_hh[g * 128 + col + 1]);
                if (g == 0) {
#pragma unroll
                    for (int q = 0; q < 4; q++) {
                        float bi = (q & 1) ? bi1 : bi0, bh = (q & 1) ? bh1 : bh0;
                        rf[i][j][q] = sigmf(ci[i][j][q] + bi + ch[i][j][q] + bh);
                    }
                } else if (g == 1) {
#pragma unroll
                    for (int q = 0; q < 4; q++) {
                        float bi = (q & 1) ? bi1 : bi0, bh = (q & 1) ? bh1 : bh0;
                        zf[i][j][q] = sigmf(ci[i][j][q] + bi + ch[i][j][q] + bh);
                    }
                } else {
#pragma unroll
                    for (int half = 0; half < 2; half++) {
                        int r = rowBase + wm + i * 16 + gr + half * 8;
                        if (r >= cN) continue;
                        float2 hv = *reinterpret_cast<const float2*>(H + (size_t)r * cD + col);
                        int q0 = half * 2, q1 = half * 2 + 1;
                        float n0 = tanhf(ci[i][j][q0] + bi0 + rf[i][j][q0] * (ch[i][j][q0] + bh0));
                        float n1 = tanhf(ci[i][j][q1] + bi1 + rf[i][j][q1] * (ch[i][j][q1] + bh1));
                        float2 o;
                        o.x = (1.0f - zf[i][j][q0]) * n0 + zf[i][j][q0] * hv.x;
                        o.y = (1.0f - zf[i][j][q1]) * n1 + zf[i][j][q1] * hv.y;
                        *reinterpret_cast<float2*>(hout + (size_t)r * cD + col) = o;
                        *reinterpret_cast<uint32_t*>(houth + (size_t)r * cD + col) = pk2(o.x, o.y);
                    }
                }
            }
    }
}

// ---------------- fused output head (fp16 tiles) ----------------
constexpr int SM_HEAD = 3 * 128 * LD2 * 2;  // 104448 -> 2 CTAs/SM

__global__ __launch_bounds__(256, 2) void k_head(
    const __half* __restrict__ Hh, const __half* __restrict__ Fh,
    const float* __restrict__ i_w, const float* __restrict__ i_b,
    const float* __restrict__ j_w, const float* __restrict__ j_b,
    float* __restrict__ out) {
    extern __shared__ __half smh[];
    __half* Xh = smh;
    __half* Xf = smh + 128 * LD2;
    __half* Ws = smh + 256 * LD2;
    int tid = threadIdx.x;
    int rowBase = blockIdx.x * 128;
    int lane = tid & 31, warp = tid >> 5;
    int wm = (warp & 3) * 32, wn = (warp >> 2) * 64;
    int gr = lane >> 2, gc = lane & 3;

    load_tile_A16(Hh, Xh, rowBase, cN, tid);
    load_tile_A16(Fh, Xf, rowBase, cN, tid);

    float cg[2][8][4], cj[2][8][4];
#pragma unroll
    for (int i = 0; i < 2; i++)
#pragma unroll
        for (int j = 0; j < 8; j++)
#pragma unroll
            for (int q = 0; q < 4; q++) { cg[i][j][q] = 0.f; cj[i][j][q] = 0.f; }

    load_tile_W128_16(i_w, 2 * cD, Ws, tid);
    __syncthreads();
    mma_loop64(Xh, Ws, wm, wn, gr, gc, cg);
    __syncthreads();
    load_tile_W128_16(i_w + cD, 2 * cD, Ws, tid);
    __syncthreads();
    mma_loop64(Xf, Ws, wm, wn, gr, gc, cg);
    __syncthreads();
    load_tile_W128_16(j_w, cD, Ws, tid);
    __syncthreads();
    mma_loop64(Xh, Ws, wm, wn, gr, gc, cj);

#pragma unroll
    for (int i = 0; i < 2; i++)
#pragma unroll
        for (int j = 0; j < 8; j++) {
            int col = wn + j * 8 + 2 * gc;
            float ib0 = __ldg(&i_b[col]), ib1 = __ldg(&i_b[col + 1]);
            float jb0 = __ldg(&j_b[col]), jb1 = __ldg(&j_b[col + 1]);
#pragma unroll
            for (int half = 0; half < 2; half++) {
                int r = rowBase + wm + i * 16 + gr + half * 8;
                if (r >= cN) continue;
                int q0 = half * 2, q1 = half * 2 + 1;
                float2 o;
                o.x = sigmf(cg[i][j][q0] + ib0) * (cj[i][j][q0] + jb0);
                o.y = sigmf(cg[i][j][q1] + ib1) * (cj[i][j][q1] + jb1);
                *reinterpret_cast<float2*>(out + (size_t)r * cD + col) = o;
            }
        }
}

// ---------------- host ----------------
extern "C" void kernel_launch(void* const* d_in, const int* in_sizes, int n_in,
                              void* d_out, int out_size) {
    (void)in_sizes; (void)n_in; (void)out_size;
    const float* features = (const float*)d_in[0];
    const int*   src      = (const int*)d_in[1];
    const int*   dst      = (const int*)d_in[2];
    const int*   etypes   = (const int*)d_in[3];
    const float* W_et     = (const float*)d_in[4];
    const float* b_et     = (const float*)d_in[5];
    const float* W_ih     = (const float*)d_in[6];
    const float* b_ih     = (const float*)d_in[7];
    const float* W_hh     = (const float*)d_in[8];
    const float* b_hh     = (const float*)d_in[9];
    const float* i_w      = (const float*)d_in[10];
    const float* i_b      = (const float*)d_in[11];
    const float* j_w      = (const float*)d_in[12];
    const float* j_b      = (const float*)d_in[13];
    float* out = (float*)d_out;

    float *h0, *h1;
    __half *h0h, *h1h, *feath, *abuf;
    cudaGetSymbolAddress((void**)&h0, g_h0);
    cudaGetSymbolAddress((void**)&h1, g_h1);
    cudaGetSymbolAddress((void**)&h0h, g_h0h);
    cudaGetSymbolAddress((void**)&h1h, g_h1h);
    cudaGetSymbolAddress((void**)&feath, g_feath);
    cudaGetSymbolAddress((void**)&abuf, g_a_h);

    cudaFuncSetAttribute(k_agg_etype, cudaFuncAttributeMaxDynamicSharedMemorySize, SM_AE);
    cudaFuncSetAttribute(k_gru_fused, cudaFuncAttributeMaxDynamicSharedMemorySize, SM_GRU);
    cudaFuncSetAttribute(k_head, cudaFuncAttributeMaxDynamicSharedMemorySize, SM_HEAD);

    // ---- CSR build: 3 launches, then agg is launch index 3 (ncu window) ----
    k_hist<<<(cE + 255) / 256, 256>>>(dst, etypes);
    k_scanlb<<<NTILE, 1024>>>();
    {
        int tot = cN * cD > cE ? cN * cD : cE;
        k_scatter_bsum<<<(tot + 255) / 256, 256>>>(src, dst, etypes, b_et, features);
    }

    const int RB64 = (cN + 63) / 64;    // 1563
    const int RB128 = (cN + 127) / 128; // 782

    const float* hc = features;
    const __half* hch = feath;
    float* houts[3] = {h0, h1, h0};
    __half* houths[3] = {h0h, h1h, h0h};
    for (int s = 0; s < 3; s++) {
        k_agg_etype<<<RB64, 256, SM_AE>>>(hch, W_et);  // fp16 gather -> g_a_h
        k_gru_fused<<<dim3(RB128, 2), 256, SM_GRU>>>(abuf, hc, hch, W_ih, b_ih, W_hh, b_hh,
                                                     houts[s], houths[s]);
        hc = houts[s];
        hch = houths[s];
    }
    k_head<<<RB128, 256, SM_HEAD>>>(hch, feath, i_w, i_b, j_w, j_b, out);
}

// round 16
// speedup vs baseline: 2.1233x; 1.1312x over previous
#include <cuda_runtime.h>
#include <cuda_fp16.h>
#include <cstdint>

// ---------------- problem constants ----------------
constexpr int cN = 100000;   // nodes
constexpr int cE = 1600000;  // edges
constexpr int cD = 128;      // feature dim
constexpr int cK = 4;        // etypes
constexpr int cM = cK * cN;                 // 400000 keys (dst*4+etype)
constexpr int NTILE = (cM + 1023) / 1024;   // 391 scan tiles

// ---------------- scratch ----------------
__device__ __align__(16) __half g_h0h[(size_t)cN * cD];   // fp16 h state (ping)
__device__ __align__(16) __half g_h1h[(size_t)cN * cD];   // fp16 h state (pong)
__device__ __align__(16) __half g_feath[(size_t)cN * cD]; // fp16 image of features
__device__ __align__(16) __half g_a_h[(size_t)cN * cD];   // message result (fp16)
__device__ __align__(16) float g_bsum[(size_t)cN * cD];

__device__ int g_deg[cM];          // zero-initialized; re-zeroed by k_scanlb each launch
__device__ int g_rp[cM + 1];
__device__ int g_cur[cM];
__device__ int g_esrc[cE];
__device__ unsigned long long g_lbstate[NTILE + 1];
__device__ int g_ticket;

// ---------------- helpers ----------------
__device__ __forceinline__ float sigmf(float x) { return 1.0f / (1.0f + __expf(-x)); }

__device__ __forceinline__ uint32_t pk2(float x, float y) {
    __half2 h = __floats2half2_rn(x, y);
    return *reinterpret_cast<uint32_t*>(&h);
}
__device__ __forceinline__ float4 up4(uint2 v) {
    float2 fa = __half22float2(*reinterpret_cast<const __half2*>(&v.x));
    float2 fb = __half22float2(*reinterpret_cast<const __half2*>(&v.y));
    return make_float4(fa.x, fa.y, fb.x, fb.y);
}
__device__ __forceinline__ float2 up2(uint32_t v) {
    return __half22float2(*reinterpret_cast<const __half2*>(&v));
}

__device__ __forceinline__ void mma_f16(float c[4], const uint32_t a[4], const uint32_t b[2]) {
    asm volatile(
        "mma.sync.aligned.m16n8k16.row.col.f32.f16.f16.f32 "
        "{%0,%1,%2,%3}, {%4,%5,%6,%7}, {%8,%9}, {%0,%1,%2,%3};"
        : "+f"(c[0]), "+f"(c[1]), "+f"(c[2]), "+f"(c[3])
        : "r"(a[0]), "r"(a[1]), "r"(a[2]), "r"(a[3]), "r"(b[0]), "r"(b[1]));
}

// ---------------- CSR build: 3 kernels ----------------
__global__ void k_hist(const int* __restrict__ dst, const int* __restrict__ et) {
    int e = blockIdx.x * blockDim.x + threadIdx.x;
    if (e < cE) atomicAdd(&g_deg[dst[e] * 4 + et[e]], 1);
    if (blockIdx.x == 0) {
        if (threadIdx.x == 0) g_ticket = 0;
        for (int i = threadIdx.x; i <= NTILE; i += blockDim.x) g_lbstate[i] = 0ull;
    }
}

__global__ void k_scanlb() {
    __shared__ int sm[1024];
    __shared__ int bid_s, exc_s;
    if (threadIdx.x == 0) bid_s = atomicAdd(&g_ticket, 1);
    __syncthreads();
    int bid = bid_s;
    int i = bid * 1024 + threadIdx.x;
    int v = 0;
    if (i < cM) {
        v = g_deg[i];
        g_deg[i] = 0;  // reset for next launch
    }
    sm[threadIdx.x] = v;
    __syncthreads();
    for (int off = 1; off < 1024; off <<= 1) {
        int t = 0;
        if (threadIdx.x >= off) t = sm[threadIdx.x - off];
        __syncthreads();
        sm[threadIdx.x] += t;
        __syncthreads();
    }
    int total = sm[1023];
    if (threadIdx.x == 0) {
        if (bid == 0) {
            atomicExch(&g_lbstate[0], (2ull << 32) | (unsigned)total);
            exc_s = 0;
        } else {
            atomicExch(&g_lbstate[bid], (1ull << 32) | (unsigned)total);
            int exc = 0;
            for (int j = bid - 1;; j--) {
                unsigned long long s;
                do { s = atomicAdd(&g_lbstate[j], 0ull); } while ((s >> 32) == 0ull);
                exc += (int)(unsigned)(s & 0xffffffffull);
                if ((s >> 32) == 2ull) break;
            }
            atomicExch(&g_lbstate[bid], (2ull << 32) | (unsigned)(exc + total));
            exc_s = exc;
        }
    }
    __syncthreads();
    int exc = exc_s;
    if (i < cM) {
        int rp = exc + sm[threadIdx.x] - v;  // exclusive
        g_rp[i] = rp;
        g_cur[i] = rp;
    }
    if (bid == NTILE - 1 && threadIdx.x == 1023) g_rp[cM] = exc + total;
}

__global__ void k_scatter_bsum(const int* __restrict__ src, const int* __restrict__ dst,
                               const int* __restrict__ et, const float* __restrict__ bet,
                               const float* __restrict__ feat) {
    int idx = blockIdx.x * blockDim.x + threadIdx.x;
    if (idx < cE) {
        int key = dst[idx] * 4 + et[idx];
        int pos = atomicAdd(&g_cur[key], 1);
        g_esrc[pos] = src[idx];
    }
    if (idx < cN * cD) {
        int r = idx >> 7, col = idx & 127;
        int rp[5];
#pragma unroll
        for (int k = 0; k <= 4; k++) rp[k] = g_rp[4 * r + k];
        float v = 0.f;
#pragma unroll
        for (int k = 0; k < 4; k++) v += (float)(rp[k + 1] - rp[k]) * __ldg(&bet[k * cD + col]);
        g_bsum[idx] = v;
        g_feath[idx] = __float2half_rn(feat[idx]);  // fp16 image of features
    }
}

// ---------------- fp16 GEMM building blocks ----------------
constexpr int LD2 = 136;  // halves per smem row (272B stride, conflict-free)

// fp16-source X tile (no conversion, half the bytes)
__device__ __forceinline__ void load_tile_A16(const __half* __restrict__ X, __half* Xs,
                                              int rowBase, int nrows, int tid) {
    for (int idx = tid; idx < 128 * 32; idx += 256) {
        int row = idx >> 5, c4 = (idx & 31) * 4;
        uint2 v = make_uint2(0u, 0u);
        int r = rowBase + row;
        if (r < nrows) v = *reinterpret_cast<const uint2*>(X + (size_t)r * cD + c4);
        *reinterpret_cast<uint2*>(Xs + row * LD2 + c4) = v;
    }
}
__device__ __forceinline__ void load_tile_W64_16(const float* __restrict__ W, int ldw, __half* Ws,
                                                 int colBase, int tid) {
    for (int idx = tid; idx < 64 * 32; idx += 256) {
        int o = idx >> 5, c4 = (idx & 31) * 4;
        float4 v = *reinterpret_cast<const float4*>(W + (size_t)(colBase + o) * ldw + c4);
        *reinterpret_cast<uint2*>(Ws + o * LD2 + c4) = make_uint2(pk2(v.x, v.y), pk2(v.z, v.w));
    }
}
__device__ __forceinline__ void load_tile_W128_16(const float* __restrict__ W, int ldw, __half* Ws,
                                                  int tid) {
    for (int idx = tid; idx < 128 * 32; idx += 256) {
        int o = idx >> 5, c4 = (idx & 31) * 4;
        float4 v = *reinterpret_cast<const float4*>(W + (size_t)o * ldw + c4);
        *reinterpret_cast<uint2*>(Ws + o * LD2 + c4) = make_uint2(pk2(v.x, v.y), pk2(v.z, v.w));
    }
}
__device__ __forceinline__ uint32_t lds32(const __half* p) {
    return *reinterpret_cast<const uint32_t*>(p);
}

__device__ __forceinline__ void mma_loop32(const __half* Xs, const __half* Ws,
                                           int wm, int wn, int gr, int gc, float c[2][4][4]) {
#pragma unroll
    for (int k0 = 0; k0 < cD; k0 += 16) {
        uint32_t a[2][4], b[4][2];
#pragma unroll
        for (int i = 0; i < 2; i++) {
            const __half* base = Xs + (wm + i * 16 + gr) * LD2 + k0 + 2 * gc;
            a[i][0] = lds32(base);
            a[i][1] = lds32(base + 8 * LD2);
            a[i][2] = lds32(base + 8);
            a[i][3] = lds32(base + 8 * LD2 + 8);
        }
#pragma unroll
        for (int j = 0; j < 4; j++) {
            const __half* base = Ws + (wn + j * 8 + gr) * LD2 + k0 + 2 * gc;
            b[j][0] = lds32(base);
            b[j][1] = lds32(base + 8);
        }
#pragma unroll
        for (int i = 0; i < 2; i++)
#pragma unroll
            for (int j = 0; j < 4; j++) mma_f16(c[i][j], a[i], b[j]);
    }
}
__device__ __forceinline__ void mma_loop64(const __half* Xs, const __half* Ws,
                                           int wm, int wn, int gr, int gc, float c[2][8][4]) {
#pragma unroll
    for (int k0 = 0; k0 < cD; k0 += 16) {
        uint32_t a[2][4], b[8][2];
#pragma unroll
        for (int i = 0; i < 2; i++) {
            const __half* base = Xs + (wm + i * 16 + gr) * LD2 + k0 + 2 * gc;
            a[i][0] = lds32(base);
            a[i][1] = lds32(base + 8 * LD2);
            a[i][2] = lds32(base + 8);
            a[i][3] = lds32(base + 8 * LD2 + 8);
        }
#pragma unroll
        for (int j = 0; j < 8; j++) {
            const __half* base = Ws + (wn + j * 8 + gr) * LD2 + k0 + 2 * gc;
            b[j][0] = lds32(base);
            b[j][1] = lds32(base + 8);
        }
#pragma unroll
        for (int i = 0; i < 2; i++)
#pragma unroll
            for (int j = 0; j < 8; j++) mma_f16(c[i][j], a[i], b[j]);
    }
}

// ---------------- fused aggregation + etype GEMM (fp16 h gather) ----------------
constexpr int ESMEM = 1536;
constexpr int SM_AE = (64 + 128) * LD2 * 2 + 260 * 4 + ESMEM * 4;  // 59408 -> 3 CTAs/SM

template <bool SMI>
__device__ __forceinline__ void seg_sum(const uint2* __restrict__ hp,
                                        const int* __restrict__ eix, int estart,
                                        int r0, int r1, int lane, float4& acc) {
    int e = r0;
    for (; e + 4 <= r1; e += 4) {  // MLP-4 main loop
        int s0 = SMI ? eix[e - estart] : __ldg(&g_esrc[e]);
        int s1 = SMI ? eix[e + 1 - estart] : __ldg(&g_esrc[e + 1]);
        int s2 = SMI ? eix[e + 2 - estart] : __ldg(&g_esrc[e + 2]);
        int s3 = SMI ? eix[e + 3 - estart] : __ldg(&g_esrc[e + 3]);
        float4 x0 = up4(hp[(size_t)s0 * 32 + lane]);
        float4 x1 = up4(hp[(size_t)s1 * 32 + lane]);
        float4 x2 = up4(hp[(size_t)s2 * 32 + lane]);
        float4 x3 = up4(hp[(size_t)s3 * 32 + lane]);
        acc.x += (x0.x + x1.x) + (x2.x + x3.x);
        acc.y += (x0.y + x1.y) + (x2.y + x3.y);
        acc.z += (x0.z + x1.z) + (x2.z + x3.z);
        acc.w += (x0.w + x1.w) + (x2.w + x3.w);
    }
    int rem = r1 - e;  // 0..3: parallel tail, adds applied in order
    if (rem > 0) {
        int s0 = SMI ? eix[e - estart] : __ldg(&g_esrc[e]);
        int s1 = (rem > 1) ? (SMI ? eix[e + 1 - estart] : __ldg(&g_esrc[e + 1])) : s0;
        int s2 = (rem > 2) ? (SMI ? eix[e + 2 - estart] : __ldg(&g_esrc[e + 2])) : s0;
        float4 x0 = up4(hp[(size_t)s0 * 32 + lane]);
        float4 x1 = up4(hp[(size_t)s1 * 32 + lane]);
        float4 x2 = up4(hp[(size_t)s2 * 32 + lane]);
        acc.x += x0.x; acc.y += x0.y; acc.z += x0.z; acc.w += x0.w;
        if (rem > 1) { acc.x += x1.x; acc.y += x1.y; acc.z += x1.z; acc.w += x1.w; }
        if (rem > 2) { acc.x += x2.x; acc.y += x2.y; acc.z += x2.z; acc.w += x2.w; }
    }
}

__global__ __launch_bounds__(256, 3) void k_agg_etype(const __half* __restrict__ h,
                                                      const float* __restrict__ Wet) {
    extern __shared__ __half smh[];
    __half* Xs = smh;             // 64 x LD2
    __half* Ws = smh + 64 * LD2;  // 128 x LD2
    int* rps = reinterpret_cast<int*>(smh + 192 * LD2);  // 257 used
    int* eix = rps + 260;                                 // ESMEM entries
    int tid = threadIdx.x, lane = tid & 31, warp = tid >> 5;
    int rowBase = blockIdx.x * 64;
    int wm = (warp & 1) * 32, wn = (warp >> 1) * 32;
    int gr = lane >> 2, gc = lane & 3;
    const uint2* hp = reinterpret_cast<const uint2*>(h);

    {
        int base = 4 * rowBase;
        for (int i = tid; i < 257; i += 256) {
            int g = base + i;
            rps[i] = g_rp[g <= cM ? g : cM];
        }
    }
    __syncthreads();
    int estart = rps[0];
    int ecnt = rps[256] - estart;
    bool insm = (ecnt <= ESMEM);
    if (insm) {
        for (int i = tid; i < ecnt; i += 256) eix[i] = g_esrc[estart + i];
    }
    __syncthreads();

    float c[2][4][4];
#pragma unroll
    for (int i = 0; i < 2; i++)
#pragma unroll
        for (int j = 0; j < 4; j++)
#pragma unroll
            for (int q = 0; q < 4; q++) c[i][j][q] = 0.f;

    for (int ke = 0; ke < cK; ke++) {
        if (ke) __syncthreads();
#pragma unroll
        for (int i = 0; i < 8; i++) {
            int vl = warp * 8 + i;
            float4 acc = make_float4(0.f, 0.f, 0.f, 0.f);
            int r0 = rps[4 * vl + ke], r1 = rps[4 * vl + ke + 1];
            if (insm) seg_sum<true>(hp, eix, estart, r0, r1, lane, acc);
            else      seg_sum<false>(hp, eix, estart, r0, r1, lane, acc);
            *reinterpret_cast<uint2*>(Xs + vl * LD2 + lane * 4) =
                make_uint2(pk2(acc.x, acc.y), pk2(acc.z, acc.w));
        }
        load_tile_W128_16(Wet + (size_t)ke * cD * cD, cD, Ws, tid);
        __syncthreads();
        mma_loop32(Xs, Ws, wm, wn, gr, gc, c);
    }

    // epilogue -> fp16 a
#pragma unroll
    for (int i = 0; i < 2; i++)
#pragma unroll
        for (int j = 0; j < 4; j++) {
            int col = wn + j * 8 + 2 * gc;
#pragma unroll
            for (int half = 0; half < 2; half++) {
                int r = rowBase + wm + i * 16 + gr + half * 8;
                if (r >= cN) continue;
                float2 bs = *reinterpret_cast<const float2*>(g_bsum + (size_t)r * cD + col);
                uint32_t o = pk2(c[i][j][half * 2] + bs.x, c[i][j][half * 2 + 1] + bs.y);
                *reinterpret_cast<uint32_t*>(g_a_h + (size_t)r * cD + col) = o;
            }
        }
}

// ---------------- fused GRU (pure fp16 state; blend reads smem Xh tile) ----------------
constexpr int SM_GRU = (2 * 128 + 64) * LD2 * 2;  // 87040 -> 2 CTAs/SM

__global__ __launch_bounds__(256, 2) void k_gru_fused(
    const __half* __restrict__ A, const __half* __restrict__ Hh,
    const float* __restrict__ W_ih, const float* __restrict__ b_ih,
    const float* __restrict__ W_hh, const float* __restrict__ b_hh,
    __half* __restrict__ houth) {
    extern __shared__ __half smh[];
    __half* Xa = smh;
    __half* Xh = smh + 128 * LD2;
    __half* Ws = smh + 256 * LD2;
    int tid = threadIdx.x;
    int rowBase = blockIdx.x * 128, colBase = blockIdx.y * 64;
    int lane = tid & 31, warp = tid >> 5;
    int wm = (warp & 3) * 32, wn = (warp >> 2) * 32;
    int gr = lane >> 2, gc = lane & 3;

    load_tile_A16(A, Xa, rowBase, cN, tid);
    load_tile_A16(Hh, Xh, rowBase, cN, tid);

    float rf[2][4][4], zf[2][4][4], ci[2][4][4], ch[2][4][4];

#pragma unroll
    for (int g = 0; g < 3; g++) {
#pragma unroll
        for (int i = 0; i < 2; i++)
#pragma unroll
            for (int j = 0; j < 4; j++)
#pragma unroll
                for (int q = 0; q < 4; q++) { ci[i][j][q] = 0.f; ch[i][j][q] = 0.f; }

        load_tile_W64_16(W_ih + (size_t)g * 128 * cD, cD, Ws, colBase, tid);
        __syncthreads();
        mma_loop32(Xa, Ws, wm, wn, gr, gc, ci);
        __syncthreads();
        load_tile_W64_16(W_hh + (size_t)g * 128 * cD, cD, Ws, colBase, tid);
        __syncthreads();
        mma_loop32(Xh, Ws, wm, wn, gr, gc, ch);
        __syncthreads();

#pragma unroll
        for (int i = 0; i < 2; i++)
#pragma unroll
            for (int j = 0; j < 4; j++) {
                int col = colBase + wn + j * 8 + 2 * gc;
                float bi0 = __ldg(&b_ih[g * 128 + col]), bi1 = __ldg(&b_ih[g * 128 + col + 1]);
                float bh0 = __ldg(&b_hh[g * 128 + col]), bh1 = __ldg(&b_hh[g * 128 + col + 1]);
                if (g == 0) {
#pragma unroll
                    for (int q = 0; q < 4; q++) {
                        float bi = (q & 1) ? bi1 : bi0, bh = (q & 1) ? bh1 : bh0;
                        rf[i][j][q] = sigmf(ci[i][j][q] + bi + ch[i][j][q] + bh);
                    }
                } else if (g == 1) {
#pragma unroll
                    for (int q = 0; q < 4; q++) {
                        float bi = (q & 1) ? bi1 : bi0, bh = (q & 1) ? bh1 : bh0;
                        zf[i][j][q] = sigmf(ci[i][j][q] + bi + ch[i][j][q] + bh);
                    }
                } else {
#pragma unroll
                    for (int half = 0; half < 2; half++) {
                        int lr = wm + i * 16 + gr + half * 8;   // local row in tile
                        int r = rowBase + lr;
                        if (r >= cN) continue;
                        // blend h comes from the fp16 smem tile (no global read)
                        float2 hv = up2(lds32(Xh + lr * LD2 + col));
                        int q0 = half * 2, q1 = half * 2 + 1;
                        float n0 = tanhf(ci[i][j][q0] + bi0 + rf[i][j][q0] * (ch[i][j][q0] + bh0));
                        float n1 = tanhf(ci[i][j][q1] + bi1 + rf[i][j][q1] * (ch[i][j][q1] + bh1));
                        float o0 = (1.0f - zf[i][j][q0]) * n0 + zf[i][j][q0] * hv.x;
                        float o1 = (1.0f - zf[i][j][q1]) * n1 + zf[i][j][q1] * hv.y;
                        *reinterpret_cast<uint32_t*>(houth + (size_t)r * cD + col) = pk2(o0, o1);
                    }
                }
            }
    }
}

// ---------------- fused output head (fp16 tiles) ----------------
constexpr int SM_HEAD = 3 * 128 * LD2 * 2;  // 104448 -> 2 CTAs/SM

__global__ __launch_bounds__(256, 2) void k_head(
    const __half* __restrict__ Hh, const __half* __restrict__ Fh,
    const float* __restrict__ i_w, const float* __restrict__ i_b,
    const float* __restrict__ j_w, const float* __restrict__ j_b,
    float* __restrict__ out) {
    extern __shared__ __half smh[];
    __half* Xh = smh;
    __half* Xf = smh + 128 * LD2;
    __half* Ws = smh + 256 * LD2;
    int tid = threadIdx.x;
    int rowBase = blockIdx.x * 128;
    int lane = tid & 31, warp = tid >> 5;
    int wm = (warp & 3) * 32, wn = (warp >> 2) * 64;
    int gr = lane >> 2, gc = lane & 3;

    load_tile_A16(Hh, Xh, rowBase, cN, tid);
    load_tile_A16(Fh, Xf, rowBase, cN, tid);

    float cg[2][8][4], cj[2][8][4];
#pragma unroll
    for (int i = 0; i < 2; i++)
#pragma unroll
        for (int j = 0; j < 8; j++)
#pragma unroll
            for (int q = 0; q < 4; q++) { cg[i][j][q] = 0.f; cj[i][j][q] = 0.f; }

    load_tile_W128_16(i_w, 2 * cD, Ws, tid);
    __syncthreads();
    mma_loop64(Xh, Ws, wm, wn, gr, gc, cg);
    __syncthreads();
    load_tile_W128_16(i_w + cD, 2 * cD, Ws, tid);
    __syncthreads();
    mma_loop64(Xf, Ws, wm, wn, gr, gc, cg);
    __syncthreads();
    load_tile_W128_16(j_w, cD, Ws, tid);
    __syncthreads();
    mma_loop64(Xh, Ws, wm, wn, gr, gc, cj);

#pragma unroll
    for (int i = 0; i < 2; i++)
#pragma unroll
        for (int j = 0; j < 8; j++) {
            int col = wn + j * 8 + 2 * gc;
            float ib0 = __ldg(&i_b[col]), ib1 = __ldg(&i_b[col + 1]);
            float jb0 = __ldg(&j_b[col]), jb1 = __ldg(&j_b[col + 1]);
#pragma unroll
            for (int half = 0; half < 2; half++) {
                int r = rowBase + wm + i * 16 + gr + half * 8;
                if (r >= cN) continue;
                int q0 = half * 2, q1 = half * 2 + 1;
                float2 o;
                o.x = sigmf(cg[i][j][q0] + ib0) * (cj[i][j][q0] + jb0);
                o.y = sigmf(cg[i][j][q1] + ib1) * (cj[i][j][q1] + jb1);
                *reinterpret_cast<float2*>(out + (size_t)r * cD + col) = o;
            }
        }
}

// ---------------- host ----------------
extern "C" void kernel_launch(void* const* d_in, const int* in_sizes, int n_in,
                              void* d_out, int out_size) {
    (void)in_sizes; (void)n_in; (void)out_size;
    const float* features = (const float*)d_in[0];
    const int*   src      = (const int*)d_in[1];
    const int*   dst      = (const int*)d_in[2];
    const int*   etypes   = (const int*)d_in[3];
    const float* W_et     = (const float*)d_in[4];
    const float* b_et     = (const float*)d_in[5];
    const float* W_ih     = (const float*)d_in[6];
    const float* b_ih     = (const float*)d_in[7];
    const float* W_hh     = (const float*)d_in[8];
    const float* b_hh     = (const float*)d_in[9];
    const float* i_w      = (const float*)d_in[10];
    const float* i_b      = (const float*)d_in[11];
    const float* j_w      = (const float*)d_in[12];
    const float* j_b      = (const float*)d_in[13];
    float* out = (float*)d_out;

    __half *h0h, *h1h, *feath, *abuf;
    cudaGetSymbolAddress((void**)&h0h, g_h0h);
    cudaGetSymbolAddress((void**)&h1h, g_h1h);
    cudaGetSymbolAddress((void**)&feath, g_feath);
    cudaGetSymbolAddress((void**)&abuf, g_a_h);

    cudaFuncSetAttribute(k_agg_etype, cudaFuncAttributeMaxDynamicSharedMemorySize, SM_AE);
    cudaFuncSetAttribute(k_gru_fused, cudaFuncAttributeMaxDynamicSharedMemorySize, SM_GRU);
    cudaFuncSetAttribute(k_head, cudaFuncAttributeMaxDynamicSharedMemorySize, SM_HEAD);

    // ---- CSR build: 3 launches, then agg is launch index 3 (ncu window) ----
    k_hist<<<(cE + 255) / 256, 256>>>(dst, etypes);
    k_scanlb<<<NTILE, 1024>>>();
    {
        int tot = cN * cD > cE ? cN * cD : cE;
        k_scatter_bsum<<<(tot + 255) / 256, 256>>>(src, dst, etypes, b_et, features);
    }

    const int RB64 = (cN + 63) / 64;    // 1563
    const int RB128 = (cN + 127) / 128; // 782

    const __half* hch = feath;
    __half* houths[3] = {h0h, h1h, h0h};
    for (int s = 0; s < 3; s++) {
        k_agg_etype<<<RB64, 256, SM_AE>>>(hch, W_et);  // fp16 gather -> g_a_h
        k_gru_fused<<<dim3(RB128, 2), 256, SM_GRU>>>(abuf, hch, W_ih, b_ih, W_hh, b_hh,
                                                     houths[s]);
        hch = houths[s];
    }
    k_head<<<RB128, 256, SM_HEAD>>>(hch, feath, i_w, i_b, j_w, j_b, out);
}

// round 17
// speedup vs baseline: 2.2027x; 1.0374x over previous
#include <cuda_runtime.h>
#include <cuda_fp16.h>
#include <cstdint>

// ---------------- problem constants ----------------
constexpr int cN = 100000;   // nodes
constexpr int cE = 1600000;  // edges
constexpr int cD = 128;      // feature dim
constexpr int cK = 4;        // etypes
constexpr int cM = cK * cN;                 // 400000 keys (dst*4+etype)
constexpr int NTILE = (cM + 1023) / 1024;   // 391 scan tiles

// ---------------- scratch ----------------
__device__ __align__(16) __half g_h0h[(size_t)cN * cD];   // fp16 h state (ping)
__device__ __align__(16) __half g_h1h[(size_t)cN * cD];   // fp16 h state (pong)
__device__ __align__(16) __half g_feath[(size_t)cN * cD]; // fp16 image of features
__device__ __align__(16) __half g_a_h[(size_t)cN * cD];   // message result (fp16)
__device__ __align__(16) float g_bsum[(size_t)cN * cD];
__device__ __align__(16) __half g_wih_h[3 * cD * cD];     // fp16 image of W_ih
__device__ __align__(16) __half g_whh_h[3 * cD * cD];     // fp16 image of W_hh

__device__ int g_deg[cM];          // zero-initialized; re-zeroed by k_scanlb each launch
__device__ int g_rp[cM + 1];
__device__ int g_cur[cM];
__device__ int g_esrc[cE];
__device__ unsigned long long g_lbstate[NTILE + 1];
__device__ int g_ticket;

// ---------------- helpers ----------------
__device__ __forceinline__ float sigmf(float x) { return 1.0f / (1.0f + __expf(-x)); }

__device__ __forceinline__ uint32_t pk2(float x, float y) {
    __half2 h = __floats2half2_rn(x, y);
    return *reinterpret_cast<uint32_t*>(&h);
}
__device__ __forceinline__ float4 up4(uint2 v) {
    float2 fa = __half22float2(*reinterpret_cast<const __half2*>(&v.x));
    float2 fb = __half22float2(*reinterpret_cast<const __half2*>(&v.y));
    return make_float4(fa.x, fa.y, fb.x, fb.y);
}
__device__ __forceinline__ float2 up2(uint32_t v) {
    return __half22float2(*reinterpret_cast<const __half2*>(&v));
}

__device__ __forceinline__ void mma_f16(float c[4], const uint32_t a[4], const uint32_t b[2]) {
    asm volatile(
        "mma.sync.aligned.m16n8k16.row.col.f32.f16.f16.f32 "
        "{%0,%1,%2,%3}, {%4,%5,%6,%7}, {%8,%9}, {%0,%1,%2,%3};"
        : "+f"(c[0]), "+f"(c[1]), "+f"(c[2]), "+f"(c[3])
        : "r"(a[0]), "r"(a[1]), "r"(a[2]), "r"(a[3]), "r"(b[0]), "r"(b[1]));
}

// ---------------- CSR build: 3 kernels ----------------
__global__ void k_hist(const int* __restrict__ dst, const int* __restrict__ et) {
    int e = blockIdx.x * blockDim.x + threadIdx.x;
    if (e < cE) atomicAdd(&g_deg[dst[e] * 4 + et[e]], 1);
    if (blockIdx.x == 0) {
        if (threadIdx.x == 0) g_ticket = 0;
        for (int i = threadIdx.x; i <= NTILE; i += blockDim.x) g_lbstate[i] = 0ull;
    }
}

__global__ void k_scanlb() {
    __shared__ int sm[1024];
    __shared__ int bid_s, exc_s;
    if (threadIdx.x == 0) bid_s = atomicAdd(&g_ticket, 1);
    __syncthreads();
    int bid = bid_s;
    int i = bid * 1024 + threadIdx.x;
    int v = 0;
    if (i < cM) {
        v = g_deg[i];
        g_deg[i] = 0;  // reset for next launch
    }
    sm[threadIdx.x] = v;
    __syncthreads();
    for (int off = 1; off < 1024; off <<= 1) {
        int t = 0;
        if (threadIdx.x >= off) t = sm[threadIdx.x - off];
        __syncthreads();
        sm[threadIdx.x] += t;
        __syncthreads();
    }
    int total = sm[1023];
    if (threadIdx.x == 0) {
        if (bid == 0) {
            atomicExch(&g_lbstate[0], (2ull << 32) | (unsigned)total);
            exc_s = 0;
        } else {
            atomicExch(&g_lbstate[bid], (1ull << 32) | (unsigned)total);
            int exc = 0;
            for (int j = bid - 1;; j--) {
                unsigned long long s;
                do { s = atomicAdd(&g_lbstate[j], 0ull); } while ((s >> 32) == 0ull);
                exc += (int)(unsigned)(s & 0xffffffffull);
                if ((s >> 32) == 2ull) break;
            }
            atomicExch(&g_lbstate[bid], (2ull << 32) | (unsigned)(exc + total));
            exc_s = exc;
        }
    }
    __syncthreads();
    int exc = exc_s;
    if (i < cM) {
        int rp = exc + sm[threadIdx.x] - v;  // exclusive
        g_rp[i] = rp;
        g_cur[i] = rp;
    }
    if (bid == NTILE - 1 && threadIdx.x == 1023) g_rp[cM] = exc + total;
}

__global__ void k_scatter_bsum(const int* __restrict__ src, const int* __restrict__ dst,
                               const int* __restrict__ et, const float* __restrict__ bet,
                               const float* __restrict__ feat,
                               const float* __restrict__ Wih, const float* __restrict__ Whh) {
    int idx = blockIdx.x * blockDim.x + threadIdx.x;
    if (idx < cE) {
        int key = dst[idx] * 4 + et[idx];
        int pos = atomicAdd(&g_cur[key], 1);
        g_esrc[pos] = src[idx];
    }
    if (idx < cN * cD) {
        int r = idx >> 7, col = idx & 127;
        int rp[5];
#pragma unroll
        for (int k = 0; k <= 4; k++) rp[k] = g_rp[4 * r + k];
        float v = 0.f;
#pragma unroll
        for (int k = 0; k < 4; k++) v += (float)(rp[k + 1] - rp[k]) * __ldg(&bet[k * cD + col]);
        g_bsum[idx] = v;
        g_feath[idx] = __float2half_rn(feat[idx]);  // fp16 image of features
    }
    if (idx < 3 * cD * cD) {
        g_wih_h[idx] = __float2half_rn(Wih[idx]);
        g_whh_h[idx] = __float2half_rn(Whh[idx]);
    }
}

// ---------------- fp16 GEMM building blocks ----------------
constexpr int LD2 = 136;  // halves per smem row (272B stride, conflict-free)

// fp16-source X tile (no conversion, half the bytes); nt = block threads
__device__ __forceinline__ void load_tile_A16(const __half* __restrict__ X, __half* Xs,
                                              int rowBase, int nrows, int tid, int nt) {
    for (int idx = tid; idx < 128 * 32; idx += nt) {
        int row = idx >> 5, c4 = (idx & 31) * 4;
        uint2 v = make_uint2(0u, 0u);
        int r = rowBase + row;
        if (r < nrows) v = *reinterpret_cast<const uint2*>(X + (size_t)r * cD + c4);
        *reinterpret_cast<uint2*>(Xs + row * LD2 + c4) = v;
    }
}
// fp16-source full 128-row W tile
__device__ __forceinline__ void load_tile_W128_h(const __half* __restrict__ W, __half* Ws,
                                                 int tid, int nt) {
    for (int idx = tid; idx < 128 * 32; idx += nt) {
        int o = idx >> 5, c4 = (idx & 31) * 4;
        uint2 v = *reinterpret_cast<const uint2*>(W + (size_t)o * cD + c4);
        *reinterpret_cast<uint2*>(Ws + o * LD2 + c4) = v;
    }
}
__device__ __forceinline__ void load_tile_W128_16(const float* __restrict__ W, int ldw, __half* Ws,
                                                  int tid) {
    for (int idx = tid; idx < 128 * 32; idx += 256) {
        int o = idx >> 5, c4 = (idx & 31) * 4;
        float4 v = *reinterpret_cast<const float4*>(W + (size_t)o * ldw + c4);
        *reinterpret_cast<uint2*>(Ws + o * LD2 + c4) = make_uint2(pk2(v.x, v.y), pk2(v.z, v.w));
    }
}
__device__ __forceinline__ uint32_t lds32(const __half* p) {
    return *reinterpret_cast<const uint32_t*>(p);
}

__device__ __forceinline__ void mma_loop32(const __half* Xs, const __half* Ws,
                                           int wm, int wn, int gr, int gc, float c[2][4][4]) {
#pragma unroll
    for (int k0 = 0; k0 < cD; k0 += 16) {
        uint32_t a[2][4], b[4][2];
#pragma unroll
        for (int i = 0; i < 2; i++) {
            const __half* base = Xs + (wm + i * 16 + gr) * LD2 + k0 + 2 * gc;
            a[i][0] = lds32(base);
            a[i][1] = lds32(base + 8 * LD2);
            a[i][2] = lds32(base + 8);
            a[i][3] = lds32(base + 8 * LD2 + 8);
        }
#pragma unroll
        for (int j = 0; j < 4; j++) {
            const __half* base = Ws + (wn + j * 8 + gr) * LD2 + k0 + 2 * gc;
            b[j][0] = lds32(base);
            b[j][1] = lds32(base + 8);
        }
#pragma unroll
        for (int i = 0; i < 2; i++)
#pragma unroll
            for (int j = 0; j < 4; j++) mma_f16(c[i][j], a[i], b[j]);
    }
}
__device__ __forceinline__ void mma_loop64(const __half* Xs, const __half* Ws,
                                           int wm, int wn, int gr, int gc, float c[2][8][4]) {
#pragma unroll
    for (int k0 = 0; k0 < cD; k0 += 16) {
        uint32_t a[2][4], b[8][2];
#pragma unroll
        for (int i = 0; i < 2; i++) {
            const __half* base = Xs + (wm + i * 16 + gr) * LD2 + k0 + 2 * gc;
            a[i][0] = lds32(base);
            a[i][1] = lds32(base + 8 * LD2);
            a[i][2] = lds32(base + 8);
            a[i][3] = lds32(base + 8 * LD2 + 8);
        }
#pragma unroll
        for (int j = 0; j < 8; j++) {
            const __half* base = Ws + (wn + j * 8 + gr) * LD2 + k0 + 2 * gc;
            b[j][0] = lds32(base);
            b[j][1] = lds32(base + 8);
        }
#pragma unroll
        for (int i = 0; i < 2; i++)
#pragma unroll
            for (int j = 0; j < 8; j++) mma_f16(c[i][j], a[i], b[j]);
    }
}

// ---------------- fused aggregation + etype GEMM (fp16 h gather; unchanged R15) ----------------
constexpr int ESMEM = 1536;
constexpr int SM_AE = (64 + 128) * LD2 * 2 + 260 * 4 + ESMEM * 4;  // 59408 -> 3 CTAs/SM

template <bool SMI>
__device__ __forceinline__ void seg_sum(const uint2* __restrict__ hp,
                                        const int* __restrict__ eix, int estart,
                                        int r0, int r1, int lane, float4& acc) {
    int e = r0;
    for (; e + 4 <= r1; e += 4) {  // MLP-4 main loop
        int s0 = SMI ? eix[e - estart] : __ldg(&g_esrc[e]);
        int s1 = SMI ? eix[e + 1 - estart] : __ldg(&g_esrc[e + 1]);
        int s2 = SMI ? eix[e + 2 - estart] : __ldg(&g_esrc[e + 2]);
        int s3 = SMI ? eix[e + 3 - estart] : __ldg(&g_esrc[e + 3]);
        float4 x0 = up4(hp[(size_t)s0 * 32 + lane]);
        float4 x1 = up4(hp[(size_t)s1 * 32 + lane]);
        float4 x2 = up4(hp[(size_t)s2 * 32 + lane]);
        float4 x3 = up4(hp[(size_t)s3 * 32 + lane]);
        acc.x += (x0.x + x1.x) + (x2.x + x3.x);
        acc.y += (x0.y + x1.y) + (x2.y + x3.y);
        acc.z += (x0.z + x1.z) + (x2.z + x3.z);
        acc.w += (x0.w + x1.w) + (x2.w + x3.w);
    }
    int rem = r1 - e;  // 0..3: parallel tail, adds applied in order
    if (rem > 0) {
        int s0 = SMI ? eix[e - estart] : __ldg(&g_esrc[e]);
        int s1 = (rem > 1) ? (SMI ? eix[e + 1 - estart] : __ldg(&g_esrc[e + 1])) : s0;
        int s2 = (rem > 2) ? (SMI ? eix[e + 2 - estart] : __ldg(&g_esrc[e + 2])) : s0;
        float4 x0 = up4(hp[(size_t)s0 * 32 + lane]);
        float4 x1 = up4(hp[(size_t)s1 * 32 + lane]);
        float4 x2 = up4(hp[(size_t)s2 * 32 + lane]);
        acc.x += x0.x; acc.y += x0.y; acc.z += x0.z; acc.w += x0.w;
        if (rem > 1) { acc.x += x1.x; acc.y += x1.y; acc.z += x1.z; acc.w += x1.w; }
        if (rem > 2) { acc.x += x2.x; acc.y += x2.y; acc.z += x2.z; acc.w += x2.w; }
    }
}

__global__ __launch_bounds__(256, 3) void k_agg_etype(const __half* __restrict__ h,
                                                      const float* __restrict__ Wet) {
    extern __shared__ __half smh[];
    __half* Xs = smh;             // 64 x LD2
    __half* Ws = smh + 64 * LD2;  // 128 x LD2
    int* rps = reinterpret_cast<int*>(smh + 192 * LD2);  // 257 used
    int* eix = rps + 260;                                 // ESMEM entries
    int tid = threadIdx.x, lane = tid & 31, warp = tid >> 5;
    int rowBase = blockIdx.x * 64;
    int wm = (warp & 1) * 32, wn = (warp >> 1) * 32;
    int gr = lane >> 2, gc = lane & 3;
    const uint2* hp = reinterpret_cast<const uint2*>(h);

    {
        int base = 4 * rowBase;
        for (int i = tid; i < 257; i += 256) {
            int g = base + i;
            rps[i] = g_rp[g <= cM ? g : cM];
        }
    }
    __syncthreads();
    int estart = rps[0];
    int ecnt = rps[256] - estart;
    bool insm = (ecnt <= ESMEM);
    if (insm) {
        for (int i = tid; i < ecnt; i += 256) eix[i] = g_esrc[estart + i];
    }
    __syncthreads();

    float c[2][4][4];
#pragma unroll
    for (int i = 0; i < 2; i++)
#pragma unroll
        for (int j = 0; j < 4; j++)
#pragma unroll
            for (int q = 0; q < 4; q++) c[i][j][q] = 0.f;

    for (int ke = 0; ke < cK; ke++) {
        if (ke) __syncthreads();
#pragma unroll
        for (int i = 0; i < 8; i++) {
            int vl = warp * 8 + i;
            float4 acc = make_float4(0.f, 0.f, 0.f, 0.f);
            int r0 = rps[4 * vl + ke], r1 = rps[4 * vl + ke + 1];
            if (insm) seg_sum<true>(hp, eix, estart, r0, r1, lane, acc);
            else      seg_sum<false>(hp, eix, estart, r0, r1, lane, acc);
            *reinterpret_cast<uint2*>(Xs + vl * LD2 + lane * 4) =
                make_uint2(pk2(acc.x, acc.y), pk2(acc.z, acc.w));
        }
        load_tile_W128_16(Wet + (size_t)ke * cD * cD, cD, Ws, tid);
        __syncthreads();
        mma_loop32(Xs, Ws, wm, wn, gr, gc, c);
    }

    // epilogue -> fp16 a
#pragma unroll
    for (int i = 0; i < 2; i++)
#pragma unroll
        for (int j = 0; j < 4; j++) {
            int col = wn + j * 8 + 2 * gc;
#pragma unroll
            for (int half = 0; half < 2; half++) {
                int r = rowBase + wm + i * 16 + gr + half * 8;
                if (r >= cN) continue;
                float2 bs = *reinterpret_cast<const float2*>(g_bsum + (size_t)r * cD + col);
                uint32_t o = pk2(c[i][j][half * 2] + bs.x, c[i][j][half * 2 + 1] + bs.y);
                *reinterpret_cast<uint32_t*>(g_a_h + (size_t)r * cD + col) = o;
            }
        }
}

// ---------------- merged GRU: 512 threads, one block per 128-row stripe ----------------
// warps 0-7: output cols 0-63; warps 8-15: cols 64-127. X tiles shared; full W tile per phase.
constexpr int SM_GRU = 3 * 128 * LD2 * 2;  // 104448

__global__ __launch_bounds__(512, 1) void k_gru_fused(
    const __half* __restrict__ A, const __half* __restrict__ Hh,
    const float* __restrict__ b_ih, const float* __restrict__ b_hh,
    __half* __restrict__ houth) {
    extern __shared__ __half smh[];
    __half* Xa = smh;
    __half* Xh = smh + 128 * LD2;
    __half* Ws = smh + 256 * LD2;
    int tid = threadIdx.x;
    int rowBase = blockIdx.x * 128;
    int lane = tid & 31, warp = tid >> 5;
    int w8 = warp & 7, wg = warp >> 3;
    int wm = (w8 & 3) * 32, wn = (w8 >> 2) * 32 + wg * 64;  // wn spans 0..96
    int gr = lane >> 2, gc = lane & 3;

    load_tile_A16(A, Xa, rowBase, cN, tid, 512);
    load_tile_A16(Hh, Xh, rowBase, cN, tid, 512);

    float rf[2][4][4], zf[2][4][4], ci[2][4][4], ch[2][4][4];

#pragma unroll
    for (int g = 0; g < 3; g++) {
#pragma unroll
        for (int i = 0; i < 2; i++)
#pragma unroll
            for (int j = 0; j < 4; j++)
#pragma unroll
                for (int q = 0; q < 4; q++) { ci[i][j][q] = 0.f; ch[i][j][q] = 0.f; }

        load_tile_W128_h(g_wih_h + (size_t)g * 128 * cD, Ws, tid, 512);
        __syncthreads();
        mma_loop32(Xa, Ws, wm, wn, gr, gc, ci);
        __syncthreads();
        load_tile_W128_h(g_whh_h + (size_t)g * 128 * cD, Ws, tid, 512);
        __syncthreads();
        mma_loop32(Xh, Ws, wm, wn, gr, gc, ch);
        __syncthreads();

#pragma unroll
        for (int i = 0; i < 2; i++)
#pragma unroll
            for (int j = 0; j < 4; j++) {
                int col = wn + j * 8 + 2 * gc;  // 0..127
                float bi0 = __ldg(&b_ih[g * 128 + col]), bi1 = __ldg(&b_ih[g * 128 + col + 1]);
                float bh0 = __ldg(&b_hh[g * 128 + col]), bh1 = __ldg(&b_hh[g * 128 + col + 1]);
                if (g == 0) {
#pragma unroll
                    for (int q = 0; q < 4; q++) {
                        float bi = (q & 1) ? bi1 : bi0, bh = (q & 1) ? bh1 : bh0;
                        rf[i][j][q] = sigmf(ci[i][j][q] + bi + ch[i][j][q] + bh);
                    }
                } else if (g == 1) {
#pragma unroll
                    for (int q = 0; q < 4; q++) {
                        float bi = (q & 1) ? bi1 : bi0, bh = (q & 1) ? bh1 : bh0;
                        zf[i][j][q] = sigmf(ci[i][j][q] + bi + ch[i][j][q] + bh);
                    }
                } else {
#pragma unroll
                    for (int half = 0; half < 2; half++) {
                        int lr = wm + i * 16 + gr + half * 8;
                        int r = rowBase + lr;
                        if (r >= cN) continue;
                        float2 hv = up2(lds32(Xh + lr * LD2 + col));
                        int q0 = half * 2, q1 = half * 2 + 1;
                        float n0 = tanhf(ci[i][j][q0] + bi0 + rf[i][j][q0] * (ch[i][j][q0] + bh0));
                        float n1 = tanhf(ci[i][j][q1] + bi1 + rf[i][j][q1] * (ch[i][j][q1] + bh1));
                        float o0 = (1.0f - zf[i][j][q0]) * n0 + zf[i][j][q0] * hv.x;
                        float o1 = (1.0f - zf[i][j][q1]) * n1 + zf[i][j][q1] * hv.y;
                        *reinterpret_cast<uint32_t*>(houth + (size_t)r * cD + col) = pk2(o0, o1);
                    }
                }
            }
    }
}

// ---------------- fused output head (fp16 tiles; unchanged R15) ----------------
constexpr int SM_HEAD = 3 * 128 * LD2 * 2;  // 104448 -> 2 CTAs/SM

__global__ __launch_bounds__(256, 2) void k_head(
    const __half* __restrict__ Hh, const __half* __restrict__ Fh,
    const float* __restrict__ i_w, const float* __restrict__ i_b,
    const float* __restrict__ j_w, const float* __restrict__ j_b,
    float* __restrict__ out) {
    extern __shared__ __half smh[];
    __half* Xh = smh;
    __half* Xf = smh + 128 * LD2;
    __half* Ws = smh + 256 * LD2;
    int tid = threadIdx.x;
    int rowBase = blockIdx.x * 128;
    int lane = tid & 31, warp = tid >> 5;
    int wm = (warp & 3) * 32, wn = (warp >> 2) * 64;
    int gr = lane >> 2, gc = lane & 3;

    load_tile_A16(Hh, Xh, rowBase, cN, tid, 256);
    load_tile_A16(Fh, Xf, rowBase, cN, tid, 256);

    float cg[2][8][4], cj[2][8][4];
#pragma unroll
    for (int i = 0; i < 2; i++)
#pragma unroll
        for (int j = 0; j < 8; j++)
#pragma unroll
            for (int q = 0; q < 4; q++) { cg[i][j][q] = 0.f; cj[i][j][q] = 0.f; }

    load_tile_W128_16(i_w, 2 * cD, Ws, tid);
    __syncthreads();
    mma_loop64(Xh, Ws, wm, wn, gr, gc, cg);
    __syncthreads();
    load_tile_W128_16(i_w + cD, 2 * cD, Ws, tid);
    __syncthreads();
    mma_loop64(Xf, Ws, wm, wn, gr, gc, cg);
    __syncthreads();
    load_tile_W128_16(j_w, cD, Ws, tid);
    __syncthreads();
    mma_loop64(Xh, Ws, wm, wn, gr, gc, cj);

#pragma unroll
    for (int i = 0; i < 2; i++)
#pragma unroll
        for (int j = 0; j < 8; j++) {
            int col = wn + j * 8 + 2 * gc;
            float ib0 = __ldg(&i_b[col]), ib1 = __ldg(&i_b[col + 1]);
            float jb0 = __ldg(&j_b[col]), jb1 = __ldg(&j_b[col + 1]);
#pragma unroll
            for (int half = 0; half < 2; half++) {
                int r = rowBase + wm + i * 16 + gr + half * 8;
                if (r >= cN) continue;
                int q0 = half * 2, q1 = half * 2 + 1;
                float2 o;
                o.x = sigmf(cg[i][j][q0] + ib0) * (cj[i][j][q0] + jb0);
                o.y = sigmf(cg[i][j][q1] + ib1) * (cj[i][j][q1] + jb1);
                *reinterpret_cast<float2*>(out + (size_t)r * cD + col) = o;
            }
        }
}

// ---------------- host ----------------
extern "C" void kernel_launch(void* const* d_in, const int* in_sizes, int n_in,
                              void* d_out, int out_size) {
    (void)in_sizes; (void)n_in; (void)out_size;
    const float* features = (const float*)d_in[0];
    const int*   src      = (const int*)d_in[1];
    const int*   dst      = (const int*)d_in[2];
    const int*   etypes   = (const int*)d_in[3];
    const float* W_et     = (const float*)d_in[4];
    const float* b_et     = (const float*)d_in[5];
    const float* W_ih     = (const float*)d_in[6];
    const float* b_ih     = (const float*)d_in[7];
    const float* W_hh     = (const float*)d_in[8];
    const float* b_hh     = (const float*)d_in[9];
    const float* i_w      = (const float*)d_in[10];
    const float* i_b      = (const float*)d_in[11];
    const float* j_w      = (const float*)d_in[12];
    const float* j_b      = (const float*)d_in[13];
    float* out = (float*)d_out;

    __half *h0h, *h1h, *feath, *abuf;
    cudaGetSymbolAddress((void**)&h0h, g_h0h);
    cudaGetSymbolAddress((void**)&h1h, g_h1h);
    cudaGetSymbolAddress((void**)&feath, g_feath);
    cudaGetSymbolAddress((void**)&abuf, g_a_h);

    cudaFuncSetAttribute(k_agg_etype, cudaFuncAttributeMaxDynamicSharedMemorySize, SM_AE);
    cudaFuncSetAttribute(k_gru_fused, cudaFuncAttributeMaxDynamicSharedMemorySize, SM_GRU);
    cudaFuncSetAttribute(k_head, cudaFuncAttributeMaxDynamicSharedMemorySize, SM_HEAD);

    // ---- CSR build: 3 launches, then agg is launch index 3 (ncu window) ----
    k_hist<<<(cE + 255) / 256, 256>>>(dst, etypes);
    k_scanlb<<<NTILE, 1024>>>();
    {
        int tot = cN * cD > cE ? cN * cD : cE;
        k_scatter_bsum<<<(tot + 255) / 256, 256>>>(src, dst, etypes, b_et, features, W_ih, W_hh);
    }

    const int RB64 = (cN + 63) / 64;    // 1563
    const int RB128 = (cN + 127) / 128; // 782

    const __half* hch = feath;
    __half* houths[3] = {h0h, h1h, h0h};
    for (int s = 0; s < 3; s++) {
        k_agg_etype<<<RB64, 256, SM_AE>>>(hch, W_et);  // fp16 gather -> g_a_h
        k_gru_fused<<<RB128, 512, SM_GRU>>>(abuf, hch, b_ih, b_hh, houths[s]);
        hch = houths[s];
    }
    k_head<<<RB128, 256, SM_HEAD>>>(hch, feath, i_w, i_b, j_w, j_b, out);
}